// round 1
// baseline (speedup 1.0000x reference)
#include <cuda_runtime.h>
#include <math.h>

#define DIM 1024
#define NH 16
#define HD 64
#define BATCH 4
#define SEQ 2048
#define MROWS (BATCH*SEQ)   // 8192

// ---------------- scratch (static device memory; no allocations) -------------
__device__ float g_q  [(size_t)MROWS * DIM];      // 32 MB  q projection (then LN+RoPE'd, pre-scaled)
__device__ float g_kv [(size_t)MROWS * 2 * DIM];  // 64 MB  kv projection (k LN'd in place)
__device__ float g_att[(size_t)MROWS * DIM];      // 32 MB  attention output

// ---------------- generic tiled SGEMM: C[M,N] = A[M,K] @ B[K,N] (+bias) ------
// 128x128 tile, BK=16, 256 threads, 8x8 micro-tile per thread.
__global__ __launch_bounds__(256) void sgemm_kernel(
    const float* __restrict__ A, const float* __restrict__ Bm,
    const float* __restrict__ bias, float* __restrict__ C,
    int M, int N, int K)
{
    __shared__ float As[16][128];   // transposed: As[k][m]
    __shared__ float Bs[16][128];   // natural:    Bs[k][n]

    const int tid = threadIdx.x;
    const int tx = tid & 15, ty = tid >> 4;
    const int m0 = blockIdx.y * 128, n0 = blockIdx.x * 128;

    float acc[8][8];
#pragma unroll
    for (int i = 0; i < 8; i++)
#pragma unroll
        for (int j = 0; j < 8; j++) acc[i][j] = 0.f;

    for (int k0 = 0; k0 < K; k0 += 16) {
        // load A tile (512 float4, 2 per thread), store transposed
#pragma unroll
        for (int t = 0; t < 2; t++) {
            int i = tid + t * 256;          // 0..511
            int row = i >> 2;               // 0..127
            int kq = (i & 3) * 4;
            float4 v = *(const float4*)(A + (size_t)(m0 + row) * K + k0 + kq);
            As[kq + 0][row] = v.x; As[kq + 1][row] = v.y;
            As[kq + 2][row] = v.z; As[kq + 3][row] = v.w;
        }
        // load B tile (512 float4, 2 per thread), natural layout
#pragma unroll
        for (int t = 0; t < 2; t++) {
            int i = tid + t * 256;
            int kk = i >> 5;                // 0..15
            int nq = (i & 31) * 4;
            *(float4*)&Bs[kk][nq] = *(const float4*)(Bm + (size_t)(k0 + kk) * N + n0 + nq);
        }
        __syncthreads();
#pragma unroll
        for (int kk = 0; kk < 16; kk++) {
            float a[8], b[8];
            *(float4*)&a[0] = *(float4*)&As[kk][ty * 8];
            *(float4*)&a[4] = *(float4*)&As[kk][ty * 8 + 4];
            *(float4*)&b[0] = *(float4*)&Bs[kk][tx * 8];
            *(float4*)&b[4] = *(float4*)&Bs[kk][tx * 8 + 4];
#pragma unroll
            for (int i = 0; i < 8; i++)
#pragma unroll
                for (int j = 0; j < 8; j++) acc[i][j] += a[i] * b[j];
        }
        __syncthreads();
    }

#pragma unroll
    for (int i = 0; i < 8; i++) {
        int row = m0 + ty * 8 + i;
#pragma unroll
        for (int j = 0; j < 8; j += 4) {
            int col = n0 + tx * 8 + j;
            float4 v;
            v.x = acc[i][j]; v.y = acc[i][j + 1]; v.z = acc[i][j + 2]; v.w = acc[i][j + 3];
            if (bias) {
                v.x += bias[col]; v.y += bias[col + 1];
                v.z += bias[col + 2]; v.w += bias[col + 3];
            }
            *(float4*)(C + (size_t)row * N + col) = v;
        }
    }
}

// ---------------- per-head LayerNorm (+optional RoPE + 1/8 scale) ------------
// one warp per (row, head); lane handles dims lane and lane+32.
__global__ __launch_bounds__(256) void ln_rope_q_kernel(
    float* __restrict__ q, const float* __restrict__ scale, const float* __restrict__ bias)
{
    int gw = blockIdx.x * 8 + (threadIdx.x >> 5);
    int lane = threadIdx.x & 31;
    int row = gw >> 4;
    int h = gw & 15;
    float* p = q + (size_t)row * DIM + h * HD;
    float e0 = p[lane], e1 = p[lane + 32];
    float ssum = e0 + e1;
#pragma unroll
    for (int o = 16; o; o >>= 1) ssum += __shfl_xor_sync(0xffffffffu, ssum, o);
    float mu = ssum * (1.f / 64.f);
    float d0 = e0 - mu, d1 = e1 - mu;
    float vs = d0 * d0 + d1 * d1;
#pragma unroll
    for (int o = 16; o; o >>= 1) vs += __shfl_xor_sync(0xffffffffu, vs, o);
    float rstd = rsqrtf(vs * (1.f / 64.f) + 1e-5f);
    float n0 = d0 * rstd * scale[lane] + bias[lane];
    float n1 = d1 * rstd * scale[lane + 32] + bias[lane + 32];
    // RoPE: pair (lane, lane+32), position = row % SEQ
    int s = row & (SEQ - 1);
    float invf = powf(10000.f, -(float)lane * (1.f / 32.f));
    float ang = (float)s * invf;
    float sn, c;
    sincosf(ang, &sn, &c);
    // fold softmax scale 1/sqrt(64) into q
    p[lane]      = (n0 * c - n1 * sn) * 0.125f;
    p[lane + 32] = (n0 * sn + n1 * c) * 0.125f;
}

__global__ __launch_bounds__(256) void ln_k_kernel(
    float* __restrict__ kv, const float* __restrict__ scale, const float* __restrict__ bias)
{
    int gw = blockIdx.x * 8 + (threadIdx.x >> 5);
    int lane = threadIdx.x & 31;
    int row = gw >> 4;
    int h = gw & 15;
    float* p = kv + (size_t)row * (2 * DIM) + h * HD;   // k = first DIM cols
    float e0 = p[lane], e1 = p[lane + 32];
    float ssum = e0 + e1;
#pragma unroll
    for (int o = 16; o; o >>= 1) ssum += __shfl_xor_sync(0xffffffffu, ssum, o);
    float mu = ssum * (1.f / 64.f);
    float d0 = e0 - mu, d1 = e1 - mu;
    float vs = d0 * d0 + d1 * d1;
#pragma unroll
    for (int o = 16; o; o >>= 1) vs += __shfl_xor_sync(0xffffffffu, vs, o);
    float rstd = rsqrtf(vs * (1.f / 64.f) + 1e-5f);
    p[lane]      = d0 * rstd * scale[lane] + bias[lane];
    p[lane + 32] = d1 * rstd * scale[lane + 32] + bias[lane + 32];
}

// ---------------- flash attention ---------------------------------------------
// block: 256 threads, BQ=128 queries of one (b,h), key tiles of 64.
// thread (tx,ty): 8 query rows (ty*8..), 4 key cols / 4 hd cols (tx*4..).
#define BQ 128
#define BK 64
#define PSTR 129

__global__ __launch_bounds__(256) void attn_kernel(
    const float* __restrict__ q, const float* __restrict__ kv, float* __restrict__ out)
{
    extern __shared__ float smem[];
    float* Qs = smem;                 // [64][128]  d-major
    float* Ks = Qs + 64 * BQ;         // [64][64]   d-major
    float* Vs = Ks + 64 * BK;         // [64][64]   key-major
    float* Ps = Vs + BK * 64;         // [64][129]  key-major, padded

    const int tid = threadIdx.x;
    const int tx = tid & 15, ty = tid >> 4;
    const int qt = blockIdx.x;        // query tile 0..15
    const int h = blockIdx.y;
    const int b = blockIdx.z;
    const int rowbase = b * SEQ + qt * BQ;
    const int ctxbase = b * SEQ;

    // load Q tile transposed: Qs[d][r]
#pragma unroll
    for (int t = 0; t < 8; t++) {
        int i = tid + t * 256;        // 0..2047
        int r = i >> 4;               // 0..127
        int dq = (i & 15) * 4;
        float4 v = *(const float4*)(q + (size_t)(rowbase + r) * DIM + h * HD + dq);
        Qs[(dq + 0) * BQ + r] = v.x; Qs[(dq + 1) * BQ + r] = v.y;
        Qs[(dq + 2) * BQ + r] = v.z; Qs[(dq + 3) * BQ + r] = v.w;
    }

    float O[8][4], m[8], l[8];
#pragma unroll
    for (int i = 0; i < 8; i++) {
        m[i] = -1e30f; l[i] = 0.f;
#pragma unroll
        for (int c = 0; c < 4; c++) O[i][c] = 0.f;
    }

    for (int kt = 0; kt < SEQ / BK; kt++) {
        __syncthreads();  // protect Ks/Vs/Ps from previous-iteration readers (and Qs stores, iter 0)
        // load K (transposed) and V (natural) tiles
#pragma unroll
        for (int t = 0; t < 4; t++) {
            int i = tid + t * 256;    // 0..1023
            int c = i >> 4;           // key 0..63
            int dq = (i & 15) * 4;
            const float* kp = kv + (size_t)(ctxbase + kt * BK + c) * (2 * DIM) + h * HD + dq;
            float4 kk = *(const float4*)kp;
            Ks[(dq + 0) * BK + c] = kk.x; Ks[(dq + 1) * BK + c] = kk.y;
            Ks[(dq + 2) * BK + c] = kk.z; Ks[(dq + 3) * BK + c] = kk.w;
            *(float4*)&Vs[c * HD + dq] = *(const float4*)(kp + DIM);
        }
        __syncthreads();

        // S = Q @ K^T  (scale already folded into q)
        float sacc[8][4];
#pragma unroll
        for (int i = 0; i < 8; i++)
#pragma unroll
            for (int j = 0; j < 4; j++) sacc[i][j] = 0.f;
#pragma unroll 8
        for (int d = 0; d < HD; d++) {
            float a[8];
            *(float4*)&a[0] = *(float4*)&Qs[d * BQ + ty * 8];
            *(float4*)&a[4] = *(float4*)&Qs[d * BQ + ty * 8 + 4];
            float4 kk = *(float4*)&Ks[d * BK + tx * 4];
            float bb[4] = {kk.x, kk.y, kk.z, kk.w};
#pragma unroll
            for (int i = 0; i < 8; i++)
#pragma unroll
                for (int j = 0; j < 4; j++) sacc[i][j] += a[i] * bb[j];
        }

        // online softmax (row stats across the 16 tx lanes)
#pragma unroll
        for (int i = 0; i < 8; i++) {
            float tmax = sacc[i][0];
#pragma unroll
            for (int j = 1; j < 4; j++) tmax = fmaxf(tmax, sacc[i][j]);
#pragma unroll
            for (int o = 1; o < 16; o <<= 1) tmax = fmaxf(tmax, __shfl_xor_sync(0xffffffffu, tmax, o));
            float mnew = fmaxf(m[i], tmax);
            float alpha = __expf(m[i] - mnew);
            float sum = 0.f;
#pragma unroll
            for (int j = 0; j < 4; j++) {
                float pp = __expf(sacc[i][j] - mnew);
                sacc[i][j] = pp; sum += pp;
            }
#pragma unroll
            for (int o = 1; o < 16; o <<= 1) sum += __shfl_xor_sync(0xffffffffu, sum, o);
            l[i] = l[i] * alpha + sum;
            m[i] = mnew;
#pragma unroll
            for (int c = 0; c < 4; c++) O[i][c] *= alpha;
        }

        // stage P transposed: Ps[key][r]
#pragma unroll
        for (int j = 0; j < 4; j++)
#pragma unroll
            for (int i = 0; i < 8; i++)
                Ps[(tx * 4 + j) * PSTR + ty * 8 + i] = sacc[i][j];
        __syncthreads();

        // O += P @ V
#pragma unroll 8
        for (int j = 0; j < BK; j++) {
            float p[8];
#pragma unroll
            for (int i = 0; i < 8; i++) p[i] = Ps[j * PSTR + ty * 8 + i];
            float4 vv = *(float4*)&Vs[j * HD + tx * 4];
            float v4[4] = {vv.x, vv.y, vv.z, vv.w};
#pragma unroll
            for (int i = 0; i < 8; i++)
#pragma unroll
                for (int c = 0; c < 4; c++) O[i][c] += p[i] * v4[c];
        }
    }

    // normalize and write: out[row][h*64 + c]
#pragma unroll
    for (int i = 0; i < 8; i++) {
        float inv = 1.f / l[i];
        float4 v;
        v.x = O[i][0] * inv; v.y = O[i][1] * inv;
        v.z = O[i][2] * inv; v.w = O[i][3] * inv;
        *(float4*)(out + (size_t)(rowbase + ty * 8 + i) * DIM + h * HD + tx * 4) = v;
    }
}

// ---------------- launch ------------------------------------------------------
extern "C" void kernel_launch(void* const* d_in, const int* in_sizes, int n_in,
                              void* d_out, int out_size)
{
    const float* x        = (const float*)d_in[0];
    const float* context  = (const float*)d_in[1];
    const float* q_w      = (const float*)d_in[2];
    const float* kv_w     = (const float*)d_in[3];
    const float* qn_scale = (const float*)d_in[4];
    const float* qn_bias  = (const float*)d_in[5];
    const float* kn_scale = (const float*)d_in[6];
    const float* kn_bias  = (const float*)d_in[7];
    const float* proj_w   = (const float*)d_in[8];
    const float* proj_b   = (const float*)d_in[9];
    float* out = (float*)d_out;

    float *pq, *pkv, *patt;
    cudaGetSymbolAddress((void**)&pq, g_q);
    cudaGetSymbolAddress((void**)&pkv, g_kv);
    cudaGetSymbolAddress((void**)&patt, g_att);

    // attention kernel needs ~98.6 KB dynamic smem
    size_t attn_smem = (64 * BQ + 64 * BK + BK * 64 + BK * PSTR) * sizeof(float);
    cudaFuncSetAttribute(attn_kernel, cudaFuncAttributeMaxDynamicSharedMemorySize, (int)attn_smem);

    // 1. q = x @ q_w                  [8192,1024]
    sgemm_kernel<<<dim3(DIM / 128, MROWS / 128), 256>>>(x, q_w, nullptr, pq, MROWS, DIM, DIM);
    // 2. kv = context @ kv_w          [8192,2048]
    sgemm_kernel<<<dim3(2 * DIM / 128, MROWS / 128), 256>>>(context, kv_w, nullptr, pkv, MROWS, 2 * DIM, DIM);
    // 3. per-head LN (+RoPE+scale on q, plain LN on k)
    ln_rope_q_kernel<<<MROWS * NH / 8, 256>>>(pq, qn_scale, qn_bias);
    ln_k_kernel<<<MROWS * NH / 8, 256>>>(pkv, kn_scale, kn_bias);
    // 4. attention
    attn_kernel<<<dim3(SEQ / BQ, NH, BATCH), 256, attn_smem>>>(pq, pkv, patt);
    // 5. out = att @ proj_w + proj_b
    sgemm_kernel<<<dim3(DIM / 128, MROWS / 128), 256>>>(patt, proj_w, proj_b, out, MROWS, DIM, DIM);
}

// round 3
// speedup vs baseline: 1.1187x; 1.1187x over previous
#include <cuda_runtime.h>
#include <math.h>

#define DIM 1024
#define NH 16
#define HD 64
#define BATCH 4
#define SEQ 2048
#define MROWS (BATCH*SEQ)   // 8192

// ---------------- scratch (static device memory; no allocations) -------------
__device__ float g_q  [(size_t)MROWS * DIM];      // 32 MB
__device__ float g_kv [(size_t)MROWS * 2 * DIM];  // 64 MB
__device__ float g_att[(size_t)MROWS * DIM];      // 32 MB

// =======================  3xTF32 tensor-core GEMM  ===========================
// C[M,N] = A[M,K] @ B[K,N] (+bias).  CTA tile 128x128, BK=32, 256 thr (8 warps
// of 64x32 each), double-buffered cp.async staging, conflict-free fragment LDS.
// Split-precision: a = hi + lo, acc += hi*hi + lo*hi + hi*lo  (~fp32 accuracy).

#define AS_STRIDE 36
#define BS_STRIDE 136
#define A_STAGE (128*AS_STRIDE)
#define B_STAGE (32*BS_STRIDE)
#define GEMM_SMEM ((2*A_STAGE + 2*B_STAGE) * sizeof(float))   // 71680 B

__device__ __forceinline__ void mma_tf32(float c[4], const unsigned a[4], const unsigned b[2]) {
    asm volatile(
        "mma.sync.aligned.m16n8k8.row.col.f32.tf32.tf32.f32 "
        "{%0,%1,%2,%3}, {%4,%5,%6,%7}, {%8,%9}, {%0,%1,%2,%3};\n"
        : "+f"(c[0]), "+f"(c[1]), "+f"(c[2]), "+f"(c[3])
        : "r"(a[0]), "r"(a[1]), "r"(a[2]), "r"(a[3]), "r"(b[0]), "r"(b[1]));
}

__device__ __forceinline__ unsigned f2tf32(float f) {
    unsigned r;
    asm("cvt.rna.tf32.f32 %0, %1;" : "=r"(r) : "f"(f));
    return r;
}
__device__ __forceinline__ void split_tf32(float f, unsigned& hi, unsigned& lo) {
    hi = f2tf32(f);
    lo = f2tf32(f - __uint_as_float(hi));
}

__global__ __launch_bounds__(256) void tf32_gemm_kernel(
    const float* __restrict__ A, const float* __restrict__ B,
    const float* __restrict__ bias, float* __restrict__ C,
    int M, int N, int K)
{
    extern __shared__ float sm[];
    float* As = sm;                 // [2][128][36]
    float* Bs = sm + 2 * A_STAGE;   // [2][32][136]

    const int tid = threadIdx.x;
    const int warp = tid >> 5, lane = tid & 31;
    const int group = lane >> 2, tig = lane & 3;
    const int wm = (warp & 1) * 64;
    const int wn = (warp >> 1) * 32;
    const int m0 = blockIdx.y * 128, n0 = blockIdx.x * 128;

    const float* Abase = A + (size_t)m0 * K;
    const float* Bbase = B + n0;

    float acc[4][4][4] = {};

#define GEMM_ISSUE(s, k0)                                                          \
    do {                                                                           \
        float* as = As + (s) * A_STAGE;                                            \
        float* bs = Bs + (s) * B_STAGE;                                            \
        _Pragma("unroll")                                                          \
        for (int t = 0; t < 4; t++) {                                              \
            int i = tid + t * 256; int row = i >> 3; int kq = (i & 7) * 4;         \
            unsigned d = (unsigned)__cvta_generic_to_shared(as + row * AS_STRIDE + kq); \
            asm volatile("cp.async.cg.shared.global [%0], [%1], 16;"               \
                         :: "r"(d), "l"(Abase + (size_t)row * K + (k0) + kq));     \
        }                                                                          \
        _Pragma("unroll")                                                          \
        for (int t = 0; t < 4; t++) {                                              \
            int i = tid + t * 256; int kr = i >> 5; int nq = (i & 31) * 4;         \
            unsigned d = (unsigned)__cvta_generic_to_shared(bs + kr * BS_STRIDE + nq); \
            asm volatile("cp.async.cg.shared.global [%0], [%1], 16;"               \
                         :: "r"(d), "l"(Bbase + (size_t)((k0) + kr) * N + nq));    \
        }                                                                          \
        asm volatile("cp.async.commit_group;");                                    \
    } while (0)

    GEMM_ISSUE(0, 0);
    const int NT = K / 32;
    for (int kt = 0; kt < NT; kt++) {
        if (kt + 1 < NT) {
            GEMM_ISSUE((kt + 1) & 1, (kt + 1) * 32);
            asm volatile("cp.async.wait_group 1;");
        } else {
            asm volatile("cp.async.wait_group 0;");
        }
        __syncthreads();

        const float* Asf = As + (kt & 1) * A_STAGE;
        const float* Bsf = Bs + (kt & 1) * B_STAGE;
#pragma unroll
        for (int kb = 0; kb < 4; kb++) {
            unsigned ah[4][4], al[4][4], bh[4][2], bl[4][2];
#pragma unroll
            for (int mi = 0; mi < 4; mi++) {
                int base = (wm + mi * 16 + group) * AS_STRIDE + kb * 8 + tig;
                split_tf32(Asf[base],                  ah[mi][0], al[mi][0]);
                split_tf32(Asf[base + 8 * AS_STRIDE],  ah[mi][1], al[mi][1]);
                split_tf32(Asf[base + 4],              ah[mi][2], al[mi][2]);
                split_tf32(Asf[base + 8 * AS_STRIDE + 4], ah[mi][3], al[mi][3]);
            }
#pragma unroll
            for (int ni = 0; ni < 4; ni++) {
                int base = (kb * 8 + tig) * BS_STRIDE + wn + ni * 8 + group;
                split_tf32(Bsf[base],                  bh[ni][0], bl[ni][0]);
                split_tf32(Bsf[base + 4 * BS_STRIDE],  bh[ni][1], bl[ni][1]);
            }
#pragma unroll
            for (int mi = 0; mi < 4; mi++)
#pragma unroll
                for (int ni = 0; ni < 4; ni++) {
                    mma_tf32(acc[mi][ni], al[mi], bh[ni]);
                    mma_tf32(acc[mi][ni], ah[mi], bl[ni]);
                    mma_tf32(acc[mi][ni], ah[mi], bh[ni]);
                }
        }
        __syncthreads();
    }

#pragma unroll
    for (int mi = 0; mi < 4; mi++) {
#pragma unroll
        for (int ni = 0; ni < 4; ni++) {
            int col = n0 + wn + ni * 8 + tig * 2;
            float bx = 0.f, by = 0.f;
            if (bias) { bx = bias[col]; by = bias[col + 1]; }
            int r0 = m0 + wm + mi * 16 + group;
            float2 v0; v0.x = acc[mi][ni][0] + bx; v0.y = acc[mi][ni][1] + by;
            *(float2*)(C + (size_t)r0 * N + col) = v0;
            float2 v1; v1.x = acc[mi][ni][2] + bx; v1.y = acc[mi][ni][3] + by;
            *(float2*)(C + (size_t)(r0 + 8) * N + col) = v1;
        }
    }
}

// ---------------- per-head LayerNorm (+RoPE + 1/8 scale on q) ----------------
__global__ __launch_bounds__(256) void ln_rope_q_kernel(
    float* __restrict__ q, const float* __restrict__ scale, const float* __restrict__ bias)
{
    int gw = blockIdx.x * 8 + (threadIdx.x >> 5);
    int lane = threadIdx.x & 31;
    int row = gw >> 4;
    int h = gw & 15;
    float* p = q + (size_t)row * DIM + h * HD;
    float e0 = p[lane], e1 = p[lane + 32];
    float ssum = e0 + e1;
#pragma unroll
    for (int o = 16; o; o >>= 1) ssum += __shfl_xor_sync(0xffffffffu, ssum, o);
    float mu = ssum * (1.f / 64.f);
    float d0 = e0 - mu, d1 = e1 - mu;
    float vs = d0 * d0 + d1 * d1;
#pragma unroll
    for (int o = 16; o; o >>= 1) vs += __shfl_xor_sync(0xffffffffu, vs, o);
    float rstd = rsqrtf(vs * (1.f / 64.f) + 1e-5f);
    float n0 = d0 * rstd * scale[lane] + bias[lane];
    float n1 = d1 * rstd * scale[lane + 32] + bias[lane + 32];
    int s = row & (SEQ - 1);
    float invf = powf(10000.f, -(float)lane * (1.f / 32.f));
    float ang = (float)s * invf;
    float sn, c;
    sincosf(ang, &sn, &c);
    p[lane]      = (n0 * c - n1 * sn) * 0.125f;
    p[lane + 32] = (n0 * sn + n1 * c) * 0.125f;
}

__global__ __launch_bounds__(256) void ln_k_kernel(
    float* __restrict__ kv, const float* __restrict__ scale, const float* __restrict__ bias)
{
    int gw = blockIdx.x * 8 + (threadIdx.x >> 5);
    int lane = threadIdx.x & 31;
    int row = gw >> 4;
    int h = gw & 15;
    float* p = kv + (size_t)row * (2 * DIM) + h * HD;
    float e0 = p[lane], e1 = p[lane + 32];
    float ssum = e0 + e1;
#pragma unroll
    for (int o = 16; o; o >>= 1) ssum += __shfl_xor_sync(0xffffffffu, ssum, o);
    float mu = ssum * (1.f / 64.f);
    float d0 = e0 - mu, d1 = e1 - mu;
    float vs = d0 * d0 + d1 * d1;
#pragma unroll
    for (int o = 16; o; o >>= 1) vs += __shfl_xor_sync(0xffffffffu, vs, o);
    float rstd = rsqrtf(vs * (1.f / 64.f) + 1e-5f);
    p[lane]      = d0 * rstd * scale[lane] + bias[lane];
    p[lane + 32] = d1 * rstd * scale[lane + 32] + bias[lane + 32];
}

// ---------------- flash attention (fp32 SIMT, unchanged) ---------------------
#define BQ 128
#define BK 64
#define PSTR 129

__global__ __launch_bounds__(256) void attn_kernel(
    const float* __restrict__ q, const float* __restrict__ kv, float* __restrict__ out)
{
    extern __shared__ float smem[];
    float* Qs = smem;                 // [64][128]  d-major
    float* Ks = Qs + 64 * BQ;         // [64][64]   d-major
    float* Vs = Ks + 64 * BK;         // [64][64]   key-major
    float* Ps = Vs + BK * 64;         // [64][129]  key-major, padded

    const int tid = threadIdx.x;
    const int tx = tid & 15, ty = tid >> 4;
    const int qt = blockIdx.x;
    const int h = blockIdx.y;
    const int b = blockIdx.z;
    const int rowbase = b * SEQ + qt * BQ;
    const int ctxbase = b * SEQ;

#pragma unroll
    for (int t = 0; t < 8; t++) {
        int i = tid + t * 256;
        int r = i >> 4;
        int dq = (i & 15) * 4;
        float4 v = *(const float4*)(q + (size_t)(rowbase + r) * DIM + h * HD + dq);
        Qs[(dq + 0) * BQ + r] = v.x; Qs[(dq + 1) * BQ + r] = v.y;
        Qs[(dq + 2) * BQ + r] = v.z; Qs[(dq + 3) * BQ + r] = v.w;
    }

    float O[8][4], m[8], l[8];
#pragma unroll
    for (int i = 0; i < 8; i++) {
        m[i] = -1e30f; l[i] = 0.f;
#pragma unroll
        for (int c = 0; c < 4; c++) O[i][c] = 0.f;
    }

    for (int kt = 0; kt < SEQ / BK; kt++) {
        __syncthreads();
#pragma unroll
        for (int t = 0; t < 4; t++) {
            int i = tid + t * 256;
            int c = i >> 4;
            int dq = (i & 15) * 4;
            const float* kp = kv + (size_t)(ctxbase + kt * BK + c) * (2 * DIM) + h * HD + dq;
            float4 kk = *(const float4*)kp;
            Ks[(dq + 0) * BK + c] = kk.x; Ks[(dq + 1) * BK + c] = kk.y;
            Ks[(dq + 2) * BK + c] = kk.z; Ks[(dq + 3) * BK + c] = kk.w;
            *(float4*)&Vs[c * HD + dq] = *(const float4*)(kp + DIM);
        }
        __syncthreads();

        float sacc[8][4];
#pragma unroll
        for (int i = 0; i < 8; i++)
#pragma unroll
            for (int j = 0; j < 4; j++) sacc[i][j] = 0.f;
#pragma unroll 8
        for (int d = 0; d < HD; d++) {
            float a[8];
            *(float4*)&a[0] = *(float4*)&Qs[d * BQ + ty * 8];
            *(float4*)&a[4] = *(float4*)&Qs[d * BQ + ty * 8 + 4];
            float4 kk = *(float4*)&Ks[d * BK + tx * 4];
            float bb[4] = {kk.x, kk.y, kk.z, kk.w};
#pragma unroll
            for (int i = 0; i < 8; i++)
#pragma unroll
                for (int j = 0; j < 4; j++) sacc[i][j] += a[i] * bb[j];
        }

#pragma unroll
        for (int i = 0; i < 8; i++) {
            float tmax = sacc[i][0];
#pragma unroll
            for (int j = 1; j < 4; j++) tmax = fmaxf(tmax, sacc[i][j]);
#pragma unroll
            for (int o = 1; o < 16; o <<= 1) tmax = fmaxf(tmax, __shfl_xor_sync(0xffffffffu, tmax, o));
            float mnew = fmaxf(m[i], tmax);
            float alpha = __expf(m[i] - mnew);
            float sum = 0.f;
#pragma unroll
            for (int j = 0; j < 4; j++) {
                float pp = __expf(sacc[i][j] - mnew);
                sacc[i][j] = pp; sum += pp;
            }
#pragma unroll
            for (int o = 1; o < 16; o <<= 1) sum += __shfl_xor_sync(0xffffffffu, sum, o);
            l[i] = l[i] * alpha + sum;
            m[i] = mnew;
#pragma unroll
            for (int c = 0; c < 4; c++) O[i][c] *= alpha;
        }

#pragma unroll
        for (int j = 0; j < 4; j++)
#pragma unroll
            for (int i = 0; i < 8; i++)
                Ps[(tx * 4 + j) * PSTR + ty * 8 + i] = sacc[i][j];
        __syncthreads();

#pragma unroll 8
        for (int j = 0; j < BK; j++) {
            float p[8];
#pragma unroll
            for (int i = 0; i < 8; i++) p[i] = Ps[j * PSTR + ty * 8 + i];
            float4 vv = *(float4*)&Vs[j * HD + tx * 4];
            float v4[4] = {vv.x, vv.y, vv.z, vv.w};
#pragma unroll
            for (int i = 0; i < 8; i++)
#pragma unroll
                for (int c = 0; c < 4; c++) O[i][c] += p[i] * v4[c];
        }
    }

#pragma unroll
    for (int i = 0; i < 8; i++) {
        float inv = 1.f / l[i];
        float4 v;
        v.x = O[i][0] * inv; v.y = O[i][1] * inv;
        v.z = O[i][2] * inv; v.w = O[i][3] * inv;
        *(float4*)(out + (size_t)(rowbase + ty * 8 + i) * DIM + h * HD + tx * 4) = v;
    }
}

// ---------------- launch ------------------------------------------------------
extern "C" void kernel_launch(void* const* d_in, const int* in_sizes, int n_in,
                              void* d_out, int out_size)
{
    const float* x        = (const float*)d_in[0];
    const float* context  = (const float*)d_in[1];
    const float* q_w      = (const float*)d_in[2];
    const float* kv_w     = (const float*)d_in[3];
    const float* qn_scale = (const float*)d_in[4];
    const float* qn_bias  = (const float*)d_in[5];
    const float* kn_scale = (const float*)d_in[6];
    const float* kn_bias  = (const float*)d_in[7];
    const float* proj_w   = (const float*)d_in[8];
    const float* proj_b   = (const float*)d_in[9];
    float* out = (float*)d_out;

    float *pq, *pkv, *patt;
    cudaGetSymbolAddress((void**)&pq, g_q);
    cudaGetSymbolAddress((void**)&pkv, g_kv);
    cudaGetSymbolAddress((void**)&patt, g_att);

    cudaFuncSetAttribute(tf32_gemm_kernel, cudaFuncAttributeMaxDynamicSharedMemorySize, (int)GEMM_SMEM);
    size_t attn_smem = (64 * BQ + 64 * BK + BK * 64 + BK * PSTR) * sizeof(float);
    cudaFuncSetAttribute(attn_kernel, cudaFuncAttributeMaxDynamicSharedMemorySize, (int)attn_smem);

    // 1. q = x @ q_w
    tf32_gemm_kernel<<<dim3(DIM / 128, MROWS / 128), 256, GEMM_SMEM>>>(x, q_w, nullptr, pq, MROWS, DIM, DIM);
    // 2. kv = context @ kv_w
    tf32_gemm_kernel<<<dim3(2 * DIM / 128, MROWS / 128), 256, GEMM_SMEM>>>(context, kv_w, nullptr, pkv, MROWS, 2 * DIM, DIM);
    // 3. per-head LN (+RoPE+scale on q, plain LN on k)
    ln_rope_q_kernel<<<MROWS * NH / 8, 256>>>(pq, qn_scale, qn_bias);
    ln_k_kernel<<<MROWS * NH / 8, 256>>>(pkv, kn_scale, kn_bias);
    // 4. attention
    attn_kernel<<<dim3(SEQ / BQ, NH, BATCH), 256, attn_smem>>>(pq, pkv, patt);
    // 5. out = att @ proj_w + proj_b
    tf32_gemm_kernel<<<dim3(DIM / 128, MROWS / 128), 256, GEMM_SMEM>>>(patt, proj_w, proj_b, out, MROWS, DIM, DIM);
}

// round 5
// speedup vs baseline: 1.3525x; 1.2090x over previous
#include <cuda_runtime.h>
#include <math.h>

#define DIM 1024
#define NH 16
#define HD 64
#define BATCH 4
#define SEQ 2048
#define MROWS (BATCH*SEQ)   // 8192

// ---------------- scratch (static device memory; no allocations) -------------
__device__ float g_q  [(size_t)MROWS * DIM];      // 32 MB  q (LN+RoPE'd, pre-scaled fp32)
__device__ float g_kv [(size_t)MROWS * 2 * DIM];  // 64 MB  raw kv projection
__device__ float g_att[(size_t)MROWS * DIM];      // 32 MB  attention output
__device__ float g_kh [(size_t)MROWS * DIM];      // 32 MB  k hi (tf32)
__device__ float g_kl [(size_t)MROWS * DIM];      // 32 MB  k lo
__device__ float g_vh [(size_t)MROWS * DIM];      // 32 MB  v hi
__device__ float g_vl [(size_t)MROWS * DIM];      // 32 MB  v lo

// ---------------- tf32 helpers ------------------------------------------------
__device__ __forceinline__ void mma_tf32(float c[4], const unsigned a[4], const unsigned b[2]) {
    asm volatile(
        "mma.sync.aligned.m16n8k8.row.col.f32.tf32.tf32.f32 "
        "{%0,%1,%2,%3}, {%4,%5,%6,%7}, {%8,%9}, {%0,%1,%2,%3};\n"
        : "+f"(c[0]), "+f"(c[1]), "+f"(c[2]), "+f"(c[3])
        : "r"(a[0]), "r"(a[1]), "r"(a[2]), "r"(a[3]), "r"(b[0]), "r"(b[1]));
}
__device__ __forceinline__ unsigned f2tf32(float f) {
    unsigned r;
    asm("cvt.rna.tf32.f32 %0, %1;" : "=r"(r) : "f"(f));
    return r;
}
__device__ __forceinline__ void split_tf32(float f, unsigned& hi, unsigned& lo) {
    hi = f2tf32(f);
    lo = f2tf32(f - __uint_as_float(hi));
}

// =======================  3xTF32 tensor-core GEMM (validated R3)  ============
#define AS_STRIDE 36
#define BS_STRIDE 136
#define A_STAGE (128*AS_STRIDE)
#define B_STAGE (32*BS_STRIDE)
#define GEMM_SMEM ((2*A_STAGE + 2*B_STAGE) * sizeof(float))

__global__ __launch_bounds__(256) void tf32_gemm_kernel(
    const float* __restrict__ A, const float* __restrict__ B,
    const float* __restrict__ bias, float* __restrict__ C,
    int M, int N, int K)
{
    extern __shared__ float sm[];
    float* As = sm;
    float* Bs = sm + 2 * A_STAGE;

    const int tid = threadIdx.x;
    const int warp = tid >> 5, lane = tid & 31;
    const int group = lane >> 2, tig = lane & 3;
    const int wm = (warp & 1) * 64;
    const int wn = (warp >> 1) * 32;
    const int m0 = blockIdx.y * 128, n0 = blockIdx.x * 128;

    const float* Abase = A + (size_t)m0 * K;
    const float* Bbase = B + n0;

    float acc[4][4][4] = {};

#define GEMM_ISSUE(s, k0)                                                          \
    do {                                                                           \
        float* as = As + (s) * A_STAGE;                                            \
        float* bs = Bs + (s) * B_STAGE;                                            \
        _Pragma("unroll")                                                          \
        for (int t = 0; t < 4; t++) {                                              \
            int i = tid + t * 256; int row = i >> 3; int kq = (i & 7) * 4;         \
            unsigned d = (unsigned)__cvta_generic_to_shared(as + row * AS_STRIDE + kq); \
            asm volatile("cp.async.cg.shared.global [%0], [%1], 16;"               \
                         :: "r"(d), "l"(Abase + (size_t)row * K + (k0) + kq));     \
        }                                                                          \
        _Pragma("unroll")                                                          \
        for (int t = 0; t < 4; t++) {                                              \
            int i = tid + t * 256; int kr = i >> 5; int nq = (i & 31) * 4;         \
            unsigned d = (unsigned)__cvta_generic_to_shared(bs + kr * BS_STRIDE + nq); \
            asm volatile("cp.async.cg.shared.global [%0], [%1], 16;"               \
                         :: "r"(d), "l"(Bbase + (size_t)((k0) + kr) * N + nq));    \
        }                                                                          \
        asm volatile("cp.async.commit_group;");                                    \
    } while (0)

    GEMM_ISSUE(0, 0);
    const int NT = K / 32;
    for (int kt = 0; kt < NT; kt++) {
        if (kt + 1 < NT) {
            GEMM_ISSUE((kt + 1) & 1, (kt + 1) * 32);
            asm volatile("cp.async.wait_group 1;");
        } else {
            asm volatile("cp.async.wait_group 0;");
        }
        __syncthreads();

        const float* Asf = As + (kt & 1) * A_STAGE;
        const float* Bsf = Bs + (kt & 1) * B_STAGE;
#pragma unroll
        for (int kb = 0; kb < 4; kb++) {
            unsigned ah[4][4], al[4][4], bh[4][2], bl[4][2];
#pragma unroll
            for (int mi = 0; mi < 4; mi++) {
                int base = (wm + mi * 16 + group) * AS_STRIDE + kb * 8 + tig;
                split_tf32(Asf[base],                     ah[mi][0], al[mi][0]);
                split_tf32(Asf[base + 8 * AS_STRIDE],     ah[mi][1], al[mi][1]);
                split_tf32(Asf[base + 4],                 ah[mi][2], al[mi][2]);
                split_tf32(Asf[base + 8 * AS_STRIDE + 4], ah[mi][3], al[mi][3]);
            }
#pragma unroll
            for (int ni = 0; ni < 4; ni++) {
                int base = (kb * 8 + tig) * BS_STRIDE + wn + ni * 8 + group;
                split_tf32(Bsf[base],                 bh[ni][0], bl[ni][0]);
                split_tf32(Bsf[base + 4 * BS_STRIDE], bh[ni][1], bl[ni][1]);
            }
#pragma unroll
            for (int mi = 0; mi < 4; mi++)
#pragma unroll
                for (int ni = 0; ni < 4; ni++) {
                    mma_tf32(acc[mi][ni], al[mi], bh[ni]);
                    mma_tf32(acc[mi][ni], ah[mi], bl[ni]);
                    mma_tf32(acc[mi][ni], ah[mi], bh[ni]);
                }
        }
        __syncthreads();
    }

#pragma unroll
    for (int mi = 0; mi < 4; mi++) {
#pragma unroll
        for (int ni = 0; ni < 4; ni++) {
            int col = n0 + wn + ni * 8 + tig * 2;
            float bx = 0.f, by = 0.f;
            if (bias) { bx = bias[col]; by = bias[col + 1]; }
            int r0 = m0 + wm + mi * 16 + group;
            float2 v0; v0.x = acc[mi][ni][0] + bx; v0.y = acc[mi][ni][1] + by;
            *(float2*)(C + (size_t)r0 * N + col) = v0;
            float2 v1; v1.x = acc[mi][ni][2] + bx; v1.y = acc[mi][ni][3] + by;
            *(float2*)(C + (size_t)(r0 + 8) * N + col) = v1;
        }
    }
}

// ---------------- per-head LayerNorm (+RoPE + 1/8 scale on q) ----------------
__global__ __launch_bounds__(256) void ln_rope_q_kernel(
    float* __restrict__ q, const float* __restrict__ scale, const float* __restrict__ bias)
{
    int gw = blockIdx.x * 8 + (threadIdx.x >> 5);
    int lane = threadIdx.x & 31;
    int row = gw >> 4;
    int h = gw & 15;
    float* p = q + (size_t)row * DIM + h * HD;
    float e0 = p[lane], e1 = p[lane + 32];
    float ssum = e0 + e1;
#pragma unroll
    for (int o = 16; o; o >>= 1) ssum += __shfl_xor_sync(0xffffffffu, ssum, o);
    float mu = ssum * (1.f / 64.f);
    float d0 = e0 - mu, d1 = e1 - mu;
    float vs = d0 * d0 + d1 * d1;
#pragma unroll
    for (int o = 16; o; o >>= 1) vs += __shfl_xor_sync(0xffffffffu, vs, o);
    float rstd = rsqrtf(vs * (1.f / 64.f) + 1e-5f);
    float n0 = d0 * rstd * scale[lane] + bias[lane];
    float n1 = d1 * rstd * scale[lane + 32] + bias[lane + 32];
    int s = row & (SEQ - 1);
    float invf = powf(10000.f, -(float)lane * (1.f / 32.f));
    float ang = (float)s * invf;
    float sn, c;
    sincosf(ang, &sn, &c);
    p[lane]      = (n0 * c - n1 * sn) * 0.125f;
    p[lane + 32] = (n0 * sn + n1 * c) * 0.125f;
}

// ---------------- k LayerNorm + tf32 split of k and v ------------------------
__global__ __launch_bounds__(256) void ln_k_v_split_kernel(
    const float* __restrict__ kv, const float* __restrict__ scale, const float* __restrict__ bias,
    float* __restrict__ kh, float* __restrict__ kl,
    float* __restrict__ vh, float* __restrict__ vl)
{
    int gw = blockIdx.x * 8 + (threadIdx.x >> 5);
    int lane = threadIdx.x & 31;
    int row = gw >> 4;
    int h = gw & 15;
    const float* p = kv + (size_t)row * (2 * DIM) + h * HD;
    float e0 = p[lane], e1 = p[lane + 32];
    float ssum = e0 + e1;
#pragma unroll
    for (int o = 16; o; o >>= 1) ssum += __shfl_xor_sync(0xffffffffu, ssum, o);
    float mu = ssum * (1.f / 64.f);
    float d0 = e0 - mu, d1 = e1 - mu;
    float vs = d0 * d0 + d1 * d1;
#pragma unroll
    for (int o = 16; o; o >>= 1) vs += __shfl_xor_sync(0xffffffffu, vs, o);
    float rstd = rsqrtf(vs * (1.f / 64.f) + 1e-5f);
    float n0 = d0 * rstd * scale[lane] + bias[lane];
    float n1 = d1 * rstd * scale[lane + 32] + bias[lane + 32];

    size_t oidx = (size_t)row * DIM + h * HD;
    unsigned hi, lo;
    split_tf32(n0, hi, lo);
    kh[oidx + lane] = __uint_as_float(hi); kl[oidx + lane] = __uint_as_float(lo);
    split_tf32(n1, hi, lo);
    kh[oidx + lane + 32] = __uint_as_float(hi); kl[oidx + lane + 32] = __uint_as_float(lo);

    const float* pv = p + DIM;
    float v0 = pv[lane], v1 = pv[lane + 32];
    split_tf32(v0, hi, lo);
    vh[oidx + lane] = __uint_as_float(hi); vl[oidx + lane] = __uint_as_float(lo);
    split_tf32(v1, hi, lo);
    vh[oidx + lane + 32] = __uint_as_float(hi); vl[oidx + lane + 32] = __uint_as_float(lo);
}

// ---------------- tensor-core flash attention (3xTF32) -----------------------
// CTA: 256 thr / 8 warps, BQ=128 (16 rows/warp), key tiles BK=64.
// K/Q/P smem stride 68 (banks 4g+t: conflict-free); V stride 72 (8t+g: cf).
#define KS 68
#define VS 72
#define PSTRIDE 68
#define KS_TILE (64*KS)
#define VS_TILE (64*VS)
#define OFF_KSH 0
#define OFF_KSL (2*KS_TILE)
#define OFF_VSH (4*KS_TILE)
#define OFF_VSL (OFF_VSH + 2*VS_TILE)
#define OFF_PSH (OFF_VSL + 2*VS_TILE)
#define OFF_PSL (OFF_PSH + 128*PSTRIDE)
#define ATTN_SMEM ((OFF_PSL + 128*PSTRIDE) * sizeof(float))   // 212992 B

__global__ __launch_bounds__(256) void attn_tc_kernel(
    const float* __restrict__ q,
    const float* __restrict__ kh, const float* __restrict__ kl,
    const float* __restrict__ vh, const float* __restrict__ vl,
    float* __restrict__ out)
{
    extern __shared__ float sm[];
    const int tid = threadIdx.x;
    const int warp = tid >> 5, lane = tid & 31;
    const int g = lane >> 2, t = lane & 3;
    const int h = blockIdx.y, b = blockIdx.z;
    const int rowbase = b * SEQ + blockIdx.x * 128;
    const int ctxbase = b * SEQ;

    float* Psh = sm + OFF_PSH;
    float* Psl = sm + OFF_PSL;

    // stage Q (fp32) into Psh area
#pragma unroll
    for (int u = 0; u < 8; u++) {
        int i = tid + u * 256;
        int r = i >> 4, c4 = (i & 15) * 4;
        unsigned d = (unsigned)__cvta_generic_to_shared(Psh + r * PSTRIDE + c4);
        asm volatile("cp.async.cg.shared.global [%0], [%1], 16;"
                     :: "r"(d), "l"(q + (size_t)(rowbase + r) * DIM + h * HD + c4));
    }
    asm volatile("cp.async.commit_group;");

#define KV_LOAD(buf, tile)                                                                         \
    do {                                                                                           \
        _Pragma("unroll")                                                                          \
        for (int u = 0; u < 4; u++) {                                                              \
            int i = tid + u * 256;                                                                 \
            int r = i >> 4, c4 = (i & 15) * 4;                                                     \
            size_t src = (size_t)(ctxbase + (tile) * 64 + r) * DIM + h * HD + c4;                  \
            unsigned d0 = (unsigned)__cvta_generic_to_shared(sm + OFF_KSH + (buf) * KS_TILE + r * KS + c4); \
            unsigned d1 = (unsigned)__cvta_generic_to_shared(sm + OFF_KSL + (buf) * KS_TILE + r * KS + c4); \
            unsigned d2 = (unsigned)__cvta_generic_to_shared(sm + OFF_VSH + (buf) * VS_TILE + r * VS + c4); \
            unsigned d3 = (unsigned)__cvta_generic_to_shared(sm + OFF_VSL + (buf) * VS_TILE + r * VS + c4); \
            asm volatile("cp.async.cg.shared.global [%0], [%1], 16;" :: "r"(d0), "l"(kh + src));   \
            asm volatile("cp.async.cg.shared.global [%0], [%1], 16;" :: "r"(d1), "l"(kl + src));   \
            asm volatile("cp.async.cg.shared.global [%0], [%1], 16;" :: "r"(d2), "l"(vh + src));   \
            asm volatile("cp.async.cg.shared.global [%0], [%1], 16;" :: "r"(d3), "l"(vl + src));   \
        }                                                                                          \
        asm volatile("cp.async.commit_group;");                                                    \
    } while (0)

    KV_LOAD(0, 0);
    asm volatile("cp.async.wait_group 1;");   // Q group done
    __syncthreads();

    // Q fragments -> registers (hi/lo), warp-private row band
    unsigned qhf[8][4], qlf[8][4];
#pragma unroll
    for (int kc = 0; kc < 8; kc++) {
        int base = (warp * 16 + g) * PSTRIDE + kc * 8 + t;
        split_tf32(Psh[base],                   qhf[kc][0], qlf[kc][0]);
        split_tf32(Psh[base + 8 * PSTRIDE],     qhf[kc][1], qlf[kc][1]);
        split_tf32(Psh[base + 4],               qhf[kc][2], qlf[kc][2]);
        split_tf32(Psh[base + 8 * PSTRIDE + 4], qhf[kc][3], qlf[kc][3]);
    }

    float o[8][4] = {};
    float m0 = -1e30f, m1 = -1e30f, l0 = 0.f, l1 = 0.f;

    const int NT = SEQ / 64;
    for (int kt = 0; kt < NT; kt++) {
        __syncthreads();                 // all warps done with prev buf reads
        if (kt + 1 < NT) {
            KV_LOAD((kt + 1) & 1, kt + 1);
            asm volatile("cp.async.wait_group 1;");
        } else {
            asm volatile("cp.async.wait_group 0;");
        }
        __syncthreads();                 // tile kt visible everywhere

        const float* Kh = sm + OFF_KSH + (kt & 1) * KS_TILE;
        const float* Kl = sm + OFF_KSL + (kt & 1) * KS_TILE;
        const float* Vh = sm + OFF_VSH + (kt & 1) * VS_TILE;
        const float* Vl = sm + OFF_VSL + (kt & 1) * VS_TILE;

        // ---- S = Q @ K^T ----
        float s[8][4] = {};
#pragma unroll
        for (int kc = 0; kc < 8; kc++) {
#pragma unroll
            for (int nt = 0; nt < 8; nt++) {
                int base = (nt * 8 + g) * KS + kc * 8 + t;
                unsigned bh[2], bl[2];
                bh[0] = __float_as_uint(Kh[base]); bh[1] = __float_as_uint(Kh[base + 4]);
                bl[0] = __float_as_uint(Kl[base]); bl[1] = __float_as_uint(Kl[base + 4]);
                mma_tf32(s[nt], qlf[kc], bh);
                mma_tf32(s[nt], qhf[kc], bl);
                mma_tf32(s[nt], qhf[kc], bh);
            }
        }

        // ---- online softmax (rows g and g+8, warp-local over tig lanes) ----
        float mx0 = s[0][0], mx1 = s[0][2];
#pragma unroll
        for (int nt = 0; nt < 8; nt++) {
            mx0 = fmaxf(mx0, fmaxf(s[nt][0], s[nt][1]));
            mx1 = fmaxf(mx1, fmaxf(s[nt][2], s[nt][3]));
        }
        mx0 = fmaxf(mx0, __shfl_xor_sync(0xffffffffu, mx0, 1));
        mx0 = fmaxf(mx0, __shfl_xor_sync(0xffffffffu, mx0, 2));
        mx1 = fmaxf(mx1, __shfl_xor_sync(0xffffffffu, mx1, 1));
        mx1 = fmaxf(mx1, __shfl_xor_sync(0xffffffffu, mx1, 2));
        float mn0 = fmaxf(m0, mx0), mn1 = fmaxf(m1, mx1);
        float a0 = __expf(m0 - mn0), a1 = __expf(m1 - mn1);
        float sum0 = 0.f, sum1 = 0.f;
#pragma unroll
        for (int nt = 0; nt < 8; nt++) {
            s[nt][0] = __expf(s[nt][0] - mn0); s[nt][1] = __expf(s[nt][1] - mn0);
            s[nt][2] = __expf(s[nt][2] - mn1); s[nt][3] = __expf(s[nt][3] - mn1);
            sum0 += s[nt][0] + s[nt][1];
            sum1 += s[nt][2] + s[nt][3];
        }
        sum0 += __shfl_xor_sync(0xffffffffu, sum0, 1);
        sum0 += __shfl_xor_sync(0xffffffffu, sum0, 2);
        sum1 += __shfl_xor_sync(0xffffffffu, sum1, 1);
        sum1 += __shfl_xor_sync(0xffffffffu, sum1, 2);
        l0 = l0 * a0 + sum0; l1 = l1 * a1 + sum1;
        m0 = mn0; m1 = mn1;
#pragma unroll
        for (int nt = 0; nt < 8; nt++) {
            o[nt][0] *= a0; o[nt][1] *= a0;
            o[nt][2] *= a1; o[nt][3] *= a1;
        }

        // ---- stage P (split hi/lo), warp-private band: no sync needed ----
#pragma unroll
        for (int nt = 0; nt < 8; nt++) {
            unsigned h0, lo0, h1, lo1;
            int base = (warp * 16 + g) * PSTRIDE + nt * 8 + 2 * t;
            split_tf32(s[nt][0], h0, lo0); split_tf32(s[nt][1], h1, lo1);
            *(float2*)&Psh[base] = make_float2(__uint_as_float(h0), __uint_as_float(h1));
            *(float2*)&Psl[base] = make_float2(__uint_as_float(lo0), __uint_as_float(lo1));
            split_tf32(s[nt][2], h0, lo0); split_tf32(s[nt][3], h1, lo1);
            *(float2*)&Psh[base + 8 * PSTRIDE] = make_float2(__uint_as_float(h0), __uint_as_float(h1));
            *(float2*)&Psl[base + 8 * PSTRIDE] = make_float2(__uint_as_float(lo0), __uint_as_float(lo1));
        }

        // ---- O += P @ V ----
#pragma unroll
        for (int kc = 0; kc < 8; kc++) {
            unsigned ah[4], al[4];
            int base = (warp * 16 + g) * PSTRIDE + kc * 8 + t;
            ah[0] = __float_as_uint(Psh[base]);
            ah[1] = __float_as_uint(Psh[base + 8 * PSTRIDE]);
            ah[2] = __float_as_uint(Psh[base + 4]);
            ah[3] = __float_as_uint(Psh[base + 8 * PSTRIDE + 4]);
            al[0] = __float_as_uint(Psl[base]);
            al[1] = __float_as_uint(Psl[base + 8 * PSTRIDE]);
            al[2] = __float_as_uint(Psl[base + 4]);
            al[3] = __float_as_uint(Psl[base + 8 * PSTRIDE + 4]);
#pragma unroll
            for (int nt = 0; nt < 8; nt++) {
                int bb = (kc * 8 + t) * VS + nt * 8 + g;
                unsigned bh[2], bl[2];
                bh[0] = __float_as_uint(Vh[bb]); bh[1] = __float_as_uint(Vh[bb + 4 * VS]);
                bl[0] = __float_as_uint(Vl[bb]); bl[1] = __float_as_uint(Vl[bb + 4 * VS]);
                mma_tf32(o[nt], al, bh);
                mma_tf32(o[nt], ah, bl);
                mma_tf32(o[nt], ah, bh);
            }
        }
    }

    // ---- normalize + write ----
    float i0 = 1.f / l0, i1 = 1.f / l1;
    int r0 = rowbase + warp * 16 + g;
#pragma unroll
    for (int nt = 0; nt < 8; nt++) {
        int col = h * HD + nt * 8 + 2 * t;
        *(float2*)(out + (size_t)r0 * DIM + col) = make_float2(o[nt][0] * i0, o[nt][1] * i0);
        *(float2*)(out + (size_t)(r0 + 8) * DIM + col) = make_float2(o[nt][2] * i1, o[nt][3] * i1);
    }
}

// ---------------- launch ------------------------------------------------------
extern "C" void kernel_launch(void* const* d_in, const int* in_sizes, int n_in,
                              void* d_out, int out_size)
{
    const float* x        = (const float*)d_in[0];
    const float* context  = (const float*)d_in[1];
    const float* q_w      = (const float*)d_in[2];
    const float* kv_w     = (const float*)d_in[3];
    const float* qn_scale = (const float*)d_in[4];
    const float* qn_bias  = (const float*)d_in[5];
    const float* kn_scale = (const float*)d_in[6];
    const float* kn_bias  = (const float*)d_in[7];
    const float* proj_w   = (const float*)d_in[8];
    const float* proj_b   = (const float*)d_in[9];
    float* out = (float*)d_out;

    float *pq, *pkv, *patt, *pkh, *pkl, *pvh, *pvl;
    cudaGetSymbolAddress((void**)&pq,  g_q);
    cudaGetSymbolAddress((void**)&pkv, g_kv);
    cudaGetSymbolAddress((void**)&patt, g_att);
    cudaGetSymbolAddress((void**)&pkh, g_kh);
    cudaGetSymbolAddress((void**)&pkl, g_kl);
    cudaGetSymbolAddress((void**)&pvh, g_vh);
    cudaGetSymbolAddress((void**)&pvl, g_vl);

    cudaFuncSetAttribute(tf32_gemm_kernel, cudaFuncAttributeMaxDynamicSharedMemorySize, (int)GEMM_SMEM);
    cudaFuncSetAttribute(attn_tc_kernel, cudaFuncAttributeMaxDynamicSharedMemorySize, (int)ATTN_SMEM);

    // 1. q = x @ q_w
    tf32_gemm_kernel<<<dim3(DIM / 128, MROWS / 128), 256, GEMM_SMEM>>>(x, q_w, nullptr, pq, MROWS, DIM, DIM);
    // 2. kv = context @ kv_w
    tf32_gemm_kernel<<<dim3(2 * DIM / 128, MROWS / 128), 256, GEMM_SMEM>>>(context, kv_w, nullptr, pkv, MROWS, 2 * DIM, DIM);
    // 3. per-head LN (+RoPE+scale on q); k LN + split, v split
    ln_rope_q_kernel<<<MROWS * NH / 8, 256>>>(pq, qn_scale, qn_bias);
    ln_k_v_split_kernel<<<MROWS * NH / 8, 256>>>(pkv, kn_scale, kn_bias, pkh, pkl, pvh, pvl);
    // 4. attention (tensor cores, 3xTF32)
    attn_tc_kernel<<<dim3(SEQ / 128, NH, BATCH), 256, ATTN_SMEM>>>(pq, pkh, pkl, pvh, pvl, patt);
    // 5. out = att @ proj_w + proj_b
    tf32_gemm_kernel<<<dim3(DIM / 128, MROWS / 128), 256, GEMM_SMEM>>>(patt, proj_w, proj_b, out, MROWS, DIM, DIM);
}

// round 7
// speedup vs baseline: 1.7809x; 1.3167x over previous
#include <cuda_runtime.h>
#include <cuda_bf16.h>
#include <math.h>

#define DIM 1024
#define NH 16
#define HD 64
#define BATCH 4
#define SEQ 2048
#define MROWS (BATCH*SEQ)   // 8192

// ---------------- scratch (static device memory; no allocations) -------------
__device__ float g_q  [(size_t)MROWS * DIM];            // 32 MB q (LN+RoPE, pre-scaled)
__device__ float g_kv [(size_t)MROWS * 2 * DIM];        // 64 MB raw kv projection
__device__ float g_att[(size_t)MROWS * DIM];            // 32 MB attention output
__device__ __nv_bfloat16 g_kh[(size_t)MROWS * DIM];     // 16 MB k hi
__device__ __nv_bfloat16 g_kl[(size_t)MROWS * DIM];     // 16 MB k lo
__device__ __nv_bfloat16 g_vh[(size_t)MROWS * DIM];     // 16 MB v hi
__device__ __nv_bfloat16 g_vl[(size_t)MROWS * DIM];     // 16 MB v lo

// ---------------- helpers -----------------------------------------------------
__device__ __forceinline__ void mma_tf32(float c[4], const unsigned a[4], const unsigned b[2]) {
    asm volatile(
        "mma.sync.aligned.m16n8k8.row.col.f32.tf32.tf32.f32 "
        "{%0,%1,%2,%3}, {%4,%5,%6,%7}, {%8,%9}, {%0,%1,%2,%3};\n"
        : "+f"(c[0]), "+f"(c[1]), "+f"(c[2]), "+f"(c[3])
        : "r"(a[0]), "r"(a[1]), "r"(a[2]), "r"(a[3]), "r"(b[0]), "r"(b[1]));
}
__device__ __forceinline__ void mma_bf16(float c[4], const unsigned a[4], const unsigned b[2]) {
    asm volatile(
        "mma.sync.aligned.m16n8k16.row.col.f32.bf16.bf16.f32 "
        "{%0,%1,%2,%3}, {%4,%5,%6,%7}, {%8,%9}, {%0,%1,%2,%3};\n"
        : "+f"(c[0]), "+f"(c[1]), "+f"(c[2]), "+f"(c[3])
        : "r"(a[0]), "r"(a[1]), "r"(a[2]), "r"(a[3]), "r"(b[0]), "r"(b[1]));
}
__device__ __forceinline__ unsigned f2tf32(float f) {
    unsigned r;
    asm("cvt.rna.tf32.f32 %0, %1;" : "=r"(r) : "f"(f));
    return r;
}
__device__ __forceinline__ void split_tf32(float f, unsigned& hi, unsigned& lo) {
    hi = f2tf32(f);
    lo = f2tf32(f - __uint_as_float(hi));
}
__device__ __forceinline__ unsigned pack_bf16(float x, float y) {
    __nv_bfloat162 v = __floats2bfloat162_rn(x, y);
    return *(unsigned*)&v;
}
__device__ __forceinline__ void ldsm_x4(unsigned& r0, unsigned& r1, unsigned& r2, unsigned& r3, unsigned addr) {
    asm volatile("ldmatrix.sync.aligned.m8n8.x4.shared.b16 {%0,%1,%2,%3}, [%4];"
                 : "=r"(r0), "=r"(r1), "=r"(r2), "=r"(r3) : "r"(addr));
}
__device__ __forceinline__ void ldsm_x4_t(unsigned& r0, unsigned& r1, unsigned& r2, unsigned& r3, unsigned addr) {
    asm volatile("ldmatrix.sync.aligned.m8n8.x4.trans.shared.b16 {%0,%1,%2,%3}, [%4];"
                 : "=r"(r0), "=r"(r1), "=r"(r2), "=r"(r3) : "r"(addr));
}

// =======================  3xTF32 tensor-core GEMM (validated)  ===============
#define AS_STRIDE 36
#define BS_STRIDE 136
#define A_STAGE (128*AS_STRIDE)
#define B_STAGE (32*BS_STRIDE)
#define GEMM_SMEM ((2*A_STAGE + 2*B_STAGE) * sizeof(float))

__global__ __launch_bounds__(256) void tf32_gemm_kernel(
    const float* __restrict__ A, const float* __restrict__ B,
    const float* __restrict__ bias, float* __restrict__ C,
    int M, int N, int K)
{
    extern __shared__ float smf[];
    float* As = smf;
    float* Bs = smf + 2 * A_STAGE;

    const int tid = threadIdx.x;
    const int warp = tid >> 5, lane = tid & 31;
    const int group = lane >> 2, tig = lane & 3;
    const int wm = (warp & 1) * 64;
    const int wn = (warp >> 1) * 32;
    const int m0 = blockIdx.y * 128, n0 = blockIdx.x * 128;

    const float* Abase = A + (size_t)m0 * K;
    const float* Bbase = B + n0;

    float acc[4][4][4] = {};

#define GEMM_ISSUE(s, k0)                                                          \
    do {                                                                           \
        float* as = As + (s) * A_STAGE;                                            \
        float* bs = Bs + (s) * B_STAGE;                                            \
        _Pragma("unroll")                                                          \
        for (int t = 0; t < 4; t++) {                                              \
            int i = tid + t * 256; int row = i >> 3; int kq = (i & 7) * 4;         \
            unsigned d = (unsigned)__cvta_generic_to_shared(as + row * AS_STRIDE + kq); \
            asm volatile("cp.async.cg.shared.global [%0], [%1], 16;"               \
                         :: "r"(d), "l"(Abase + (size_t)row * K + (k0) + kq));     \
        }                                                                          \
        _Pragma("unroll")                                                          \
        for (int t = 0; t < 4; t++) {                                              \
            int i = tid + t * 256; int kr = i >> 5; int nq = (i & 31) * 4;         \
            unsigned d = (unsigned)__cvta_generic_to_shared(bs + kr * BS_STRIDE + nq); \
            asm volatile("cp.async.cg.shared.global [%0], [%1], 16;"               \
                         :: "r"(d), "l"(Bbase + (size_t)((k0) + kr) * N + nq));    \
        }                                                                          \
        asm volatile("cp.async.commit_group;");                                    \
    } while (0)

    GEMM_ISSUE(0, 0);
    const int NT = K / 32;
    for (int kt = 0; kt < NT; kt++) {
        if (kt + 1 < NT) {
            GEMM_ISSUE((kt + 1) & 1, (kt + 1) * 32);
            asm volatile("cp.async.wait_group 1;");
        } else {
            asm volatile("cp.async.wait_group 0;");
        }
        __syncthreads();

        const float* Asf = As + (kt & 1) * A_STAGE;
        const float* Bsf = Bs + (kt & 1) * B_STAGE;
#pragma unroll
        for (int kb = 0; kb < 4; kb++) {
            unsigned ah[4][4], al[4][4], bh[4][2], bl[4][2];
#pragma unroll
            for (int mi = 0; mi < 4; mi++) {
                int base = (wm + mi * 16 + group) * AS_STRIDE + kb * 8 + tig;
                split_tf32(Asf[base],                     ah[mi][0], al[mi][0]);
                split_tf32(Asf[base + 8 * AS_STRIDE],     ah[mi][1], al[mi][1]);
                split_tf32(Asf[base + 4],                 ah[mi][2], al[mi][2]);
                split_tf32(Asf[base + 8 * AS_STRIDE + 4], ah[mi][3], al[mi][3]);
            }
#pragma unroll
            for (int ni = 0; ni < 4; ni++) {
                int base = (kb * 8 + tig) * BS_STRIDE + wn + ni * 8 + group;
                split_tf32(Bsf[base],                 bh[ni][0], bl[ni][0]);
                split_tf32(Bsf[base + 4 * BS_STRIDE], bh[ni][1], bl[ni][1]);
            }
#pragma unroll
            for (int mi = 0; mi < 4; mi++)
#pragma unroll
                for (int ni = 0; ni < 4; ni++) {
                    mma_tf32(acc[mi][ni], al[mi], bh[ni]);
                    mma_tf32(acc[mi][ni], ah[mi], bl[ni]);
                    mma_tf32(acc[mi][ni], ah[mi], bh[ni]);
                }
        }
        __syncthreads();
    }

#pragma unroll
    for (int mi = 0; mi < 4; mi++) {
#pragma unroll
        for (int ni = 0; ni < 4; ni++) {
            int col = n0 + wn + ni * 8 + tig * 2;
            float bx = 0.f, by = 0.f;
            if (bias) { bx = bias[col]; by = bias[col + 1]; }
            int r0 = m0 + wm + mi * 16 + group;
            float2 v0; v0.x = acc[mi][ni][0] + bx; v0.y = acc[mi][ni][1] + by;
            *(float2*)(C + (size_t)r0 * N + col) = v0;
            float2 v1; v1.x = acc[mi][ni][2] + bx; v1.y = acc[mi][ni][3] + by;
            *(float2*)(C + (size_t)(r0 + 8) * N + col) = v1;
        }
    }
}

// ---------------- per-head LayerNorm (+RoPE + 1/8 scale on q) ----------------
__global__ __launch_bounds__(256) void ln_rope_q_kernel(
    float* __restrict__ q, const float* __restrict__ scale, const float* __restrict__ bias)
{
    int gw = blockIdx.x * 8 + (threadIdx.x >> 5);
    int lane = threadIdx.x & 31;
    int row = gw >> 4;
    int h = gw & 15;
    float* p = q + (size_t)row * DIM + h * HD;
    float e0 = p[lane], e1 = p[lane + 32];
    float ssum = e0 + e1;
#pragma unroll
    for (int o = 16; o; o >>= 1) ssum += __shfl_xor_sync(0xffffffffu, ssum, o);
    float mu = ssum * (1.f / 64.f);
    float d0 = e0 - mu, d1 = e1 - mu;
    float vs = d0 * d0 + d1 * d1;
#pragma unroll
    for (int o = 16; o; o >>= 1) vs += __shfl_xor_sync(0xffffffffu, vs, o);
    float rstd = rsqrtf(vs * (1.f / 64.f) + 1e-5f);
    float n0 = d0 * rstd * scale[lane] + bias[lane];
    float n1 = d1 * rstd * scale[lane + 32] + bias[lane + 32];
    int s = row & (SEQ - 1);
    float invf = powf(10000.f, -(float)lane * (1.f / 32.f));
    float ang = (float)s * invf;
    float sn, c;
    sincosf(ang, &sn, &c);
    p[lane]      = (n0 * c - n1 * sn) * 0.125f;
    p[lane + 32] = (n0 * sn + n1 * c) * 0.125f;
}

// ---------------- k LayerNorm + bf16 hi/lo split of k and v ------------------
__global__ __launch_bounds__(256) void ln_k_v_split_kernel(
    const float* __restrict__ kv, const float* __restrict__ scale, const float* __restrict__ bias,
    __nv_bfloat16* __restrict__ kh, __nv_bfloat16* __restrict__ kl,
    __nv_bfloat16* __restrict__ vh, __nv_bfloat16* __restrict__ vl)
{
    int gw = blockIdx.x * 8 + (threadIdx.x >> 5);
    int lane = threadIdx.x & 31;
    int row = gw >> 4;
    int h = gw & 15;
    const float* p = kv + (size_t)row * (2 * DIM) + h * HD;
    float e0 = p[lane], e1 = p[lane + 32];
    float ssum = e0 + e1;
#pragma unroll
    for (int o = 16; o; o >>= 1) ssum += __shfl_xor_sync(0xffffffffu, ssum, o);
    float mu = ssum * (1.f / 64.f);
    float d0 = e0 - mu, d1 = e1 - mu;
    float vs = d0 * d0 + d1 * d1;
#pragma unroll
    for (int o = 16; o; o >>= 1) vs += __shfl_xor_sync(0xffffffffu, vs, o);
    float rstd = rsqrtf(vs * (1.f / 64.f) + 1e-5f);
    float n0 = d0 * rstd * scale[lane] + bias[lane];
    float n1 = d1 * rstd * scale[lane + 32] + bias[lane + 32];

    size_t oidx = (size_t)row * DIM + h * HD;
    __nv_bfloat16 bh;
    bh = __float2bfloat16_rn(n0);
    kh[oidx + lane] = bh; kl[oidx + lane] = __float2bfloat16_rn(n0 - __bfloat162float(bh));
    bh = __float2bfloat16_rn(n1);
    kh[oidx + lane + 32] = bh; kl[oidx + lane + 32] = __float2bfloat16_rn(n1 - __bfloat162float(bh));

    const float* pv = p + DIM;
    float v0 = pv[lane], v1 = pv[lane + 32];
    bh = __float2bfloat16_rn(v0);
    vh[oidx + lane] = bh; vl[oidx + lane] = __float2bfloat16_rn(v0 - __bfloat162float(bh));
    bh = __float2bfloat16_rn(v1);
    vh[oidx + lane + 32] = bh; vl[oidx + lane + 32] = __float2bfloat16_rn(v1 - __bfloat162float(bh));
}

// ---------------- bf16x3 ldmatrix flash attention ----------------------------
// CTA 256 thr / 8 warps, BQ=128 (16 rows/warp), key tiles BK=64.
// smem rows: 72 b16 (144 B) -> ldmatrix phases hit banks 4r..4r+3, conflict-free.
#define KROW 144
#define KTILE (64*KROW)            // 9216 B
#define OFF_KH 0                   // [2][KTILE]
#define OFF_KL (2*KTILE)
#define OFF_VH (4*KTILE)
#define OFF_VL (6*KTILE)
#define OFF_PH (8*KTILE)           // 73728, [128][144] = 18432 B
#define OFF_PL (OFF_PH + 128*KROW)
#define ATTN_SMEM (OFF_PL + 128*KROW)   // 110592 B

__global__ __launch_bounds__(256) void attn_tc_kernel(
    const float* __restrict__ q,
    const __nv_bfloat16* __restrict__ kh, const __nv_bfloat16* __restrict__ kl,
    const __nv_bfloat16* __restrict__ vh, const __nv_bfloat16* __restrict__ vl,
    float* __restrict__ out)
{
    extern __shared__ char smc[];
    char* sm = smc;
    const int tid = threadIdx.x;
    const int warp = tid >> 5, lane = tid & 31;
    const int g = lane >> 2, t = lane & 3;
    const int mat = lane >> 3, r = lane & 7;       // ldmatrix lane mapping
    const int h = blockIdx.y, b = blockIdx.z;
    const int rowbase = b * SEQ + blockIdx.x * 128;
    const int ctxbase = b * SEQ;

    // ---- stage Q (fp32) into P area ----
#pragma unroll
    for (int u = 0; u < 8; u++) {
        int i = tid + u * 256;
        int row = i >> 4, c4 = (i & 15) * 4;
        unsigned d = (unsigned)__cvta_generic_to_shared(sm + OFF_PH + row * 256 + c4 * 4);
        asm volatile("cp.async.cg.shared.global [%0], [%1], 16;"
                     :: "r"(d), "l"(q + (size_t)(rowbase + row) * DIM + h * HD + c4));
    }
    asm volatile("cp.async.commit_group;");

#define KV_LOAD(buf, tile)                                                                     \
    do {                                                                                       \
        _Pragma("unroll")                                                                      \
        for (int u = 0; u < 2; u++) {                                                          \
            int i = tid + u * 256;                                                             \
            int key = i >> 3, c = i & 7;                                                       \
            size_t src = ((size_t)(ctxbase + (tile) * 64 + key) << 10) + h * HD + c * 8;       \
            unsigned dst = (unsigned)__cvta_generic_to_shared(sm + (buf) * KTILE + key * KROW + c * 16); \
            asm volatile("cp.async.cg.shared.global [%0], [%1], 16;" :: "r"(dst + OFF_KH), "l"(kh + src)); \
            asm volatile("cp.async.cg.shared.global [%0], [%1], 16;" :: "r"(dst + OFF_KL), "l"(kl + src)); \
            asm volatile("cp.async.cg.shared.global [%0], [%1], 16;" :: "r"(dst + OFF_VH), "l"(vh + src)); \
            asm volatile("cp.async.cg.shared.global [%0], [%1], 16;" :: "r"(dst + OFF_VL), "l"(vl + src)); \
        }                                                                                      \
        asm volatile("cp.async.commit_group;");                                                \
    } while (0)

    KV_LOAD(0, 0);
    asm volatile("cp.async.wait_group 1;");   // Q staged
    __syncthreads();

    // ---- Q fragments (bf16 hi/lo), warp-private rows ----
    unsigned qh[4][4], ql[4][4];
    {
        const float* Qs = (const float*)(sm + OFF_PH);
        int row = warp * 16 + g;
#pragma unroll
        for (int kc = 0; kc < 4; kc++) {
            int d0 = kc * 16 + 2 * t;
#pragma unroll
            for (int a = 0; a < 4; a++) {
                int rr = row + (a & 1) * 8;
                int dd = d0 + (a >> 1) * 8;
                float x = Qs[rr * 64 + dd], y = Qs[rr * 64 + dd + 1];
                float xh = __bfloat162float(__float2bfloat16_rn(x));
                float yh = __bfloat162float(__float2bfloat16_rn(y));
                qh[kc][a] = pack_bf16(xh, yh);
                ql[kc][a] = pack_bf16(x - xh, y - yh);
            }
        }
    }

    float o[8][4] = {};
    float m0 = -1e30f, m1 = -1e30f, l0 = 0.f, l1 = 0.f;

    const unsigned smbase = (unsigned)__cvta_generic_to_shared(sm);
    // per-lane ldmatrix address components
    const unsigned kpre = (mat >> 1) * 8 * KROW + r * KROW + (mat & 1) * 16;        // K: keys block + d half
    const unsigned ppre = (warp * 16 + (mat & 1) * 8 + r) * KROW + (mat >> 1) * 16; // P: rows + key half
    const unsigned vpre = (mat & 1) * 8 * KROW + r * KROW + (mat >> 1) * 16;        // V: key half + d block

    const int NT = SEQ / 64;
    for (int kt = 0; kt < NT; kt++) {
        __syncthreads();
        if (kt + 1 < NT) {
            KV_LOAD((kt + 1) & 1, kt + 1);
            asm volatile("cp.async.wait_group 1;");
        } else {
            asm volatile("cp.async.wait_group 0;");
        }
        __syncthreads();

        const unsigned buf = (kt & 1) * KTILE;

        // ---- S = Q @ K^T ----
        float s[8][4] = {};
#pragma unroll
        for (int kc = 0; kc < 4; kc++) {
#pragma unroll
            for (int ntp = 0; ntp < 4; ntp++) {
                unsigned aK = smbase + buf + ntp * (16 * KROW) + kc * 32 + kpre;
                unsigned h0, h1, h2, h3, lo0, lo1, lo2, lo3;
                ldsm_x4(h0, h1, h2, h3, aK + OFF_KH);
                ldsm_x4(lo0, lo1, lo2, lo3, aK + OFF_KL);
                unsigned bh0[2] = {h0, h1}, bh1[2] = {h2, h3};
                unsigned bl0[2] = {lo0, lo1}, bl1[2] = {lo2, lo3};
                mma_bf16(s[2 * ntp],     ql[kc], bh0);
                mma_bf16(s[2 * ntp],     qh[kc], bl0);
                mma_bf16(s[2 * ntp],     qh[kc], bh0);
                mma_bf16(s[2 * ntp + 1], ql[kc], bh1);
                mma_bf16(s[2 * ntp + 1], qh[kc], bl1);
                mma_bf16(s[2 * ntp + 1], qh[kc], bh1);
            }
        }

        // ---- online softmax (rows g, g+8; warp-local over 4 tig lanes) ----
        float mx0 = s[0][0], mx1 = s[0][2];
#pragma unroll
        for (int nt = 0; nt < 8; nt++) {
            mx0 = fmaxf(mx0, fmaxf(s[nt][0], s[nt][1]));
            mx1 = fmaxf(mx1, fmaxf(s[nt][2], s[nt][3]));
        }
        mx0 = fmaxf(mx0, __shfl_xor_sync(0xffffffffu, mx0, 1));
        mx0 = fmaxf(mx0, __shfl_xor_sync(0xffffffffu, mx0, 2));
        mx1 = fmaxf(mx1, __shfl_xor_sync(0xffffffffu, mx1, 1));
        mx1 = fmaxf(mx1, __shfl_xor_sync(0xffffffffu, mx1, 2));
        float mn0 = fmaxf(m0, mx0), mn1 = fmaxf(m1, mx1);
        float a0 = __expf(m0 - mn0), a1 = __expf(m1 - mn1);
        float sum0 = 0.f, sum1 = 0.f;
#pragma unroll
        for (int nt = 0; nt < 8; nt++) {
            s[nt][0] = __expf(s[nt][0] - mn0); s[nt][1] = __expf(s[nt][1] - mn0);
            s[nt][2] = __expf(s[nt][2] - mn1); s[nt][3] = __expf(s[nt][3] - mn1);
            sum0 += s[nt][0] + s[nt][1];
            sum1 += s[nt][2] + s[nt][3];
        }
        sum0 += __shfl_xor_sync(0xffffffffu, sum0, 1);
        sum0 += __shfl_xor_sync(0xffffffffu, sum0, 2);
        sum1 += __shfl_xor_sync(0xffffffffu, sum1, 1);
        sum1 += __shfl_xor_sync(0xffffffffu, sum1, 2);
        l0 = l0 * a0 + sum0; l1 = l1 * a1 + sum1;
        m0 = mn0; m1 = mn1;
#pragma unroll
        for (int nt = 0; nt < 8; nt++) {
            o[nt][0] *= a0; o[nt][1] *= a0;
            o[nt][2] *= a1; o[nt][3] *= a1;
        }

        // ---- stage P (bf16 hi/lo), warp-private row band ----
#pragma unroll
        for (int nt = 0; nt < 8; nt++) {
            int byte0 = (warp * 16 + g) * KROW + (nt * 8 + 2 * t) * 2;
            float p0 = s[nt][0], p1 = s[nt][1];
            float p0h = __bfloat162float(__float2bfloat16_rn(p0));
            float p1h = __bfloat162float(__float2bfloat16_rn(p1));
            *(unsigned*)(sm + OFF_PH + byte0) = pack_bf16(p0h, p1h);
            *(unsigned*)(sm + OFF_PL + byte0) = pack_bf16(p0 - p0h, p1 - p1h);
            int byte1 = byte0 + 8 * KROW;
            float p2 = s[nt][2], p3 = s[nt][3];
            float p2h = __bfloat162float(__float2bfloat16_rn(p2));
            float p3h = __bfloat162float(__float2bfloat16_rn(p3));
            *(unsigned*)(sm + OFF_PH + byte1) = pack_bf16(p2h, p3h);
            *(unsigned*)(sm + OFF_PL + byte1) = pack_bf16(p2 - p2h, p3 - p3h);
        }
        __syncwarp();

        // ---- O += P @ V ----
#pragma unroll
        for (int kc = 0; kc < 4; kc++) {
            unsigned aP = smbase + kc * 32 + ppre;
            unsigned pah[4], pal[4];
            ldsm_x4(pah[0], pah[1], pah[2], pah[3], aP + OFF_PH);
            ldsm_x4(pal[0], pal[1], pal[2], pal[3], aP + OFF_PL);
#pragma unroll
            for (int ntp = 0; ntp < 4; ntp++) {
                unsigned aV = smbase + buf + kc * (16 * KROW) + ntp * 32 + vpre;
                unsigned h0, h1, h2, h3, lo0, lo1, lo2, lo3;
                ldsm_x4_t(h0, h1, h2, h3, aV + OFF_VH);
                ldsm_x4_t(lo0, lo1, lo2, lo3, aV + OFF_VL);
                unsigned bh0[2] = {h0, h1}, bh1[2] = {h2, h3};
                unsigned bl0[2] = {lo0, lo1}, bl1[2] = {lo2, lo3};
                mma_bf16(o[2 * ntp],     pal, bh0);
                mma_bf16(o[2 * ntp],     pah, bl0);
                mma_bf16(o[2 * ntp],     pah, bh0);
                mma_bf16(o[2 * ntp + 1], pal, bh1);
                mma_bf16(o[2 * ntp + 1], pah, bl1);
                mma_bf16(o[2 * ntp + 1], pah, bh1);
            }
        }
    }

    // ---- normalize + write ----
    float i0 = 1.f / l0, i1 = 1.f / l1;
    int r0 = rowbase + warp * 16 + g;
#pragma unroll
    for (int nt = 0; nt < 8; nt++) {
        int col = h * HD + nt * 8 + 2 * t;
        *(float2*)(out + (size_t)r0 * DIM + col) = make_float2(o[nt][0] * i0, o[nt][1] * i0);
        *(float2*)(out + (size_t)(r0 + 8) * DIM + col) = make_float2(o[nt][2] * i1, o[nt][3] * i1);
    }
}

// ---------------- launch ------------------------------------------------------
extern "C" void kernel_launch(void* const* d_in, const int* in_sizes, int n_in,
                              void* d_out, int out_size)
{
    const float* x        = (const float*)d_in[0];
    const float* context  = (const float*)d_in[1];
    const float* q_w      = (const float*)d_in[2];
    const float* kv_w     = (const float*)d_in[3];
    const float* qn_scale = (const float*)d_in[4];
    const float* qn_bias  = (const float*)d_in[5];
    const float* kn_scale = (const float*)d_in[6];
    const float* kn_bias  = (const float*)d_in[7];
    const float* proj_w   = (const float*)d_in[8];
    const float* proj_b   = (const float*)d_in[9];
    float* out = (float*)d_out;

    float *pq, *pkv, *patt;
    __nv_bfloat16 *pkh, *pkl, *pvh, *pvl;
    cudaGetSymbolAddress((void**)&pq,  g_q);
    cudaGetSymbolAddress((void**)&pkv, g_kv);
    cudaGetSymbolAddress((void**)&patt, g_att);
    cudaGetSymbolAddress((void**)&pkh, g_kh);
    cudaGetSymbolAddress((void**)&pkl, g_kl);
    cudaGetSymbolAddress((void**)&pvh, g_vh);
    cudaGetSymbolAddress((void**)&pvl, g_vl);

    cudaFuncSetAttribute(tf32_gemm_kernel, cudaFuncAttributeMaxDynamicSharedMemorySize, (int)GEMM_SMEM);
    cudaFuncSetAttribute(attn_tc_kernel, cudaFuncAttributeMaxDynamicSharedMemorySize, (int)ATTN_SMEM);

    // 1. q = x @ q_w
    tf32_gemm_kernel<<<dim3(DIM / 128, MROWS / 128), 256, GEMM_SMEM>>>(x, q_w, nullptr, pq, MROWS, DIM, DIM);
    // 2. kv = context @ kv_w
    tf32_gemm_kernel<<<dim3(2 * DIM / 128, MROWS / 128), 256, GEMM_SMEM>>>(context, kv_w, nullptr, pkv, MROWS, 2 * DIM, DIM);
    // 3. per-head LN (+RoPE+scale on q); k LN + bf16 split, v bf16 split
    ln_rope_q_kernel<<<MROWS * NH / 8, 256>>>(pq, qn_scale, qn_bias);
    ln_k_v_split_kernel<<<MROWS * NH / 8, 256>>>(pkv, kn_scale, kn_bias, pkh, pkl, pvh, pvl);
    // 4. attention (bf16x3 + ldmatrix)
    attn_tc_kernel<<<dim3(SEQ / 128, NH, BATCH), 256, ATTN_SMEM>>>(pq, pkh, pkl, pvh, pvl, patt);
    // 5. out = att @ proj_w + proj_b
    tf32_gemm_kernel<<<dim3(DIM / 128, MROWS / 128), 256, GEMM_SMEM>>>(patt, proj_w, proj_b, out, MROWS, DIM, DIM);
}

// round 9
// speedup vs baseline: 2.7371x; 1.5369x over previous
#include <cuda_runtime.h>
#include <cuda_bf16.h>
#include <math.h>

#define DIM 1024
#define NH 16
#define HD 64
#define BATCH 4
#define SEQ 2048
#define MROWS (BATCH*SEQ)   // 8192

// ---------------- scratch (static device memory; no allocations) -------------
__device__ float g_q  [(size_t)MROWS * DIM];            // q proj (fp32, LN+RoPE in place)
__device__ float g_kv [(size_t)MROWS * 2 * DIM];        // raw kv projection fp32
__device__ __nv_bfloat16 g_kh[(size_t)MROWS * DIM];     // k hi
__device__ __nv_bfloat16 g_kl[(size_t)MROWS * DIM];     // k lo
__device__ __nv_bfloat16 g_vh[(size_t)MROWS * DIM];     // v hi
__device__ __nv_bfloat16 g_vl[(size_t)MROWS * DIM];     // v lo
__device__ __nv_bfloat16 g_ah[(size_t)MROWS * DIM];     // attention out hi
__device__ __nv_bfloat16 g_al[(size_t)MROWS * DIM];     // attention out lo
__device__ __nv_bfloat16 g_xh[(size_t)MROWS * DIM];     // x hi/lo
__device__ __nv_bfloat16 g_xl[(size_t)MROWS * DIM];
__device__ __nv_bfloat16 g_ch[(size_t)MROWS * DIM];     // context hi/lo
__device__ __nv_bfloat16 g_cl[(size_t)MROWS * DIM];
__device__ __nv_bfloat16 g_qwh[(size_t)DIM * DIM];      // weights hi/lo
__device__ __nv_bfloat16 g_qwl[(size_t)DIM * DIM];
__device__ __nv_bfloat16 g_kvwh[(size_t)DIM * 2 * DIM];
__device__ __nv_bfloat16 g_kvwl[(size_t)DIM * 2 * DIM];
__device__ __nv_bfloat16 g_pwh[(size_t)DIM * DIM];
__device__ __nv_bfloat16 g_pwl[(size_t)DIM * DIM];

// ---------------- helpers -----------------------------------------------------
__device__ __forceinline__ void mma_bf16(float c[4], const unsigned a[4], const unsigned b[2]) {
    asm volatile(
        "mma.sync.aligned.m16n8k16.row.col.f32.bf16.bf16.f32 "
        "{%0,%1,%2,%3}, {%4,%5,%6,%7}, {%8,%9}, {%0,%1,%2,%3};\n"
        : "+f"(c[0]), "+f"(c[1]), "+f"(c[2]), "+f"(c[3])
        : "r"(a[0]), "r"(a[1]), "r"(a[2]), "r"(a[3]), "r"(b[0]), "r"(b[1]));
}
__device__ __forceinline__ unsigned pack_bf16(float x, float y) {
    __nv_bfloat162 v = __floats2bfloat162_rn(x, y);
    return *(unsigned*)&v;
}
__device__ __forceinline__ void ldsm_x4(unsigned& r0, unsigned& r1, unsigned& r2, unsigned& r3, unsigned addr) {
    asm volatile("ldmatrix.sync.aligned.m8n8.x4.shared.b16 {%0,%1,%2,%3}, [%4];"
                 : "=r"(r0), "=r"(r1), "=r"(r2), "=r"(r3) : "r"(addr));
}
__device__ __forceinline__ void ldsm_x4_t(unsigned& r0, unsigned& r1, unsigned& r2, unsigned& r3, unsigned addr) {
    asm volatile("ldmatrix.sync.aligned.m8n8.x4.trans.shared.b16 {%0,%1,%2,%3}, [%4];"
                 : "=r"(r0), "=r"(r1), "=r"(r2), "=r"(r3) : "r"(addr));
}

// ---------------- elementwise fp32 -> bf16 hi/lo split ------------------------
__global__ __launch_bounds__(256) void split_bf16_kernel(
    const float* __restrict__ in, __nv_bfloat16* __restrict__ hi, __nv_bfloat16* __restrict__ lo)
{
    size_t i = ((size_t)blockIdx.x * 256 + threadIdx.x) * 4;
    float4 v = *(const float4*)(in + i);
    float hx = __bfloat162float(__float2bfloat16_rn(v.x));
    float hy = __bfloat162float(__float2bfloat16_rn(v.y));
    float hz = __bfloat162float(__float2bfloat16_rn(v.z));
    float hw = __bfloat162float(__float2bfloat16_rn(v.w));
    uint2 hv, lv;
    hv.x = pack_bf16(hx, hy); hv.y = pack_bf16(hz, hw);
    lv.x = pack_bf16(v.x - hx, v.y - hy); lv.y = pack_bf16(v.z - hz, v.w - hw);
    *(uint2*)(hi + i) = hv;
    *(uint2*)(lo + i) = lv;
}

// =======================  bf16x3 ldmatrix GEMM  ==============================
// C[M,N](fp32) = (Ah+Al)[M,K] @ (Bh+Bl)[K,N] (+bias), 3-term split products.
// CTA 128x128, BK=32, 256 thr / 8 warps (2x4 of 64x32). Double-buffered cp.async.
// Smem: A rows 80 B (40 b16), B rows 272 B (136 b16) — ldmatrix conflict-free.
#define G_AROW 80
#define G_BROW 272
#define G_OFF_AL 10240
#define G_OFF_BH 20480
#define G_OFF_BL 29184
#define G_STG 37888
#define GEMM_SMEM (2*G_STG)   // 75776 B

__global__ __launch_bounds__(256) void bf16_gemm_kernel(
    const __nv_bfloat16* __restrict__ Ah, const __nv_bfloat16* __restrict__ Al,
    const __nv_bfloat16* __restrict__ Bh, const __nv_bfloat16* __restrict__ Bl,
    const float* __restrict__ bias, float* __restrict__ C,
    int M, int N, int K)
{
    extern __shared__ char dynsm[];
    char* sm = dynsm;
    const int tid = threadIdx.x;
    const int warp = tid >> 5, lane = tid & 31;
    const int group = lane >> 2, tig = lane & 3;
    const int mat = lane >> 3, r = lane & 7;
    const int wm = (warp & 1) * 64;
    const int wn = (warp >> 1) * 32;
    const int m0 = blockIdx.y * 128, n0 = blockIdx.x * 128;

    float acc[4][4][4] = {};

#define BGEMM_ISSUE(s, k0)                                                                    \
    do {                                                                                      \
        _Pragma("unroll")                                                                     \
        for (int u = 0; u < 2; u++) {                                                         \
            int j = tid + u * 256;                                                            \
            int row = j >> 2, c = j & 3;                                                      \
            size_t src = (size_t)(m0 + row) * K + (k0) + c * 8;                               \
            unsigned d = (unsigned)__cvta_generic_to_shared(sm + (s) * G_STG + row * G_AROW + c * 16); \
            asm volatile("cp.async.cg.shared.global [%0], [%1], 16;" :: "r"(d), "l"(Ah + src)); \
            asm volatile("cp.async.cg.shared.global [%0], [%1], 16;" :: "r"(d + G_OFF_AL), "l"(Al + src)); \
        }                                                                                     \
        _Pragma("unroll")                                                                     \
        for (int u = 0; u < 2; u++) {                                                         \
            int j = tid + u * 256;                                                            \
            int kr = j >> 4, c = j & 15;                                                      \
            size_t src = (size_t)((k0) + kr) * N + n0 + c * 8;                                \
            unsigned d = (unsigned)__cvta_generic_to_shared(sm + (s) * G_STG + G_OFF_BH + kr * G_BROW + c * 16); \
            asm volatile("cp.async.cg.shared.global [%0], [%1], 16;" :: "r"(d), "l"(Bh + src)); \
            asm volatile("cp.async.cg.shared.global [%0], [%1], 16;" :: "r"(d + (G_OFF_BL - G_OFF_BH)), "l"(Bl + src)); \
        }                                                                                     \
        asm volatile("cp.async.commit_group;");                                               \
    } while (0)

    const unsigned smbase = (unsigned)__cvta_generic_to_shared(sm);
    const unsigned a_pre = ((mat & 1) * 8 + r) * G_AROW + (mat >> 1) * 16;
    const unsigned b_pre = ((mat & 1) * 8 + r) * G_BROW + (mat >> 1) * 16;

    BGEMM_ISSUE(0, 0);
    const int NT = K / 32;
    for (int kt = 0; kt < NT; kt++) {
        if (kt + 1 < NT) {
            BGEMM_ISSUE((kt + 1) & 1, (kt + 1) * 32);
            asm volatile("cp.async.wait_group 1;");
        } else {
            asm volatile("cp.async.wait_group 0;");
        }
        __syncthreads();

        const unsigned base = smbase + (kt & 1) * G_STG;
#pragma unroll
        for (int kk = 0; kk < 2; kk++) {
            unsigned ah[4][4], al[4][4];
#pragma unroll
            for (int mi = 0; mi < 4; mi++) {
                unsigned aa = base + (wm + mi * 16) * G_AROW + kk * 32 + a_pre;
                ldsm_x4(ah[mi][0], ah[mi][1], ah[mi][2], ah[mi][3], aa);
                ldsm_x4(al[mi][0], al[mi][1], al[mi][2], al[mi][3], aa + G_OFF_AL);
            }
            unsigned bh[4][2], bl[4][2];
#pragma unroll
            for (int j = 0; j < 2; j++) {
                unsigned bb = base + G_OFF_BH + kk * 16 * G_BROW + (wn + j * 16) * 2 + b_pre;
                unsigned t0, t1, t2, t3;
                ldsm_x4_t(t0, t1, t2, t3, bb);
                bh[2 * j][0] = t0; bh[2 * j][1] = t1; bh[2 * j + 1][0] = t2; bh[2 * j + 1][1] = t3;
                ldsm_x4_t(t0, t1, t2, t3, bb + (G_OFF_BL - G_OFF_BH));
                bl[2 * j][0] = t0; bl[2 * j][1] = t1; bl[2 * j + 1][0] = t2; bl[2 * j + 1][1] = t3;
            }
#pragma unroll
            for (int mi = 0; mi < 4; mi++)
#pragma unroll
                for (int ni = 0; ni < 4; ni++) {
                    mma_bf16(acc[mi][ni], al[mi], bh[ni]);
                    mma_bf16(acc[mi][ni], ah[mi], bl[ni]);
                    mma_bf16(acc[mi][ni], ah[mi], bh[ni]);
                }
        }
        __syncthreads();
    }

#pragma unroll
    for (int mi = 0; mi < 4; mi++) {
#pragma unroll
        for (int ni = 0; ni < 4; ni++) {
            int col = n0 + wn + ni * 8 + tig * 2;
            float bx = 0.f, by = 0.f;
            if (bias) { bx = bias[col]; by = bias[col + 1]; }
            int r0 = m0 + wm + mi * 16 + group;
            float2 v0; v0.x = acc[mi][ni][0] + bx; v0.y = acc[mi][ni][1] + by;
            *(float2*)(C + (size_t)r0 * N + col) = v0;
            float2 v1; v1.x = acc[mi][ni][2] + bx; v1.y = acc[mi][ni][3] + by;
            *(float2*)(C + (size_t)(r0 + 8) * N + col) = v1;
        }
    }
}

// ---------------- per-head LayerNorm (+RoPE + 1/8 scale on q) ----------------
__global__ __launch_bounds__(256) void ln_rope_q_kernel(
    float* __restrict__ q, const float* __restrict__ scale, const float* __restrict__ bias)
{
    int gw = blockIdx.x * 8 + (threadIdx.x >> 5);
    int lane = threadIdx.x & 31;
    int row = gw >> 4;
    int h = gw & 15;
    float* p = q + (size_t)row * DIM + h * HD;
    float e0 = p[lane], e1 = p[lane + 32];
    float ssum = e0 + e1;
#pragma unroll
    for (int o = 16; o; o >>= 1) ssum += __shfl_xor_sync(0xffffffffu, ssum, o);
    float mu = ssum * (1.f / 64.f);
    float d0 = e0 - mu, d1 = e1 - mu;
    float vs = d0 * d0 + d1 * d1;
#pragma unroll
    for (int o = 16; o; o >>= 1) vs += __shfl_xor_sync(0xffffffffu, vs, o);
    float rstd = rsqrtf(vs * (1.f / 64.f) + 1e-5f);
    float n0 = d0 * rstd * scale[lane] + bias[lane];
    float n1 = d1 * rstd * scale[lane + 32] + bias[lane + 32];
    int s = row & (SEQ - 1);
    float invf = powf(10000.f, -(float)lane * (1.f / 32.f));
    float ang = (float)s * invf;
    float sn, c;
    sincosf(ang, &sn, &c);
    p[lane]      = (n0 * c - n1 * sn) * 0.125f;
    p[lane + 32] = (n0 * sn + n1 * c) * 0.125f;
}

// ---------------- k LayerNorm + bf16 hi/lo split of k and v ------------------
__global__ __launch_bounds__(256) void ln_k_v_split_kernel(
    const float* __restrict__ kv, const float* __restrict__ scale, const float* __restrict__ bias,
    __nv_bfloat16* __restrict__ kh, __nv_bfloat16* __restrict__ kl,
    __nv_bfloat16* __restrict__ vh, __nv_bfloat16* __restrict__ vl)
{
    int gw = blockIdx.x * 8 + (threadIdx.x >> 5);
    int lane = threadIdx.x & 31;
    int row = gw >> 4;
    int h = gw & 15;
    const float* p = kv + (size_t)row * (2 * DIM) + h * HD;
    float e0 = p[lane], e1 = p[lane + 32];
    float ssum = e0 + e1;
#pragma unroll
    for (int o = 16; o; o >>= 1) ssum += __shfl_xor_sync(0xffffffffu, ssum, o);
    float mu = ssum * (1.f / 64.f);
    float d0 = e0 - mu, d1 = e1 - mu;
    float vs = d0 * d0 + d1 * d1;
#pragma unroll
    for (int o = 16; o; o >>= 1) vs += __shfl_xor_sync(0xffffffffu, vs, o);
    float rstd = rsqrtf(vs * (1.f / 64.f) + 1e-5f);
    float n0 = d0 * rstd * scale[lane] + bias[lane];
    float n1 = d1 * rstd * scale[lane + 32] + bias[lane + 32];

    size_t oidx = (size_t)row * DIM + h * HD;
    __nv_bfloat16 bh;
    bh = __float2bfloat16_rn(n0);
    kh[oidx + lane] = bh; kl[oidx + lane] = __float2bfloat16_rn(n0 - __bfloat162float(bh));
    bh = __float2bfloat16_rn(n1);
    kh[oidx + lane + 32] = bh; kl[oidx + lane + 32] = __float2bfloat16_rn(n1 - __bfloat162float(bh));

    const float* pv = p + DIM;
    float v0 = pv[lane], v1 = pv[lane + 32];
    bh = __float2bfloat16_rn(v0);
    vh[oidx + lane] = bh; vl[oidx + lane] = __float2bfloat16_rn(v0 - __bfloat162float(bh));
    bh = __float2bfloat16_rn(v1);
    vh[oidx + lane + 32] = bh; vl[oidx + lane + 32] = __float2bfloat16_rn(v1 - __bfloat162float(bh));
}

// ---------------- bf16x3 ldmatrix flash attention (validated R7) -------------
#define KROW 144
#define KTILE (64*KROW)
#define OFF_KH 0
#define OFF_KL (2*KTILE)
#define OFF_VH (4*KTILE)
#define OFF_VL (6*KTILE)
#define OFF_PH (8*KTILE)
#define OFF_PL (OFF_PH + 128*KROW)
#define ATTN_SMEM (OFF_PL + 128*KROW)   // 110592 B

__global__ __launch_bounds__(256) void attn_tc_kernel(
    const float* __restrict__ q,
    const __nv_bfloat16* __restrict__ kh, const __nv_bfloat16* __restrict__ kl,
    const __nv_bfloat16* __restrict__ vh, const __nv_bfloat16* __restrict__ vl,
    __nv_bfloat16* __restrict__ oh, __nv_bfloat16* __restrict__ ol)
{
    extern __shared__ char dynsm[];
    char* sm = dynsm;
    const int tid = threadIdx.x;
    const int warp = tid >> 5, lane = tid & 31;
    const int g = lane >> 2, t = lane & 3;
    const int mat = lane >> 3, r = lane & 7;
    const int h = blockIdx.y, b = blockIdx.z;
    const int rowbase = b * SEQ + blockIdx.x * 128;
    const int ctxbase = b * SEQ;

    // ---- stage Q (fp32) into P area ----
#pragma unroll
    for (int u = 0; u < 8; u++) {
        int i = tid + u * 256;
        int row = i >> 4, c4 = (i & 15) * 4;
        unsigned d = (unsigned)__cvta_generic_to_shared(sm + OFF_PH + row * 256 + c4 * 4);
        asm volatile("cp.async.cg.shared.global [%0], [%1], 16;"
                     :: "r"(d), "l"(q + (size_t)(rowbase + row) * DIM + h * HD + c4));
    }
    asm volatile("cp.async.commit_group;");

#define KV_LOAD(buf, tile)                                                                     \
    do {                                                                                       \
        _Pragma("unroll")                                                                      \
        for (int u = 0; u < 2; u++) {                                                          \
            int i = tid + u * 256;                                                             \
            int key = i >> 3, c = i & 7;                                                       \
            size_t src = ((size_t)(ctxbase + (tile) * 64 + key) << 10) + h * HD + c * 8;       \
            unsigned dst = (unsigned)__cvta_generic_to_shared(sm + (buf) * KTILE + key * KROW + c * 16); \
            asm volatile("cp.async.cg.shared.global [%0], [%1], 16;" :: "r"(dst + OFF_KH), "l"(kh + src)); \
            asm volatile("cp.async.cg.shared.global [%0], [%1], 16;" :: "r"(dst + OFF_KL), "l"(kl + src)); \
            asm volatile("cp.async.cg.shared.global [%0], [%1], 16;" :: "r"(dst + OFF_VH), "l"(vh + src)); \
            asm volatile("cp.async.cg.shared.global [%0], [%1], 16;" :: "r"(dst + OFF_VL), "l"(vl + src)); \
        }                                                                                      \
        asm volatile("cp.async.commit_group;");                                                \
    } while (0)

    KV_LOAD(0, 0);
    asm volatile("cp.async.wait_group 1;");
    __syncthreads();

    // ---- Q fragments (bf16 hi/lo), warp-private rows ----
    unsigned qh[4][4], ql[4][4];
    {
        const float* Qs = (const float*)(sm + OFF_PH);
        int row = warp * 16 + g;
#pragma unroll
        for (int kc = 0; kc < 4; kc++) {
            int d0 = kc * 16 + 2 * t;
#pragma unroll
            for (int a = 0; a < 4; a++) {
                int rr = row + (a & 1) * 8;
                int dd = d0 + (a >> 1) * 8;
                float x = Qs[rr * 64 + dd], y = Qs[rr * 64 + dd + 1];
                float xh = __bfloat162float(__float2bfloat16_rn(x));
                float yh = __bfloat162float(__float2bfloat16_rn(y));
                qh[kc][a] = pack_bf16(xh, yh);
                ql[kc][a] = pack_bf16(x - xh, y - yh);
            }
        }
    }

    float o[8][4] = {};
    float m0 = -1e30f, m1 = -1e30f, l0 = 0.f, l1 = 0.f;

    const unsigned smbase = (unsigned)__cvta_generic_to_shared(sm);
    const unsigned kpre = (mat >> 1) * 8 * KROW + r * KROW + (mat & 1) * 16;
    const unsigned ppre = (warp * 16 + (mat & 1) * 8 + r) * KROW + (mat >> 1) * 16;
    const unsigned vpre = (mat & 1) * 8 * KROW + r * KROW + (mat >> 1) * 16;

    const int NT = SEQ / 64;
    for (int kt = 0; kt < NT; kt++) {
        __syncthreads();
        if (kt + 1 < NT) {
            KV_LOAD((kt + 1) & 1, kt + 1);
            asm volatile("cp.async.wait_group 1;");
        } else {
            asm volatile("cp.async.wait_group 0;");
        }
        __syncthreads();

        const unsigned buf = (kt & 1) * KTILE;

        // ---- S = Q @ K^T ----
        float s[8][4] = {};
#pragma unroll
        for (int kc = 0; kc < 4; kc++) {
#pragma unroll
            for (int ntp = 0; ntp < 4; ntp++) {
                unsigned aK = smbase + buf + ntp * (16 * KROW) + kc * 32 + kpre;
                unsigned h0, h1, h2, h3, lo0, lo1, lo2, lo3;
                ldsm_x4(h0, h1, h2, h3, aK + OFF_KH);
                ldsm_x4(lo0, lo1, lo2, lo3, aK + OFF_KL);
                unsigned bh0[2] = {h0, h1}, bh1[2] = {h2, h3};
                unsigned bl0[2] = {lo0, lo1}, bl1[2] = {lo2, lo3};
                mma_bf16(s[2 * ntp],     ql[kc], bh0);
                mma_bf16(s[2 * ntp],     qh[kc], bl0);
                mma_bf16(s[2 * ntp],     qh[kc], bh0);
                mma_bf16(s[2 * ntp + 1], ql[kc], bh1);
                mma_bf16(s[2 * ntp + 1], qh[kc], bl1);
                mma_bf16(s[2 * ntp + 1], qh[kc], bh1);
            }
        }

        // ---- online softmax ----
        float mx0 = s[0][0], mx1 = s[0][2];
#pragma unroll
        for (int nt = 0; nt < 8; nt++) {
            mx0 = fmaxf(mx0, fmaxf(s[nt][0], s[nt][1]));
            mx1 = fmaxf(mx1, fmaxf(s[nt][2], s[nt][3]));
        }
        mx0 = fmaxf(mx0, __shfl_xor_sync(0xffffffffu, mx0, 1));
        mx0 = fmaxf(mx0, __shfl_xor_sync(0xffffffffu, mx0, 2));
        mx1 = fmaxf(mx1, __shfl_xor_sync(0xffffffffu, mx1, 1));
        mx1 = fmaxf(mx1, __shfl_xor_sync(0xffffffffu, mx1, 2));
        float mn0 = fmaxf(m0, mx0), mn1 = fmaxf(m1, mx1);
        float a0 = __expf(m0 - mn0), a1 = __expf(m1 - mn1);
        float sum0 = 0.f, sum1 = 0.f;
#pragma unroll
        for (int nt = 0; nt < 8; nt++) {
            s[nt][0] = __expf(s[nt][0] - mn0); s[nt][1] = __expf(s[nt][1] - mn0);
            s[nt][2] = __expf(s[nt][2] - mn1); s[nt][3] = __expf(s[nt][3] - mn1);
            sum0 += s[nt][0] + s[nt][1];
            sum1 += s[nt][2] + s[nt][3];
        }
        sum0 += __shfl_xor_sync(0xffffffffu, sum0, 1);
        sum0 += __shfl_xor_sync(0xffffffffu, sum0, 2);
        sum1 += __shfl_xor_sync(0xffffffffu, sum1, 1);
        sum1 += __shfl_xor_sync(0xffffffffu, sum1, 2);
        l0 = l0 * a0 + sum0; l1 = l1 * a1 + sum1;
        m0 = mn0; m1 = mn1;
#pragma unroll
        for (int nt = 0; nt < 8; nt++) {
            o[nt][0] *= a0; o[nt][1] *= a0;
            o[nt][2] *= a1; o[nt][3] *= a1;
        }

        // ---- stage P (bf16 hi/lo), warp-private row band ----
#pragma unroll
        for (int nt = 0; nt < 8; nt++) {
            int byte0 = (warp * 16 + g) * KROW + (nt * 8 + 2 * t) * 2;
            float p0 = s[nt][0], p1 = s[nt][1];
            float p0h = __bfloat162float(__float2bfloat16_rn(p0));
            float p1h = __bfloat162float(__float2bfloat16_rn(p1));
            *(unsigned*)(sm + OFF_PH + byte0) = pack_bf16(p0h, p1h);
            *(unsigned*)(sm + OFF_PL + byte0) = pack_bf16(p0 - p0h, p1 - p1h);
            int byte1 = byte0 + 8 * KROW;
            float p2 = s[nt][2], p3 = s[nt][3];
            float p2h = __bfloat162float(__float2bfloat16_rn(p2));
            float p3h = __bfloat162float(__float2bfloat16_rn(p3));
            *(unsigned*)(sm + OFF_PH + byte1) = pack_bf16(p2h, p3h);
            *(unsigned*)(sm + OFF_PL + byte1) = pack_bf16(p2 - p2h, p3 - p3h);
        }
        __syncwarp();

        // ---- O += P @ V ----
#pragma unroll
        for (int kc = 0; kc < 4; kc++) {
            unsigned aP = smbase + kc * 32 + ppre;
            unsigned pah[4], pal[4];
            ldsm_x4(pah[0], pah[1], pah[2], pah[3], aP + OFF_PH);
            ldsm_x4(pal[0], pal[1], pal[2], pal[3], aP + OFF_PL);
#pragma unroll
            for (int ntp = 0; ntp < 4; ntp++) {
                unsigned aV = smbase + buf + kc * (16 * KROW) + ntp * 32 + vpre;
                unsigned h0, h1, h2, h3, lo0, lo1, lo2, lo3;
                ldsm_x4_t(h0, h1, h2, h3, aV + OFF_VH);
                ldsm_x4_t(lo0, lo1, lo2, lo3, aV + OFF_VL);
                unsigned bh0[2] = {h0, h1}, bh1[2] = {h2, h3};
                unsigned bl0[2] = {lo0, lo1}, bl1[2] = {lo2, lo3};
                mma_bf16(o[2 * ntp],     pal, bh0);
                mma_bf16(o[2 * ntp],     pah, bl0);
                mma_bf16(o[2 * ntp],     pah, bh0);
                mma_bf16(o[2 * ntp + 1], pal, bh1);
                mma_bf16(o[2 * ntp + 1], pah, bl1);
                mma_bf16(o[2 * ntp + 1], pah, bh1);
            }
        }
    }

    // ---- normalize + write as bf16 hi/lo (feeds out-proj GEMM) ----
    float i0 = 1.f / l0, i1 = 1.f / l1;
    int r0 = rowbase + warp * 16 + g;
#pragma unroll
    for (int nt = 0; nt < 8; nt++) {
        int col = h * HD + nt * 8 + 2 * t;
        size_t idx0 = (size_t)r0 * DIM + col;
        size_t idx1 = (size_t)(r0 + 8) * DIM + col;
        float x = o[nt][0] * i0, y = o[nt][1] * i0;
        float xh = __bfloat162float(__float2bfloat16_rn(x));
        float yh = __bfloat162float(__float2bfloat16_rn(y));
        *(unsigned*)(oh + idx0) = pack_bf16(xh, yh);
        *(unsigned*)(ol + idx0) = pack_bf16(x - xh, y - yh);
        x = o[nt][2] * i1; y = o[nt][3] * i1;
        xh = __bfloat162float(__float2bfloat16_rn(x));
        yh = __bfloat162float(__float2bfloat16_rn(y));
        *(unsigned*)(oh + idx1) = pack_bf16(xh, yh);
        *(unsigned*)(ol + idx1) = pack_bf16(x - xh, y - yh);
    }
}

// ---------------- launch ------------------------------------------------------
extern "C" void kernel_launch(void* const* d_in, const int* in_sizes, int n_in,
                              void* d_out, int out_size)
{
    const float* x        = (const float*)d_in[0];
    const float* context  = (const float*)d_in[1];
    const float* q_w      = (const float*)d_in[2];
    const float* kv_w     = (const float*)d_in[3];
    const float* qn_scale = (const float*)d_in[4];
    const float* qn_bias  = (const float*)d_in[5];
    const float* kn_scale = (const float*)d_in[6];
    const float* kn_bias  = (const float*)d_in[7];
    const float* proj_w   = (const float*)d_in[8];
    const float* proj_b   = (const float*)d_in[9];
    float* out = (float*)d_out;

    float *pq, *pkv;
    __nv_bfloat16 *pkh, *pkl, *pvh, *pvl, *pah, *pal;
    __nv_bfloat16 *pxh, *pxl, *pch, *pcl, *pqwh, *pqwl, *pkvwh, *pkvwl, *ppwh, *ppwl;
    cudaGetSymbolAddress((void**)&pq,  g_q);
    cudaGetSymbolAddress((void**)&pkv, g_kv);
    cudaGetSymbolAddress((void**)&pkh, g_kh);
    cudaGetSymbolAddress((void**)&pkl, g_kl);
    cudaGetSymbolAddress((void**)&pvh, g_vh);
    cudaGetSymbolAddress((void**)&pvl, g_vl);
    cudaGetSymbolAddress((void**)&pah, g_ah);
    cudaGetSymbolAddress((void**)&pal, g_al);
    cudaGetSymbolAddress((void**)&pxh, g_xh);
    cudaGetSymbolAddress((void**)&pxl, g_xl);
    cudaGetSymbolAddress((void**)&pch, g_ch);
    cudaGetSymbolAddress((void**)&pcl, g_cl);
    cudaGetSymbolAddress((void**)&pqwh, g_qwh);
    cudaGetSymbolAddress((void**)&pqwl, g_qwl);
    cudaGetSymbolAddress((void**)&pkvwh, g_kvwh);
    cudaGetSymbolAddress((void**)&pkvwl, g_kvwl);
    cudaGetSymbolAddress((void**)&ppwh, g_pwh);
    cudaGetSymbolAddress((void**)&ppwl, g_pwl);

    cudaFuncSetAttribute(bf16_gemm_kernel, cudaFuncAttributeMaxDynamicSharedMemorySize, (int)GEMM_SMEM);
    cudaFuncSetAttribute(attn_tc_kernel, cudaFuncAttributeMaxDynamicSharedMemorySize, (int)ATTN_SMEM);

    // 0. split inputs/weights to bf16 hi/lo
    split_bf16_kernel<<<MROWS * DIM / 1024, 256>>>(x, pxh, pxl);
    split_bf16_kernel<<<MROWS * DIM / 1024, 256>>>(context, pch, pcl);
    split_bf16_kernel<<<DIM * DIM / 1024, 256>>>(q_w, pqwh, pqwl);
    split_bf16_kernel<<<DIM * 2 * DIM / 1024, 256>>>(kv_w, pkvwh, pkvwl);
    split_bf16_kernel<<<DIM * DIM / 1024, 256>>>(proj_w, ppwh, ppwl);

    // 1. q = x @ q_w
    bf16_gemm_kernel<<<dim3(DIM / 128, MROWS / 128), 256, GEMM_SMEM>>>(
        pxh, pxl, pqwh, pqwl, nullptr, pq, MROWS, DIM, DIM);
    // 2. kv = context @ kv_w
    bf16_gemm_kernel<<<dim3(2 * DIM / 128, MROWS / 128), 256, GEMM_SMEM>>>(
        pch, pcl, pkvwh, pkvwl, nullptr, pkv, MROWS, 2 * DIM, DIM);
    // 3. per-head LN (+RoPE+scale on q); k LN + bf16 split, v bf16 split
    ln_rope_q_kernel<<<MROWS * NH / 8, 256>>>(pq, qn_scale, qn_bias);
    ln_k_v_split_kernel<<<MROWS * NH / 8, 256>>>(pkv, kn_scale, kn_bias, pkh, pkl, pvh, pvl);
    // 4. attention (bf16x3 + ldmatrix), writes bf16 hi/lo
    attn_tc_kernel<<<dim3(SEQ / 128, NH, BATCH), 256, ATTN_SMEM>>>(pq, pkh, pkl, pvh, pvl, pah, pal);
    // 5. out = att @ proj_w + proj_b
    bf16_gemm_kernel<<<dim3(DIM / 128, MROWS / 128), 256, GEMM_SMEM>>>(
        pah, pal, ppwh, ppwl, proj_b, out, MROWS, DIM, DIM);
}

// round 10
// speedup vs baseline: 2.7424x; 1.0020x over previous
#include <cuda_runtime.h>
#include <cuda_bf16.h>
#include <math.h>

#define DIM 1024
#define NH 16
#define HD 64
#define BATCH 4
#define SEQ 2048
#define MROWS (BATCH*SEQ)   // 8192

// ---------------- scratch (static device memory; no allocations) -------------
__device__ float g_q  [(size_t)MROWS * DIM];            // q proj (fp32, LN+RoPE in place)
__device__ float g_kv [(size_t)MROWS * 2 * DIM];        // raw kv projection fp32
__device__ __nv_bfloat16 g_kh[(size_t)MROWS * DIM];     // k hi
__device__ __nv_bfloat16 g_kl[(size_t)MROWS * DIM];     // k lo
__device__ __nv_bfloat16 g_vh[(size_t)MROWS * DIM];     // v hi
__device__ __nv_bfloat16 g_vl[(size_t)MROWS * DIM];     // v lo
__device__ __nv_bfloat16 g_ah[(size_t)MROWS * DIM];     // attention out hi
__device__ __nv_bfloat16 g_al[(size_t)MROWS * DIM];     // attention out lo
__device__ __nv_bfloat16 g_xh[(size_t)MROWS * DIM];     // x hi/lo
__device__ __nv_bfloat16 g_xl[(size_t)MROWS * DIM];
__device__ __nv_bfloat16 g_ch[(size_t)MROWS * DIM];     // context hi/lo
__device__ __nv_bfloat16 g_cl[(size_t)MROWS * DIM];
__device__ __nv_bfloat16 g_qwh[(size_t)DIM * DIM];      // weights hi/lo
__device__ __nv_bfloat16 g_qwl[(size_t)DIM * DIM];
__device__ __nv_bfloat16 g_kvwh[(size_t)DIM * 2 * DIM];
__device__ __nv_bfloat16 g_kvwl[(size_t)DIM * 2 * DIM];
__device__ __nv_bfloat16 g_pwh[(size_t)DIM * DIM];
__device__ __nv_bfloat16 g_pwl[(size_t)DIM * DIM];

// ---------------- helpers -----------------------------------------------------
__device__ __forceinline__ void mma_bf16(float c[4], const unsigned a[4], const unsigned b[2]) {
    asm volatile(
        "mma.sync.aligned.m16n8k16.row.col.f32.bf16.bf16.f32 "
        "{%0,%1,%2,%3}, {%4,%5,%6,%7}, {%8,%9}, {%0,%1,%2,%3};\n"
        : "+f"(c[0]), "+f"(c[1]), "+f"(c[2]), "+f"(c[3])
        : "r"(a[0]), "r"(a[1]), "r"(a[2]), "r"(a[3]), "r"(b[0]), "r"(b[1]));
}
__device__ __forceinline__ unsigned pack_bf16(float x, float y) {
    __nv_bfloat162 v = __floats2bfloat162_rn(x, y);
    return *(unsigned*)&v;
}
__device__ __forceinline__ void ldsm_x4(unsigned& r0, unsigned& r1, unsigned& r2, unsigned& r3, unsigned addr) {
    asm volatile("ldmatrix.sync.aligned.m8n8.x4.shared.b16 {%0,%1,%2,%3}, [%4];"
                 : "=r"(r0), "=r"(r1), "=r"(r2), "=r"(r3) : "r"(addr));
}
__device__ __forceinline__ void ldsm_x4_t(unsigned& r0, unsigned& r1, unsigned& r2, unsigned& r3, unsigned addr) {
    asm volatile("ldmatrix.sync.aligned.m8n8.x4.trans.shared.b16 {%0,%1,%2,%3}, [%4];"
                 : "=r"(r0), "=r"(r1), "=r"(r2), "=r"(r3) : "r"(addr));
}

// ---------------- elementwise fp32 -> bf16 hi/lo split ------------------------
__global__ __launch_bounds__(256) void split_bf16_kernel(
    const float* __restrict__ in, __nv_bfloat16* __restrict__ hi, __nv_bfloat16* __restrict__ lo)
{
    size_t i = ((size_t)blockIdx.x * 256 + threadIdx.x) * 4;
    float4 v = *(const float4*)(in + i);
    float hx = __bfloat162float(__float2bfloat16_rn(v.x));
    float hy = __bfloat162float(__float2bfloat16_rn(v.y));
    float hz = __bfloat162float(__float2bfloat16_rn(v.z));
    float hw = __bfloat162float(__float2bfloat16_rn(v.w));
    uint2 hv, lv;
    hv.x = pack_bf16(hx, hy); hv.y = pack_bf16(hz, hw);
    lv.x = pack_bf16(v.x - hx, v.y - hy); lv.y = pack_bf16(v.z - hz, v.w - hw);
    *(uint2*)(hi + i) = hv;
    *(uint2*)(lo + i) = lv;
}

// =======================  bf16x3 ldmatrix GEMM (validated R8)  ===============
#define G_AROW 80
#define G_BROW 272
#define G_OFF_AL 10240
#define G_OFF_BH 20480
#define G_OFF_BL 29184
#define G_STG 37888
#define GEMM_SMEM (2*G_STG)   // 75776 B

__global__ __launch_bounds__(256) void bf16_gemm_kernel(
    const __nv_bfloat16* __restrict__ Ah, const __nv_bfloat16* __restrict__ Al,
    const __nv_bfloat16* __restrict__ Bh, const __nv_bfloat16* __restrict__ Bl,
    const float* __restrict__ bias, float* __restrict__ C,
    int M, int N, int K)
{
    extern __shared__ char dynsm[];
    char* sm = dynsm;
    const int tid = threadIdx.x;
    const int warp = tid >> 5, lane = tid & 31;
    const int group = lane >> 2, tig = lane & 3;
    const int mat = lane >> 3, r = lane & 7;
    const int wm = (warp & 1) * 64;
    const int wn = (warp >> 1) * 32;
    const int m0 = blockIdx.y * 128, n0 = blockIdx.x * 128;

    float acc[4][4][4] = {};

#define BGEMM_ISSUE(s, k0)                                                                    \
    do {                                                                                      \
        _Pragma("unroll")                                                                     \
        for (int u = 0; u < 2; u++) {                                                         \
            int j = tid + u * 256;                                                            \
            int row = j >> 2, c = j & 3;                                                      \
            size_t src = (size_t)(m0 + row) * K + (k0) + c * 8;                               \
            unsigned d = (unsigned)__cvta_generic_to_shared(sm + (s) * G_STG + row * G_AROW + c * 16); \
            asm volatile("cp.async.cg.shared.global [%0], [%1], 16;" :: "r"(d), "l"(Ah + src)); \
            asm volatile("cp.async.cg.shared.global [%0], [%1], 16;" :: "r"(d + G_OFF_AL), "l"(Al + src)); \
        }                                                                                     \
        _Pragma("unroll")                                                                     \
        for (int u = 0; u < 2; u++) {                                                         \
            int j = tid + u * 256;                                                            \
            int kr = j >> 4, c = j & 15;                                                      \
            size_t src = (size_t)((k0) + kr) * N + n0 + c * 8;                                \
            unsigned d = (unsigned)__cvta_generic_to_shared(sm + (s) * G_STG + G_OFF_BH + kr * G_BROW + c * 16); \
            asm volatile("cp.async.cg.shared.global [%0], [%1], 16;" :: "r"(d), "l"(Bh + src)); \
            asm volatile("cp.async.cg.shared.global [%0], [%1], 16;" :: "r"(d + (G_OFF_BL - G_OFF_BH)), "l"(Bl + src)); \
        }                                                                                     \
        asm volatile("cp.async.commit_group;");                                               \
    } while (0)

    const unsigned smbase = (unsigned)__cvta_generic_to_shared(sm);
    const unsigned a_pre = ((mat & 1) * 8 + r) * G_AROW + (mat >> 1) * 16;
    const unsigned b_pre = ((mat & 1) * 8 + r) * G_BROW + (mat >> 1) * 16;

    BGEMM_ISSUE(0, 0);
    const int NT = K / 32;
    for (int kt = 0; kt < NT; kt++) {
        if (kt + 1 < NT) {
            BGEMM_ISSUE((kt + 1) & 1, (kt + 1) * 32);
            asm volatile("cp.async.wait_group 1;");
        } else {
            asm volatile("cp.async.wait_group 0;");
        }
        __syncthreads();

        const unsigned base = smbase + (kt & 1) * G_STG;
#pragma unroll
        for (int kk = 0; kk < 2; kk++) {
            unsigned ah[4][4], al[4][4];
#pragma unroll
            for (int mi = 0; mi < 4; mi++) {
                unsigned aa = base + (wm + mi * 16) * G_AROW + kk * 32 + a_pre;
                ldsm_x4(ah[mi][0], ah[mi][1], ah[mi][2], ah[mi][3], aa);
                ldsm_x4(al[mi][0], al[mi][1], al[mi][2], al[mi][3], aa + G_OFF_AL);
            }
            unsigned bh[4][2], bl[4][2];
#pragma unroll
            for (int j = 0; j < 2; j++) {
                unsigned bb = base + G_OFF_BH + kk * 16 * G_BROW + (wn + j * 16) * 2 + b_pre;
                unsigned t0, t1, t2, t3;
                ldsm_x4_t(t0, t1, t2, t3, bb);
                bh[2 * j][0] = t0; bh[2 * j][1] = t1; bh[2 * j + 1][0] = t2; bh[2 * j + 1][1] = t3;
                ldsm_x4_t(t0, t1, t2, t3, bb + (G_OFF_BL - G_OFF_BH));
                bl[2 * j][0] = t0; bl[2 * j][1] = t1; bl[2 * j + 1][0] = t2; bl[2 * j + 1][1] = t3;
            }
#pragma unroll
            for (int mi = 0; mi < 4; mi++)
#pragma unroll
                for (int ni = 0; ni < 4; ni++) {
                    mma_bf16(acc[mi][ni], al[mi], bh[ni]);
                    mma_bf16(acc[mi][ni], ah[mi], bl[ni]);
                    mma_bf16(acc[mi][ni], ah[mi], bh[ni]);
                }
        }
        __syncthreads();
    }

#pragma unroll
    for (int mi = 0; mi < 4; mi++) {
#pragma unroll
        for (int ni = 0; ni < 4; ni++) {
            int col = n0 + wn + ni * 8 + tig * 2;
            float bx = 0.f, by = 0.f;
            if (bias) { bx = bias[col]; by = bias[col + 1]; }
            int r0 = m0 + wm + mi * 16 + group;
            float2 v0; v0.x = acc[mi][ni][0] + bx; v0.y = acc[mi][ni][1] + by;
            *(float2*)(C + (size_t)r0 * N + col) = v0;
            float2 v1; v1.x = acc[mi][ni][2] + bx; v1.y = acc[mi][ni][3] + by;
            *(float2*)(C + (size_t)(r0 + 8) * N + col) = v1;
        }
    }
}

// ---------------- per-head LayerNorm (+RoPE + 1/8 scale on q) ----------------
__global__ __launch_bounds__(256) void ln_rope_q_kernel(
    float* __restrict__ q, const float* __restrict__ scale, const float* __restrict__ bias)
{
    int gw = blockIdx.x * 8 + (threadIdx.x >> 5);
    int lane = threadIdx.x & 31;
    int row = gw >> 4;
    int h = gw & 15;
    float* p = q + (size_t)row * DIM + h * HD;
    float e0 = p[lane], e1 = p[lane + 32];
    float ssum = e0 + e1;
#pragma unroll
    for (int o = 16; o; o >>= 1) ssum += __shfl_xor_sync(0xffffffffu, ssum, o);
    float mu = ssum * (1.f / 64.f);
    float d0 = e0 - mu, d1 = e1 - mu;
    float vs = d0 * d0 + d1 * d1;
#pragma unroll
    for (int o = 16; o; o >>= 1) vs += __shfl_xor_sync(0xffffffffu, vs, o);
    float rstd = rsqrtf(vs * (1.f / 64.f) + 1e-5f);
    float n0 = d0 * rstd * scale[lane] + bias[lane];
    float n1 = d1 * rstd * scale[lane + 32] + bias[lane + 32];
    int s = row & (SEQ - 1);
    float invf = powf(10000.f, -(float)lane * (1.f / 32.f));
    float ang = (float)s * invf;
    float sn, c;
    sincosf(ang, &sn, &c);
    p[lane]      = (n0 * c - n1 * sn) * 0.125f;
    p[lane + 32] = (n0 * sn + n1 * c) * 0.125f;
}

// ---------------- k LayerNorm + bf16 hi/lo split of k and v ------------------
__global__ __launch_bounds__(256) void ln_k_v_split_kernel(
    const float* __restrict__ kv, const float* __restrict__ scale, const float* __restrict__ bias,
    __nv_bfloat16* __restrict__ kh, __nv_bfloat16* __restrict__ kl,
    __nv_bfloat16* __restrict__ vh, __nv_bfloat16* __restrict__ vl)
{
    int gw = blockIdx.x * 8 + (threadIdx.x >> 5);
    int lane = threadIdx.x & 31;
    int row = gw >> 4;
    int h = gw & 15;
    const float* p = kv + (size_t)row * (2 * DIM) + h * HD;
    float e0 = p[lane], e1 = p[lane + 32];
    float ssum = e0 + e1;
#pragma unroll
    for (int o = 16; o; o >>= 1) ssum += __shfl_xor_sync(0xffffffffu, ssum, o);
    float mu = ssum * (1.f / 64.f);
    float d0 = e0 - mu, d1 = e1 - mu;
    float vs = d0 * d0 + d1 * d1;
#pragma unroll
    for (int o = 16; o; o >>= 1) vs += __shfl_xor_sync(0xffffffffu, vs, o);
    float rstd = rsqrtf(vs * (1.f / 64.f) + 1e-5f);
    float n0 = d0 * rstd * scale[lane] + bias[lane];
    float n1 = d1 * rstd * scale[lane + 32] + bias[lane + 32];

    size_t oidx = (size_t)row * DIM + h * HD;
    __nv_bfloat16 bh;
    bh = __float2bfloat16_rn(n0);
    kh[oidx + lane] = bh; kl[oidx + lane] = __float2bfloat16_rn(n0 - __bfloat162float(bh));
    bh = __float2bfloat16_rn(n1);
    kh[oidx + lane + 32] = bh; kl[oidx + lane + 32] = __float2bfloat16_rn(n1 - __bfloat162float(bh));

    const float* pv = p + DIM;
    float v0 = pv[lane], v1 = pv[lane + 32];
    bh = __float2bfloat16_rn(v0);
    vh[oidx + lane] = bh; vl[oidx + lane] = __float2bfloat16_rn(v0 - __bfloat162float(bh));
    bh = __float2bfloat16_rn(v1);
    vh[oidx + lane + 32] = bh; vl[oidx + lane + 32] = __float2bfloat16_rn(v1 - __bfloat162float(bh));
}

// ---------------- bf16x3 ldmatrix flash attention (occupancy 2) --------------
#define KROW 144
#define KTILE (64*KROW)
#define OFF_KH 0
#define OFF_KL (2*KTILE)
#define OFF_VH (4*KTILE)
#define OFF_VL (6*KTILE)
#define OFF_PH (8*KTILE)
#define OFF_PL (OFF_PH + 128*KROW)
#define ATTN_SMEM (OFF_PL + 128*KROW)   // 110592 B -> 2 CTAs/SM

__global__ __launch_bounds__(256, 2) void attn_tc_kernel(
    const float* __restrict__ q,
    const __nv_bfloat16* __restrict__ kh, const __nv_bfloat16* __restrict__ kl,
    const __nv_bfloat16* __restrict__ vh, const __nv_bfloat16* __restrict__ vl,
    __nv_bfloat16* __restrict__ oh, __nv_bfloat16* __restrict__ ol)
{
    extern __shared__ char dynsm[];
    char* sm = dynsm;
    const int tid = threadIdx.x;
    const int warp = tid >> 5, lane = tid & 31;
    const int g = lane >> 2, t = lane & 3;
    const int mat = lane >> 3, r = lane & 7;
    const int h = blockIdx.y, b = blockIdx.z;
    const int rowbase = b * SEQ + blockIdx.x * 128;
    const int ctxbase = b * SEQ;

    // ---- stage Q (fp32) into P area ----
#pragma unroll
    for (int u = 0; u < 8; u++) {
        int i = tid + u * 256;
        int row = i >> 4, c4 = (i & 15) * 4;
        unsigned d = (unsigned)__cvta_generic_to_shared(sm + OFF_PH + row * 256 + c4 * 4);
        asm volatile("cp.async.cg.shared.global [%0], [%1], 16;"
                     :: "r"(d), "l"(q + (size_t)(rowbase + row) * DIM + h * HD + c4));
    }
    asm volatile("cp.async.commit_group;");

#define KV_LOAD(buf, tile)                                                                     \
    do {                                                                                       \
        _Pragma("unroll")                                                                      \
        for (int u = 0; u < 2; u++) {                                                          \
            int i = tid + u * 256;                                                             \
            int key = i >> 3, c = i & 7;                                                       \
            size_t src = ((size_t)(ctxbase + (tile) * 64 + key) << 10) + h * HD + c * 8;       \
            unsigned dst = (unsigned)__cvta_generic_to_shared(sm + (buf) * KTILE + key * KROW + c * 16); \
            asm volatile("cp.async.cg.shared.global [%0], [%1], 16;" :: "r"(dst + OFF_KH), "l"(kh + src)); \
            asm volatile("cp.async.cg.shared.global [%0], [%1], 16;" :: "r"(dst + OFF_KL), "l"(kl + src)); \
            asm volatile("cp.async.cg.shared.global [%0], [%1], 16;" :: "r"(dst + OFF_VH), "l"(vh + src)); \
            asm volatile("cp.async.cg.shared.global [%0], [%1], 16;" :: "r"(dst + OFF_VL), "l"(vl + src)); \
        }                                                                                      \
        asm volatile("cp.async.commit_group;");                                                \
    } while (0)

    KV_LOAD(0, 0);
    asm volatile("cp.async.wait_group 1;");
    __syncthreads();

    // ---- Q fragments (bf16 hi/lo), warp-private rows ----
    unsigned qh[4][4], ql[4][4];
    {
        const float* Qs = (const float*)(sm + OFF_PH);
        int row = warp * 16 + g;
#pragma unroll
        for (int kc = 0; kc < 4; kc++) {
            int d0 = kc * 16 + 2 * t;
#pragma unroll
            for (int a = 0; a < 4; a++) {
                int rr = row + (a & 1) * 8;
                int dd = d0 + (a >> 1) * 8;
                float x = Qs[rr * 64 + dd], y = Qs[rr * 64 + dd + 1];
                float xh = __bfloat162float(__float2bfloat16_rn(x));
                float yh = __bfloat162float(__float2bfloat16_rn(y));
                qh[kc][a] = pack_bf16(xh, yh);
                ql[kc][a] = pack_bf16(x - xh, y - yh);
            }
        }
    }

    float o[8][4] = {};
    float m0 = -1e30f, m1 = -1e30f, l0 = 0.f, l1 = 0.f;

    const unsigned smbase = (unsigned)__cvta_generic_to_shared(sm);
    const unsigned kpre = (mat >> 1) * 8 * KROW + r * KROW + (mat & 1) * 16;
    const unsigned ppre = (warp * 16 + (mat & 1) * 8 + r) * KROW + (mat >> 1) * 16;
    const unsigned vpre = (mat & 1) * 8 * KROW + r * KROW + (mat >> 1) * 16;

    const int NT = SEQ / 64;
    for (int kt = 0; kt < NT; kt++) {
        __syncthreads();
        if (kt + 1 < NT) {
            KV_LOAD((kt + 1) & 1, kt + 1);
            asm volatile("cp.async.wait_group 1;");
        } else {
            asm volatile("cp.async.wait_group 0;");
        }
        __syncthreads();

        const unsigned buf = (kt & 1) * KTILE;

        // ---- S = Q @ K^T ----
        float s[8][4] = {};
#pragma unroll
        for (int kc = 0; kc < 4; kc++) {
#pragma unroll
            for (int ntp = 0; ntp < 4; ntp++) {
                unsigned aK = smbase + buf + ntp * (16 * KROW) + kc * 32 + kpre;
                unsigned h0, h1, h2, h3, lo0, lo1, lo2, lo3;
                ldsm_x4(h0, h1, h2, h3, aK + OFF_KH);
                ldsm_x4(lo0, lo1, lo2, lo3, aK + OFF_KL);
                unsigned bh0[2] = {h0, h1}, bh1[2] = {h2, h3};
                unsigned bl0[2] = {lo0, lo1}, bl1[2] = {lo2, lo3};
                mma_bf16(s[2 * ntp],     ql[kc], bh0);
                mma_bf16(s[2 * ntp],     qh[kc], bl0);
                mma_bf16(s[2 * ntp],     qh[kc], bh0);
                mma_bf16(s[2 * ntp + 1], ql[kc], bh1);
                mma_bf16(s[2 * ntp + 1], qh[kc], bl1);
                mma_bf16(s[2 * ntp + 1], qh[kc], bh1);
            }
        }

        // ---- online softmax ----
        float mx0 = s[0][0], mx1 = s[0][2];
#pragma unroll
        for (int nt = 0; nt < 8; nt++) {
            mx0 = fmaxf(mx0, fmaxf(s[nt][0], s[nt][1]));
            mx1 = fmaxf(mx1, fmaxf(s[nt][2], s[nt][3]));
        }
        mx0 = fmaxf(mx0, __shfl_xor_sync(0xffffffffu, mx0, 1));
        mx0 = fmaxf(mx0, __shfl_xor_sync(0xffffffffu, mx0, 2));
        mx1 = fmaxf(mx1, __shfl_xor_sync(0xffffffffu, mx1, 1));
        mx1 = fmaxf(mx1, __shfl_xor_sync(0xffffffffu, mx1, 2));
        float mn0 = fmaxf(m0, mx0), mn1 = fmaxf(m1, mx1);
        float a0 = __expf(m0 - mn0), a1 = __expf(m1 - mn1);
        float sum0 = 0.f, sum1 = 0.f;
#pragma unroll
        for (int nt = 0; nt < 8; nt++) {
            s[nt][0] = __expf(s[nt][0] - mn0); s[nt][1] = __expf(s[nt][1] - mn0);
            s[nt][2] = __expf(s[nt][2] - mn1); s[nt][3] = __expf(s[nt][3] - mn1);
            sum0 += s[nt][0] + s[nt][1];
            sum1 += s[nt][2] + s[nt][3];
        }
        sum0 += __shfl_xor_sync(0xffffffffu, sum0, 1);
        sum0 += __shfl_xor_sync(0xffffffffu, sum0, 2);
        sum1 += __shfl_xor_sync(0xffffffffu, sum1, 1);
        sum1 += __shfl_xor_sync(0xffffffffu, sum1, 2);
        l0 = l0 * a0 + sum0; l1 = l1 * a1 + sum1;
        m0 = mn0; m1 = mn1;
#pragma unroll
        for (int nt = 0; nt < 8; nt++) {
            o[nt][0] *= a0; o[nt][1] *= a0;
            o[nt][2] *= a1; o[nt][3] *= a1;
        }

        // ---- stage P (bf16 hi/lo), warp-private row band ----
#pragma unroll
        for (int nt = 0; nt < 8; nt++) {
            int byte0 = (warp * 16 + g) * KROW + (nt * 8 + 2 * t) * 2;
            float p0 = s[nt][0], p1 = s[nt][1];
            float p0h = __bfloat162float(__float2bfloat16_rn(p0));
            float p1h = __bfloat162float(__float2bfloat16_rn(p1));
            *(unsigned*)(sm + OFF_PH + byte0) = pack_bf16(p0h, p1h);
            *(unsigned*)(sm + OFF_PL + byte0) = pack_bf16(p0 - p0h, p1 - p1h);
            int byte1 = byte0 + 8 * KROW;
            float p2 = s[nt][2], p3 = s[nt][3];
            float p2h = __bfloat162float(__float2bfloat16_rn(p2));
            float p3h = __bfloat162float(__float2bfloat16_rn(p3));
            *(unsigned*)(sm + OFF_PH + byte1) = pack_bf16(p2h, p3h);
            *(unsigned*)(sm + OFF_PL + byte1) = pack_bf16(p2 - p2h, p3 - p3h);
        }
        __syncwarp();

        // ---- O += P @ V ----
#pragma unroll
        for (int kc = 0; kc < 4; kc++) {
            unsigned aP = smbase + kc * 32 + ppre;
            unsigned pah[4], pal[4];
            ldsm_x4(pah[0], pah[1], pah[2], pah[3], aP + OFF_PH);
            ldsm_x4(pal[0], pal[1], pal[2], pal[3], aP + OFF_PL);
#pragma unroll
            for (int ntp = 0; ntp < 4; ntp++) {
                unsigned aV = smbase + buf + kc * (16 * KROW) + ntp * 32 + vpre;
                unsigned h0, h1, h2, h3, lo0, lo1, lo2, lo3;
                ldsm_x4_t(h0, h1, h2, h3, aV + OFF_VH);
                ldsm_x4_t(lo0, lo1, lo2, lo3, aV + OFF_VL);
                unsigned bh0[2] = {h0, h1}, bh1[2] = {h2, h3};
                unsigned bl0[2] = {lo0, lo1}, bl1[2] = {lo2, lo3};
                mma_bf16(o[2 * ntp],     pal, bh0);
                mma_bf16(o[2 * ntp],     pah, bl0);
                mma_bf16(o[2 * ntp],     pah, bh0);
                mma_bf16(o[2 * ntp + 1], pal, bh1);
                mma_bf16(o[2 * ntp + 1], pah, bl1);
                mma_bf16(o[2 * ntp + 1], pah, bh1);
            }
        }
    }

    // ---- normalize + write as bf16 hi/lo (feeds out-proj GEMM) ----
    float i0 = 1.f / l0, i1 = 1.f / l1;
    int r0 = rowbase + warp * 16 + g;
#pragma unroll
    for (int nt = 0; nt < 8; nt++) {
        int col = h * HD + nt * 8 + 2 * t;
        size_t idx0 = (size_t)r0 * DIM + col;
        size_t idx1 = (size_t)(r0 + 8) * DIM + col;
        float x = o[nt][0] * i0, y = o[nt][1] * i0;
        float xh = __bfloat162float(__float2bfloat16_rn(x));
        float yh = __bfloat162float(__float2bfloat16_rn(y));
        *(unsigned*)(oh + idx0) = pack_bf16(xh, yh);
        *(unsigned*)(ol + idx0) = pack_bf16(x - xh, y - yh);
        x = o[nt][2] * i1; y = o[nt][3] * i1;
        xh = __bfloat162float(__float2bfloat16_rn(x));
        yh = __bfloat162float(__float2bfloat16_rn(y));
        *(unsigned*)(oh + idx1) = pack_bf16(xh, yh);
        *(unsigned*)(ol + idx1) = pack_bf16(x - xh, y - yh);
    }
}

// ---------------- launch ------------------------------------------------------
extern "C" void kernel_launch(void* const* d_in, const int* in_sizes, int n_in,
                              void* d_out, int out_size)
{
    const float* x        = (const float*)d_in[0];
    const float* context  = (const float*)d_in[1];
    const float* q_w      = (const float*)d_in[2];
    const float* kv_w     = (const float*)d_in[3];
    const float* qn_scale = (const float*)d_in[4];
    const float* qn_bias  = (const float*)d_in[5];
    const float* kn_scale = (const float*)d_in[6];
    const float* kn_bias  = (const float*)d_in[7];
    const float* proj_w   = (const float*)d_in[8];
    const float* proj_b   = (const float*)d_in[9];
    float* out = (float*)d_out;

    float *pq, *pkv;
    __nv_bfloat16 *pkh, *pkl, *pvh, *pvl, *pah, *pal;
    __nv_bfloat16 *pxh, *pxl, *pch, *pcl, *pqwh, *pqwl, *pkvwh, *pkvwl, *ppwh, *ppwl;
    cudaGetSymbolAddress((void**)&pq,  g_q);
    cudaGetSymbolAddress((void**)&pkv, g_kv);
    cudaGetSymbolAddress((void**)&pkh, g_kh);
    cudaGetSymbolAddress((void**)&pkl, g_kl);
    cudaGetSymbolAddress((void**)&pvh, g_vh);
    cudaGetSymbolAddress((void**)&pvl, g_vl);
    cudaGetSymbolAddress((void**)&pah, g_ah);
    cudaGetSymbolAddress((void**)&pal, g_al);
    cudaGetSymbolAddress((void**)&pxh, g_xh);
    cudaGetSymbolAddress((void**)&pxl, g_xl);
    cudaGetSymbolAddress((void**)&pch, g_ch);
    cudaGetSymbolAddress((void**)&pcl, g_cl);
    cudaGetSymbolAddress((void**)&pqwh, g_qwh);
    cudaGetSymbolAddress((void**)&pqwl, g_qwl);
    cudaGetSymbolAddress((void**)&pkvwh, g_kvwh);
    cudaGetSymbolAddress((void**)&pkvwl, g_kvwl);
    cudaGetSymbolAddress((void**)&ppwh, g_pwh);
    cudaGetSymbolAddress((void**)&ppwl, g_pwl);

    cudaFuncSetAttribute(bf16_gemm_kernel, cudaFuncAttributeMaxDynamicSharedMemorySize, (int)GEMM_SMEM);
    cudaFuncSetAttribute(attn_tc_kernel, cudaFuncAttributeMaxDynamicSharedMemorySize, (int)ATTN_SMEM);

    // 0. split inputs/weights to bf16 hi/lo
    split_bf16_kernel<<<MROWS * DIM / 1024, 256>>>(x, pxh, pxl);
    split_bf16_kernel<<<MROWS * DIM / 1024, 256>>>(context, pch, pcl);
    split_bf16_kernel<<<DIM * DIM / 1024, 256>>>(q_w, pqwh, pqwl);
    split_bf16_kernel<<<DIM * 2 * DIM / 1024, 256>>>(kv_w, pkvwh, pkvwl);
    split_bf16_kernel<<<DIM * DIM / 1024, 256>>>(proj_w, ppwh, ppwl);

    // 1. q = x @ q_w
    bf16_gemm_kernel<<<dim3(DIM / 128, MROWS / 128), 256, GEMM_SMEM>>>(
        pxh, pxl, pqwh, pqwl, nullptr, pq, MROWS, DIM, DIM);
    // 2. kv = context @ kv_w
    bf16_gemm_kernel<<<dim3(2 * DIM / 128, MROWS / 128), 256, GEMM_SMEM>>>(
        pch, pcl, pkvwh, pkvwl, nullptr, pkv, MROWS, 2 * DIM, DIM);
    // 3. per-head LN (+RoPE+scale on q); k LN + bf16 split, v bf16 split
    ln_rope_q_kernel<<<MROWS * NH / 8, 256>>>(pq, qn_scale, qn_bias);
    ln_k_v_split_kernel<<<MROWS * NH / 8, 256>>>(pkv, kn_scale, kn_bias, pkh, pkl, pvh, pvl);
    // 4. attention (bf16x3 + ldmatrix, 2 CTAs/SM)
    attn_tc_kernel<<<dim3(SEQ / 128, NH, BATCH), 256, ATTN_SMEM>>>(pq, pkh, pkl, pvh, pvl, pah, pal);
    // 5. out = att @ proj_w + proj_b
    bf16_gemm_kernel<<<dim3(DIM / 128, MROWS / 128), 256, GEMM_SMEM>>>(
        pah, pal, ppwh, ppwl, proj_b, out, MROWS, DIM, DIM);
}

// round 11
// speedup vs baseline: 3.1300x; 1.1413x over previous
#include <cuda_runtime.h>
#include <cuda_bf16.h>
#include <cuda_fp16.h>
#include <math.h>

#define DIM 1024
#define NH 16
#define HD 64
#define BATCH 4
#define SEQ 2048
#define MROWS (BATCH*SEQ)   // 8192

// ---------------- scratch (static device memory; no allocations) -------------
__device__ float g_q  [(size_t)MROWS * DIM];            // q proj (fp32, LN+RoPE in place)
__device__ float g_kv [(size_t)MROWS * 2 * DIM];        // raw kv projection fp32
__device__ __nv_bfloat16 g_kh[(size_t)MROWS * DIM];     // k hi
__device__ __nv_bfloat16 g_kl[(size_t)MROWS * DIM];     // k lo
__device__ __half        g_vf[(size_t)MROWS * DIM];     // v fp16 (single)
__device__ __nv_bfloat16 g_ah[(size_t)MROWS * DIM];     // attention out hi
__device__ __nv_bfloat16 g_al[(size_t)MROWS * DIM];     // attention out lo
__device__ __nv_bfloat16 g_xh[(size_t)MROWS * DIM];     // x hi/lo
__device__ __nv_bfloat16 g_xl[(size_t)MROWS * DIM];
__device__ __nv_bfloat16 g_ch[(size_t)MROWS * DIM];     // context hi/lo
__device__ __nv_bfloat16 g_cl[(size_t)MROWS * DIM];
__device__ __nv_bfloat16 g_qwh[(size_t)DIM * DIM];      // weights hi/lo
__device__ __nv_bfloat16 g_qwl[(size_t)DIM * DIM];
__device__ __nv_bfloat16 g_kvwh[(size_t)DIM * 2 * DIM];
__device__ __nv_bfloat16 g_kvwl[(size_t)DIM * 2 * DIM];
__device__ __nv_bfloat16 g_pwh[(size_t)DIM * DIM];
__device__ __nv_bfloat16 g_pwl[(size_t)DIM * DIM];

// ---------------- helpers -----------------------------------------------------
__device__ __forceinline__ void mma_bf16(float c[4], const unsigned a[4], const unsigned b[2]) {
    asm volatile(
        "mma.sync.aligned.m16n8k16.row.col.f32.bf16.bf16.f32 "
        "{%0,%1,%2,%3}, {%4,%5,%6,%7}, {%8,%9}, {%0,%1,%2,%3};\n"
        : "+f"(c[0]), "+f"(c[1]), "+f"(c[2]), "+f"(c[3])
        : "r"(a[0]), "r"(a[1]), "r"(a[2]), "r"(a[3]), "r"(b[0]), "r"(b[1]));
}
__device__ __forceinline__ void mma_fp16(float c[4], const unsigned a[4], const unsigned b[2]) {
    asm volatile(
        "mma.sync.aligned.m16n8k16.row.col.f32.f16.f16.f32 "
        "{%0,%1,%2,%3}, {%4,%5,%6,%7}, {%8,%9}, {%0,%1,%2,%3};\n"
        : "+f"(c[0]), "+f"(c[1]), "+f"(c[2]), "+f"(c[3])
        : "r"(a[0]), "r"(a[1]), "r"(a[2]), "r"(a[3]), "r"(b[0]), "r"(b[1]));
}
__device__ __forceinline__ unsigned pack_bf16(float x, float y) {
    __nv_bfloat162 v = __floats2bfloat162_rn(x, y);
    return *(unsigned*)&v;
}
__device__ __forceinline__ unsigned pack_f16(float x, float y) {
    __half2 v = __floats2half2_rn(x, y);
    return *(unsigned*)&v;
}
__device__ __forceinline__ void ldsm_x4(unsigned& r0, unsigned& r1, unsigned& r2, unsigned& r3, unsigned addr) {
    asm volatile("ldmatrix.sync.aligned.m8n8.x4.shared.b16 {%0,%1,%2,%3}, [%4];"
                 : "=r"(r0), "=r"(r1), "=r"(r2), "=r"(r3) : "r"(addr));
}
__device__ __forceinline__ void ldsm_x4_t(unsigned& r0, unsigned& r1, unsigned& r2, unsigned& r3, unsigned addr) {
    asm volatile("ldmatrix.sync.aligned.m8n8.x4.trans.shared.b16 {%0,%1,%2,%3}, [%4];"
                 : "=r"(r0), "=r"(r1), "=r"(r2), "=r"(r3) : "r"(addr));
}

// ---------------- elementwise fp32 -> bf16 hi/lo split ------------------------
__global__ __launch_bounds__(256) void split_bf16_kernel(
    const float* __restrict__ in, __nv_bfloat16* __restrict__ hi, __nv_bfloat16* __restrict__ lo)
{
    size_t i = ((size_t)blockIdx.x * 256 + threadIdx.x) * 4;
    float4 v = *(const float4*)(in + i);
    float hx = __bfloat162float(__float2bfloat16_rn(v.x));
    float hy = __bfloat162float(__float2bfloat16_rn(v.y));
    float hz = __bfloat162float(__float2bfloat16_rn(v.z));
    float hw = __bfloat162float(__float2bfloat16_rn(v.w));
    uint2 hv, lv;
    hv.x = pack_bf16(hx, hy); hv.y = pack_bf16(hz, hw);
    lv.x = pack_bf16(v.x - hx, v.y - hy); lv.y = pack_bf16(v.z - hz, v.w - hw);
    *(uint2*)(hi + i) = hv;
    *(uint2*)(lo + i) = lv;
}

// =======================  bf16x3 ldmatrix GEMM, 3-stage pipeline  ============
#define G_AROW 80
#define G_BROW 272
#define G_OFF_AL 10240
#define G_OFF_BH 20480
#define G_OFF_BL 29184
#define G_STG 37888
#define GEMM_SMEM (3*G_STG)   // 113664 B

__global__ __launch_bounds__(256) void bf16_gemm_kernel(
    const __nv_bfloat16* __restrict__ Ah, const __nv_bfloat16* __restrict__ Al,
    const __nv_bfloat16* __restrict__ Bh, const __nv_bfloat16* __restrict__ Bl,
    const float* __restrict__ bias, float* __restrict__ C,
    int M, int N, int K)
{
    extern __shared__ char dynsm[];
    char* sm = dynsm;
    const int tid = threadIdx.x;
    const int warp = tid >> 5, lane = tid & 31;
    const int group = lane >> 2, tig = lane & 3;
    const int mat = lane >> 3, r = lane & 7;
    const int wm = (warp & 1) * 64;
    const int wn = (warp >> 1) * 32;
    const int m0 = blockIdx.y * 128, n0 = blockIdx.x * 128;

    float acc[4][4][4] = {};

#define BGEMM_ISSUE(s, k0)                                                                    \
    do {                                                                                      \
        _Pragma("unroll")                                                                     \
        for (int u = 0; u < 2; u++) {                                                         \
            int j = tid + u * 256;                                                            \
            int row = j >> 2, c = j & 3;                                                      \
            size_t src = (size_t)(m0 + row) * K + (k0) + c * 8;                               \
            unsigned d = (unsigned)__cvta_generic_to_shared(sm + (s) * G_STG + row * G_AROW + c * 16); \
            asm volatile("cp.async.cg.shared.global [%0], [%1], 16;" :: "r"(d), "l"(Ah + src)); \
            asm volatile("cp.async.cg.shared.global [%0], [%1], 16;" :: "r"(d + G_OFF_AL), "l"(Al + src)); \
        }                                                                                     \
        _Pragma("unroll")                                                                     \
        for (int u = 0; u < 2; u++) {                                                         \
            int j = tid + u * 256;                                                            \
            int kr = j >> 4, c = j & 15;                                                      \
            size_t src = (size_t)((k0) + kr) * N + n0 + c * 8;                                \
            unsigned d = (unsigned)__cvta_generic_to_shared(sm + (s) * G_STG + G_OFF_BH + kr * G_BROW + c * 16); \
            asm volatile("cp.async.cg.shared.global [%0], [%1], 16;" :: "r"(d), "l"(Bh + src)); \
            asm volatile("cp.async.cg.shared.global [%0], [%1], 16;" :: "r"(d + (G_OFF_BL - G_OFF_BH)), "l"(Bl + src)); \
        }                                                                                     \
        asm volatile("cp.async.commit_group;");                                               \
    } while (0)

    const unsigned smbase = (unsigned)__cvta_generic_to_shared(sm);
    const unsigned a_pre = ((mat & 1) * 8 + r) * G_AROW + (mat >> 1) * 16;
    const unsigned b_pre = ((mat & 1) * 8 + r) * G_BROW + (mat >> 1) * 16;

    const int NT = K / 32;
    BGEMM_ISSUE(0, 0);
    BGEMM_ISSUE(1, 32);
    for (int kt = 0; kt < NT; kt++) {
        if (kt + 2 < NT) {
            int st = (kt + 2) % 3;
            BGEMM_ISSUE(st, (kt + 2) * 32);
            asm volatile("cp.async.wait_group 2;");
        } else if (kt + 1 < NT) {
            asm volatile("cp.async.wait_group 1;");
        } else {
            asm volatile("cp.async.wait_group 0;");
        }
        __syncthreads();

        const unsigned base = smbase + (kt % 3) * G_STG;
#pragma unroll
        for (int kk = 0; kk < 2; kk++) {
            unsigned ah[4][4], al[4][4];
#pragma unroll
            for (int mi = 0; mi < 4; mi++) {
                unsigned aa = base + (wm + mi * 16) * G_AROW + kk * 32 + a_pre;
                ldsm_x4(ah[mi][0], ah[mi][1], ah[mi][2], ah[mi][3], aa);
                ldsm_x4(al[mi][0], al[mi][1], al[mi][2], al[mi][3], aa + G_OFF_AL);
            }
            unsigned bh[4][2], bl[4][2];
#pragma unroll
            for (int j = 0; j < 2; j++) {
                unsigned bb = base + G_OFF_BH + kk * 16 * G_BROW + (wn + j * 16) * 2 + b_pre;
                unsigned t0, t1, t2, t3;
                ldsm_x4_t(t0, t1, t2, t3, bb);
                bh[2 * j][0] = t0; bh[2 * j][1] = t1; bh[2 * j + 1][0] = t2; bh[2 * j + 1][1] = t3;
                ldsm_x4_t(t0, t1, t2, t3, bb + (G_OFF_BL - G_OFF_BH));
                bl[2 * j][0] = t0; bl[2 * j][1] = t1; bl[2 * j + 1][0] = t2; bl[2 * j + 1][1] = t3;
            }
#pragma unroll
            for (int mi = 0; mi < 4; mi++)
#pragma unroll
                for (int ni = 0; ni < 4; ni++) {
                    mma_bf16(acc[mi][ni], al[mi], bh[ni]);
                    mma_bf16(acc[mi][ni], ah[mi], bl[ni]);
                    mma_bf16(acc[mi][ni], ah[mi], bh[ni]);
                }
        }
        __syncthreads();
    }

#pragma unroll
    for (int mi = 0; mi < 4; mi++) {
#pragma unroll
        for (int ni = 0; ni < 4; ni++) {
            int col = n0 + wn + ni * 8 + tig * 2;
            float bx = 0.f, by = 0.f;
            if (bias) { bx = bias[col]; by = bias[col + 1]; }
            int r0 = m0 + wm + mi * 16 + group;
            float2 v0; v0.x = acc[mi][ni][0] + bx; v0.y = acc[mi][ni][1] + by;
            *(float2*)(C + (size_t)r0 * N + col) = v0;
            float2 v1; v1.x = acc[mi][ni][2] + bx; v1.y = acc[mi][ni][3] + by;
            *(float2*)(C + (size_t)(r0 + 8) * N + col) = v1;
        }
    }
}

// ---------------- per-head LayerNorm (+RoPE + 1/8 scale on q) ----------------
__global__ __launch_bounds__(256) void ln_rope_q_kernel(
    float* __restrict__ q, const float* __restrict__ scale, const float* __restrict__ bias)
{
    int gw = blockIdx.x * 8 + (threadIdx.x >> 5);
    int lane = threadIdx.x & 31;
    int row = gw >> 4;
    int h = gw & 15;
    float* p = q + (size_t)row * DIM + h * HD;
    float e0 = p[lane], e1 = p[lane + 32];
    float ssum = e0 + e1;
#pragma unroll
    for (int o = 16; o; o >>= 1) ssum += __shfl_xor_sync(0xffffffffu, ssum, o);
    float mu = ssum * (1.f / 64.f);
    float d0 = e0 - mu, d1 = e1 - mu;
    float vs = d0 * d0 + d1 * d1;
#pragma unroll
    for (int o = 16; o; o >>= 1) vs += __shfl_xor_sync(0xffffffffu, vs, o);
    float rstd = rsqrtf(vs * (1.f / 64.f) + 1e-5f);
    float n0 = d0 * rstd * scale[lane] + bias[lane];
    float n1 = d1 * rstd * scale[lane + 32] + bias[lane + 32];
    int s = row & (SEQ - 1);
    float invf = powf(10000.f, -(float)lane * (1.f / 32.f));
    float ang = (float)s * invf;
    float sn, c;
    sincosf(ang, &sn, &c);
    p[lane]      = (n0 * c - n1 * sn) * 0.125f;
    p[lane + 32] = (n0 * sn + n1 * c) * 0.125f;
}

// ---------------- k LayerNorm + bf16 split; v -> fp16 ------------------------
__global__ __launch_bounds__(256) void ln_k_v_split_kernel(
    const float* __restrict__ kv, const float* __restrict__ scale, const float* __restrict__ bias,
    __nv_bfloat16* __restrict__ kh, __nv_bfloat16* __restrict__ kl,
    __half* __restrict__ vf)
{
    int gw = blockIdx.x * 8 + (threadIdx.x >> 5);
    int lane = threadIdx.x & 31;
    int row = gw >> 4;
    int h = gw & 15;
    const float* p = kv + (size_t)row * (2 * DIM) + h * HD;
    float e0 = p[lane], e1 = p[lane + 32];
    float ssum = e0 + e1;
#pragma unroll
    for (int o = 16; o; o >>= 1) ssum += __shfl_xor_sync(0xffffffffu, ssum, o);
    float mu = ssum * (1.f / 64.f);
    float d0 = e0 - mu, d1 = e1 - mu;
    float vs = d0 * d0 + d1 * d1;
#pragma unroll
    for (int o = 16; o; o >>= 1) vs += __shfl_xor_sync(0xffffffffu, vs, o);
    float rstd = rsqrtf(vs * (1.f / 64.f) + 1e-5f);
    float n0 = d0 * rstd * scale[lane] + bias[lane];
    float n1 = d1 * rstd * scale[lane + 32] + bias[lane + 32];

    size_t oidx = (size_t)row * DIM + h * HD;
    __nv_bfloat16 bh;
    bh = __float2bfloat16_rn(n0);
    kh[oidx + lane] = bh; kl[oidx + lane] = __float2bfloat16_rn(n0 - __bfloat162float(bh));
    bh = __float2bfloat16_rn(n1);
    kh[oidx + lane + 32] = bh; kl[oidx + lane + 32] = __float2bfloat16_rn(n1 - __bfloat162float(bh));

    const float* pv = p + DIM;
    vf[oidx + lane]      = __float2half_rn(pv[lane]);
    vf[oidx + lane + 32] = __float2half_rn(pv[lane + 32]);
}

// ---------------- flash attention: QK bf16x3, PV fp16 ------------------------
// CTA 256 thr / 8 warps, BQ=128 (16 rows/warp), key tiles BK=64, occupancy 2.
#define KROW 144
#define KTILE (64*KROW)            // 9216 B
#define OFF_KH 0                   // [2][KTILE]
#define OFF_KL (2*KTILE)
#define OFF_VF (4*KTILE)
#define OFF_PH (6*KTILE)           // 55296, [128][144B] fp16
#define ATTN_SMEM (OFF_PH + 128*KROW)   // 73728 B -> 2 CTAs/SM

__global__ __launch_bounds__(256, 2) void attn_tc_kernel(
    const float* __restrict__ q,
    const __nv_bfloat16* __restrict__ kh, const __nv_bfloat16* __restrict__ kl,
    const __half* __restrict__ vf,
    __nv_bfloat16* __restrict__ oh, __nv_bfloat16* __restrict__ ol)
{
    extern __shared__ char dynsm[];
    char* sm = dynsm;
    const int tid = threadIdx.x;
    const int warp = tid >> 5, lane = tid & 31;
    const int g = lane >> 2, t = lane & 3;
    const int mat = lane >> 3, r = lane & 7;
    const int h = blockIdx.y, b = blockIdx.z;
    const int rowbase = b * SEQ + blockIdx.x * 128;
    const int ctxbase = b * SEQ;

#define KV_LOAD(buf, tile)                                                                     \
    do {                                                                                       \
        _Pragma("unroll")                                                                      \
        for (int u = 0; u < 2; u++) {                                                          \
            int i = tid + u * 256;                                                             \
            int key = i >> 3, c = i & 7;                                                       \
            size_t src = ((size_t)(ctxbase + (tile) * 64 + key) << 10) + h * HD + c * 8;       \
            unsigned dst = (unsigned)__cvta_generic_to_shared(sm + (buf) * KTILE + key * KROW + c * 16); \
            asm volatile("cp.async.cg.shared.global [%0], [%1], 16;" :: "r"(dst + OFF_KH), "l"(kh + src)); \
            asm volatile("cp.async.cg.shared.global [%0], [%1], 16;" :: "r"(dst + OFF_KL), "l"(kl + src)); \
            asm volatile("cp.async.cg.shared.global [%0], [%1], 16;" :: "r"(dst + OFF_VF), "l"(vf + src)); \
        }                                                                                      \
        asm volatile("cp.async.commit_group;");                                                \
    } while (0)

    KV_LOAD(0, 0);

    // ---- Q fragments (bf16 hi/lo) via direct LDG, warp-private rows ----
    unsigned qh[4][4], ql[4][4];
    {
        const float* qp = q + (size_t)(rowbase + warp * 16 + g) * DIM + h * HD;
#pragma unroll
        for (int kc = 0; kc < 4; kc++) {
#pragma unroll
            for (int a = 0; a < 4; a++) {
                const float* pp = qp + (size_t)((a & 1) * 8) * DIM + kc * 16 + 2 * t + (a >> 1) * 8;
                float x = pp[0], y = pp[1];
                float xh = __bfloat162float(__float2bfloat16_rn(x));
                float yh = __bfloat162float(__float2bfloat16_rn(y));
                qh[kc][a] = pack_bf16(xh, yh);
                ql[kc][a] = pack_bf16(x - xh, y - yh);
            }
        }
    }

    float o[8][4] = {};
    float m0 = -1e30f, m1 = -1e30f, l0 = 0.f, l1 = 0.f;

    const unsigned smbase = (unsigned)__cvta_generic_to_shared(sm);
    const unsigned kpre = (mat >> 1) * 8 * KROW + r * KROW + (mat & 1) * 16;
    const unsigned ppre = (warp * 16 + (mat & 1) * 8 + r) * KROW + (mat >> 1) * 16;
    const unsigned vpre = (mat & 1) * 8 * KROW + r * KROW + (mat >> 1) * 16;

    const int NT = SEQ / 64;
    for (int kt = 0; kt < NT; kt++) {
        __syncthreads();
        if (kt + 1 < NT) {
            KV_LOAD((kt + 1) & 1, kt + 1);
            asm volatile("cp.async.wait_group 1;");
        } else {
            asm volatile("cp.async.wait_group 0;");
        }
        __syncthreads();

        const unsigned buf = (kt & 1) * KTILE;

        // ---- S = Q @ K^T (bf16 x3) ----
        float s[8][4] = {};
#pragma unroll
        for (int kc = 0; kc < 4; kc++) {
#pragma unroll
            for (int ntp = 0; ntp < 4; ntp++) {
                unsigned aK = smbase + buf + ntp * (16 * KROW) + kc * 32 + kpre;
                unsigned h0, h1, h2, h3, lo0, lo1, lo2, lo3;
                ldsm_x4(h0, h1, h2, h3, aK + OFF_KH);
                ldsm_x4(lo0, lo1, lo2, lo3, aK + OFF_KL);
                unsigned bh0[2] = {h0, h1}, bh1[2] = {h2, h3};
                unsigned bl0[2] = {lo0, lo1}, bl1[2] = {lo2, lo3};
                mma_bf16(s[2 * ntp],     ql[kc], bh0);
                mma_bf16(s[2 * ntp],     qh[kc], bl0);
                mma_bf16(s[2 * ntp],     qh[kc], bh0);
                mma_bf16(s[2 * ntp + 1], ql[kc], bh1);
                mma_bf16(s[2 * ntp + 1], qh[kc], bl1);
                mma_bf16(s[2 * ntp + 1], qh[kc], bh1);
            }
        }

        // ---- online softmax (rows g, g+8; warp-local over 4 tig lanes) ----
        float mx0 = s[0][0], mx1 = s[0][2];
#pragma unroll
        for (int nt = 0; nt < 8; nt++) {
            mx0 = fmaxf(mx0, fmaxf(s[nt][0], s[nt][1]));
            mx1 = fmaxf(mx1, fmaxf(s[nt][2], s[nt][3]));
        }
        mx0 = fmaxf(mx0, __shfl_xor_sync(0xffffffffu, mx0, 1));
        mx0 = fmaxf(mx0, __shfl_xor_sync(0xffffffffu, mx0, 2));
        mx1 = fmaxf(mx1, __shfl_xor_sync(0xffffffffu, mx1, 1));
        mx1 = fmaxf(mx1, __shfl_xor_sync(0xffffffffu, mx1, 2));
        float mn0 = fmaxf(m0, mx0), mn1 = fmaxf(m1, mx1);
        float a0 = __expf(m0 - mn0), a1 = __expf(m1 - mn1);
        float sum0 = 0.f, sum1 = 0.f;
#pragma unroll
        for (int nt = 0; nt < 8; nt++) {
            s[nt][0] = __expf(s[nt][0] - mn0); s[nt][1] = __expf(s[nt][1] - mn0);
            s[nt][2] = __expf(s[nt][2] - mn1); s[nt][3] = __expf(s[nt][3] - mn1);
            sum0 += s[nt][0] + s[nt][1];
            sum1 += s[nt][2] + s[nt][3];
        }
        sum0 += __shfl_xor_sync(0xffffffffu, sum0, 1);
        sum0 += __shfl_xor_sync(0xffffffffu, sum0, 2);
        sum1 += __shfl_xor_sync(0xffffffffu, sum1, 1);
        sum1 += __shfl_xor_sync(0xffffffffu, sum1, 2);
        l0 = l0 * a0 + sum0; l1 = l1 * a1 + sum1;
        m0 = mn0; m1 = mn1;
#pragma unroll
        for (int nt = 0; nt < 8; nt++) {
            o[nt][0] *= a0; o[nt][1] *= a0;
            o[nt][2] *= a1; o[nt][3] *= a1;
        }

        // ---- stage P (fp16), warp-private row band ----
#pragma unroll
        for (int nt = 0; nt < 8; nt++) {
            int byte0 = (warp * 16 + g) * KROW + (nt * 8 + 2 * t) * 2;
            *(unsigned*)(sm + OFF_PH + byte0) = pack_f16(s[nt][0], s[nt][1]);
            *(unsigned*)(sm + OFF_PH + byte0 + 8 * KROW) = pack_f16(s[nt][2], s[nt][3]);
        }
        __syncwarp();

        // ---- O += P @ V (fp16 single) ----
#pragma unroll
        for (int kc = 0; kc < 4; kc++) {
            unsigned aP = smbase + kc * 32 + ppre;
            unsigned pa[4];
            ldsm_x4(pa[0], pa[1], pa[2], pa[3], aP + OFF_PH);
#pragma unroll
            for (int ntp = 0; ntp < 4; ntp++) {
                unsigned aV = smbase + buf + kc * (16 * KROW) + ntp * 32 + vpre + OFF_VF;
                unsigned v0, v1, v2, v3;
                ldsm_x4_t(v0, v1, v2, v3, aV);
                unsigned b0[2] = {v0, v1}, b1[2] = {v2, v3};
                mma_fp16(o[2 * ntp],     pa, b0);
                mma_fp16(o[2 * ntp + 1], pa, b1);
            }
        }
    }

    // ---- normalize + write as bf16 hi/lo (feeds out-proj GEMM) ----
    float i0 = 1.f / l0, i1 = 1.f / l1;
    int r0 = rowbase + warp * 16 + g;
#pragma unroll
    for (int nt = 0; nt < 8; nt++) {
        int col = h * HD + nt * 8 + 2 * t;
        size_t idx0 = (size_t)r0 * DIM + col;
        size_t idx1 = (size_t)(r0 + 8) * DIM + col;
        float x = o[nt][0] * i0, y = o[nt][1] * i0;
        float xh = __bfloat162float(__float2bfloat16_rn(x));
        float yh = __bfloat162float(__float2bfloat16_rn(y));
        *(unsigned*)(oh + idx0) = pack_bf16(xh, yh);
        *(unsigned*)(ol + idx0) = pack_bf16(x - xh, y - yh);
        x = o[nt][2] * i1; y = o[nt][3] * i1;
        xh = __bfloat162float(__float2bfloat16_rn(x));
        yh = __bfloat162float(__float2bfloat16_rn(y));
        *(unsigned*)(oh + idx1) = pack_bf16(xh, yh);
        *(unsigned*)(ol + idx1) = pack_bf16(x - xh, y - yh);
    }
}

// ---------------- launch ------------------------------------------------------
extern "C" void kernel_launch(void* const* d_in, const int* in_sizes, int n_in,
                              void* d_out, int out_size)
{
    const float* x        = (const float*)d_in[0];
    const float* context  = (const float*)d_in[1];
    const float* q_w      = (const float*)d_in[2];
    const float* kv_w     = (const float*)d_in[3];
    const float* qn_scale = (const float*)d_in[4];
    const float* qn_bias  = (const float*)d_in[5];
    const float* kn_scale = (const float*)d_in[6];
    const float* kn_bias  = (const float*)d_in[7];
    const float* proj_w   = (const float*)d_in[8];
    const float* proj_b   = (const float*)d_in[9];
    float* out = (float*)d_out;

    float *pq, *pkv;
    __half *pvf;
    __nv_bfloat16 *pkh, *pkl, *pah, *pal;
    __nv_bfloat16 *pxh, *pxl, *pch, *pcl, *pqwh, *pqwl, *pkvwh, *pkvwl, *ppwh, *ppwl;
    cudaGetSymbolAddress((void**)&pq,  g_q);
    cudaGetSymbolAddress((void**)&pkv, g_kv);
    cudaGetSymbolAddress((void**)&pkh, g_kh);
    cudaGetSymbolAddress((void**)&pkl, g_kl);
    cudaGetSymbolAddress((void**)&pvf, g_vf);
    cudaGetSymbolAddress((void**)&pah, g_ah);
    cudaGetSymbolAddress((void**)&pal, g_al);
    cudaGetSymbolAddress((void**)&pxh, g_xh);
    cudaGetSymbolAddress((void**)&pxl, g_xl);
    cudaGetSymbolAddress((void**)&pch, g_ch);
    cudaGetSymbolAddress((void**)&pcl, g_cl);
    cudaGetSymbolAddress((void**)&pqwh, g_qwh);
    cudaGetSymbolAddress((void**)&pqwl, g_qwl);
    cudaGetSymbolAddress((void**)&pkvwh, g_kvwh);
    cudaGetSymbolAddress((void**)&pkvwl, g_kvwl);
    cudaGetSymbolAddress((void**)&ppwh, g_pwh);
    cudaGetSymbolAddress((void**)&ppwl, g_pwl);

    cudaFuncSetAttribute(bf16_gemm_kernel, cudaFuncAttributeMaxDynamicSharedMemorySize, (int)GEMM_SMEM);
    cudaFuncSetAttribute(attn_tc_kernel, cudaFuncAttributeMaxDynamicSharedMemorySize, (int)ATTN_SMEM);

    // 0. split inputs/weights to bf16 hi/lo
    split_bf16_kernel<<<MROWS * DIM / 1024, 256>>>(x, pxh, pxl);
    split_bf16_kernel<<<MROWS * DIM / 1024, 256>>>(context, pch, pcl);
    split_bf16_kernel<<<DIM * DIM / 1024, 256>>>(q_w, pqwh, pqwl);
    split_bf16_kernel<<<DIM * 2 * DIM / 1024, 256>>>(kv_w, pkvwh, pkvwl);
    split_bf16_kernel<<<DIM * DIM / 1024, 256>>>(proj_w, ppwh, ppwl);

    // 1. q = x @ q_w
    bf16_gemm_kernel<<<dim3(DIM / 128, MROWS / 128), 256, GEMM_SMEM>>>(
        pxh, pxl, pqwh, pqwl, nullptr, pq, MROWS, DIM, DIM);
    // 2. kv = context @ kv_w
    bf16_gemm_kernel<<<dim3(2 * DIM / 128, MROWS / 128), 256, GEMM_SMEM>>>(
        pch, pcl, pkvwh, pkvwl, nullptr, pkv, MROWS, 2 * DIM, DIM);
    // 3. per-head LN (+RoPE+scale on q); k LN + bf16 split, v fp16
    ln_rope_q_kernel<<<MROWS * NH / 8, 256>>>(pq, qn_scale, qn_bias);
    ln_k_v_split_kernel<<<MROWS * NH / 8, 256>>>(pkv, kn_scale, kn_bias, pkh, pkl, pvf);
    // 4. attention (QK bf16x3, PV fp16)
    attn_tc_kernel<<<dim3(SEQ / 128, NH, BATCH), 256, ATTN_SMEM>>>(pq, pkh, pkl, pvf, pah, pal);
    // 5. out = att @ proj_w + proj_b
    bf16_gemm_kernel<<<dim3(DIM / 128, MROWS / 128), 256, GEMM_SMEM>>>(
        pah, pal, ppwh, ppwl, proj_b, out, MROWS, DIM, DIM);
}

// round 13
// speedup vs baseline: 3.6872x; 1.1780x over previous
#include <cuda_runtime.h>
#include <cuda_bf16.h>
#include <cuda_fp16.h>
#include <math.h>

#define DIM 1024
#define NH 16
#define HD 64
#define BATCH 4
#define SEQ 2048
#define MROWS (BATCH*SEQ)   // 8192

// ---------------- scratch (static device memory; no allocations) -------------
__device__ float g_q  [(size_t)MROWS * DIM];            // q proj fp32 (pre-LN)
__device__ float g_kv [(size_t)MROWS * 2 * DIM];        // raw kv projection fp32
__device__ __half        g_qf[(size_t)MROWS * DIM];     // q fp16 (LN+RoPE+scale)
__device__ __half        g_kf[(size_t)MROWS * DIM];     // k fp16 (LN)
__device__ __half        g_vf[(size_t)MROWS * DIM];     // v fp16
__device__ __nv_bfloat16 g_ah[(size_t)MROWS * DIM];     // attention out hi
__device__ __nv_bfloat16 g_al[(size_t)MROWS * DIM];     // attention out lo
__device__ __nv_bfloat16 g_xh[(size_t)MROWS * DIM];     // x hi/lo
__device__ __nv_bfloat16 g_xl[(size_t)MROWS * DIM];
__device__ __nv_bfloat16 g_ch[(size_t)MROWS * DIM];     // context hi/lo
__device__ __nv_bfloat16 g_cl[(size_t)MROWS * DIM];
__device__ __nv_bfloat16 g_qwh[(size_t)DIM * DIM];      // weights hi/lo
__device__ __nv_bfloat16 g_qwl[(size_t)DIM * DIM];
__device__ __nv_bfloat16 g_kvwh[(size_t)DIM * 2 * DIM];
__device__ __nv_bfloat16 g_kvwl[(size_t)DIM * 2 * DIM];
__device__ __nv_bfloat16 g_pwh[(size_t)DIM * DIM];
__device__ __nv_bfloat16 g_pwl[(size_t)DIM * DIM];

// ---------------- helpers -----------------------------------------------------
__device__ __forceinline__ void mma_bf16(float c[4], const unsigned a[4], const unsigned b[2]) {
    asm volatile(
        "mma.sync.aligned.m16n8k16.row.col.f32.bf16.bf16.f32 "
        "{%0,%1,%2,%3}, {%4,%5,%6,%7}, {%8,%9}, {%0,%1,%2,%3};\n"
        : "+f"(c[0]), "+f"(c[1]), "+f"(c[2]), "+f"(c[3])
        : "r"(a[0]), "r"(a[1]), "r"(a[2]), "r"(a[3]), "r"(b[0]), "r"(b[1]));
}
__device__ __forceinline__ void mma_fp16(float c[4], const unsigned a[4], const unsigned b[2]) {
    asm volatile(
        "mma.sync.aligned.m16n8k16.row.col.f32.f16.f16.f32 "
        "{%0,%1,%2,%3}, {%4,%5,%6,%7}, {%8,%9}, {%0,%1,%2,%3};\n"
        : "+f"(c[0]), "+f"(c[1]), "+f"(c[2]), "+f"(c[3])
        : "r"(a[0]), "r"(a[1]), "r"(a[2]), "r"(a[3]), "r"(b[0]), "r"(b[1]));
}
__device__ __forceinline__ unsigned pack_bf16(float x, float y) {
    __nv_bfloat162 v = __floats2bfloat162_rn(x, y);
    return *(unsigned*)&v;
}
__device__ __forceinline__ unsigned pack_f16(float x, float y) {
    __half2 v = __floats2half2_rn(x, y);
    return *(unsigned*)&v;
}
__device__ __forceinline__ void ldsm_x4(unsigned& r0, unsigned& r1, unsigned& r2, unsigned& r3, unsigned addr) {
    asm volatile("ldmatrix.sync.aligned.m8n8.x4.shared.b16 {%0,%1,%2,%3}, [%4];"
                 : "=r"(r0), "=r"(r1), "=r"(r2), "=r"(r3) : "r"(addr));
}
__device__ __forceinline__ void ldsm_x4_t(unsigned& r0, unsigned& r1, unsigned& r2, unsigned& r3, unsigned addr) {
    asm volatile("ldmatrix.sync.aligned.m8n8.x4.trans.shared.b16 {%0,%1,%2,%3}, [%4];"
                 : "=r"(r0), "=r"(r1), "=r"(r2), "=r"(r3) : "r"(addr));
}

// ---------------- elementwise fp32 -> bf16 hi/lo split ------------------------
__global__ __launch_bounds__(256) void split_bf16_kernel(
    const float* __restrict__ in, __nv_bfloat16* __restrict__ hi, __nv_bfloat16* __restrict__ lo)
{
    size_t i = ((size_t)blockIdx.x * 256 + threadIdx.x) * 4;
    float4 v = *(const float4*)(in + i);
    float hx = __bfloat162float(__float2bfloat16_rn(v.x));
    float hy = __bfloat162float(__float2bfloat16_rn(v.y));
    float hz = __bfloat162float(__float2bfloat16_rn(v.z));
    float hw = __bfloat162float(__float2bfloat16_rn(v.w));
    uint2 hv, lv;
    hv.x = pack_bf16(hx, hy); hv.y = pack_bf16(hz, hw);
    lv.x = pack_bf16(v.x - hx, v.y - hy); lv.y = pack_bf16(v.z - hz, v.w - hw);
    *(uint2*)(hi + i) = hv;
    *(uint2*)(lo + i) = lv;
}

// =======================  bf16x3 ldmatrix GEMM, 3-stage pipeline (R10) =======
#define G_AROW 80
#define G_BROW 272
#define G_OFF_AL 10240
#define G_OFF_BH 20480
#define G_OFF_BL 29184
#define G_STG 37888
#define GEMM_SMEM (3*G_STG)   // 113664 B

__global__ __launch_bounds__(256) void bf16_gemm_kernel(
    const __nv_bfloat16* __restrict__ Ah, const __nv_bfloat16* __restrict__ Al,
    const __nv_bfloat16* __restrict__ Bh, const __nv_bfloat16* __restrict__ Bl,
    const float* __restrict__ bias, float* __restrict__ C,
    int M, int N, int K)
{
    extern __shared__ char dynsm[];
    char* sm = dynsm;
    const int tid = threadIdx.x;
    const int warp = tid >> 5, lane = tid & 31;
    const int group = lane >> 2, tig = lane & 3;
    const int mat = lane >> 3, r = lane & 7;
    const int wm = (warp & 1) * 64;
    const int wn = (warp >> 1) * 32;
    const int m0 = blockIdx.y * 128, n0 = blockIdx.x * 128;

    float acc[4][4][4] = {};

#define BGEMM_ISSUE(s, k0)                                                                    \
    do {                                                                                      \
        _Pragma("unroll")                                                                     \
        for (int u = 0; u < 2; u++) {                                                         \
            int j = tid + u * 256;                                                            \
            int row = j >> 2, c = j & 3;                                                      \
            size_t src = (size_t)(m0 + row) * K + (k0) + c * 8;                               \
            unsigned d = (unsigned)__cvta_generic_to_shared(sm + (s) * G_STG + row * G_AROW + c * 16); \
            asm volatile("cp.async.cg.shared.global [%0], [%1], 16;" :: "r"(d), "l"(Ah + src)); \
            asm volatile("cp.async.cg.shared.global [%0], [%1], 16;" :: "r"(d + G_OFF_AL), "l"(Al + src)); \
        }                                                                                     \
        _Pragma("unroll")                                                                     \
        for (int u = 0; u < 2; u++) {                                                         \
            int j = tid + u * 256;                                                            \
            int kr = j >> 4, c = j & 15;                                                      \
            size_t src = (size_t)((k0) + kr) * N + n0 + c * 8;                                \
            unsigned d = (unsigned)__cvta_generic_to_shared(sm + (s) * G_STG + G_OFF_BH + kr * G_BROW + c * 16); \
            asm volatile("cp.async.cg.shared.global [%0], [%1], 16;" :: "r"(d), "l"(Bh + src)); \
            asm volatile("cp.async.cg.shared.global [%0], [%1], 16;" :: "r"(d + (G_OFF_BL - G_OFF_BH)), "l"(Bl + src)); \
        }                                                                                     \
        asm volatile("cp.async.commit_group;");                                               \
    } while (0)

    const unsigned smbase = (unsigned)__cvta_generic_to_shared(sm);
    const unsigned a_pre = ((mat & 1) * 8 + r) * G_AROW + (mat >> 1) * 16;
    const unsigned b_pre = ((mat & 1) * 8 + r) * G_BROW + (mat >> 1) * 16;

    const int NT = K / 32;
    BGEMM_ISSUE(0, 0);
    BGEMM_ISSUE(1, 32);
    for (int kt = 0; kt < NT; kt++) {
        if (kt + 2 < NT) {
            int st = (kt + 2) % 3;
            BGEMM_ISSUE(st, (kt + 2) * 32);
            asm volatile("cp.async.wait_group 2;");
        } else if (kt + 1 < NT) {
            asm volatile("cp.async.wait_group 1;");
        } else {
            asm volatile("cp.async.wait_group 0;");
        }
        __syncthreads();

        const unsigned base = smbase + (kt % 3) * G_STG;
#pragma unroll
        for (int kk = 0; kk < 2; kk++) {
            unsigned ah[4][4], al[4][4];
#pragma unroll
            for (int mi = 0; mi < 4; mi++) {
                unsigned aa = base + (wm + mi * 16) * G_AROW + kk * 32 + a_pre;
                ldsm_x4(ah[mi][0], ah[mi][1], ah[mi][2], ah[mi][3], aa);
                ldsm_x4(al[mi][0], al[mi][1], al[mi][2], al[mi][3], aa + G_OFF_AL);
            }
            unsigned bh[4][2], bl[4][2];
#pragma unroll
            for (int j = 0; j < 2; j++) {
                unsigned bb = base + G_OFF_BH + kk * 16 * G_BROW + (wn + j * 16) * 2 + b_pre;
                unsigned t0, t1, t2, t3;
                ldsm_x4_t(t0, t1, t2, t3, bb);
                bh[2 * j][0] = t0; bh[2 * j][1] = t1; bh[2 * j + 1][0] = t2; bh[2 * j + 1][1] = t3;
                ldsm_x4_t(t0, t1, t2, t3, bb + (G_OFF_BL - G_OFF_BH));
                bl[2 * j][0] = t0; bl[2 * j][1] = t1; bl[2 * j + 1][0] = t2; bl[2 * j + 1][1] = t3;
            }
#pragma unroll
            for (int mi = 0; mi < 4; mi++)
#pragma unroll
                for (int ni = 0; ni < 4; ni++) {
                    mma_bf16(acc[mi][ni], al[mi], bh[ni]);
                    mma_bf16(acc[mi][ni], ah[mi], bl[ni]);
                    mma_bf16(acc[mi][ni], ah[mi], bh[ni]);
                }
        }
        __syncthreads();
    }

#pragma unroll
    for (int mi = 0; mi < 4; mi++) {
#pragma unroll
        for (int ni = 0; ni < 4; ni++) {
            int col = n0 + wn + ni * 8 + tig * 2;
            float bx = 0.f, by = 0.f;
            if (bias) { bx = bias[col]; by = bias[col + 1]; }
            int r0 = m0 + wm + mi * 16 + group;
            float2 v0; v0.x = acc[mi][ni][0] + bx; v0.y = acc[mi][ni][1] + by;
            *(float2*)(C + (size_t)r0 * N + col) = v0;
            float2 v1; v1.x = acc[mi][ni][2] + bx; v1.y = acc[mi][ni][3] + by;
            *(float2*)(C + (size_t)(r0 + 8) * N + col) = v1;
        }
    }
}

// ---------------- per-head LayerNorm (+RoPE + 1/8 scale) -> fp16 q -----------
__global__ __launch_bounds__(256) void ln_rope_q_kernel(
    const float* __restrict__ q, const float* __restrict__ scale, const float* __restrict__ bias,
    __half* __restrict__ qf)
{
    int gw = blockIdx.x * 8 + (threadIdx.x >> 5);
    int lane = threadIdx.x & 31;
    int row = gw >> 4;
    int h = gw & 15;
    const float* p = q + (size_t)row * DIM + h * HD;
    float e0 = p[lane], e1 = p[lane + 32];
    float ssum = e0 + e1;
#pragma unroll
    for (int o = 16; o; o >>= 1) ssum += __shfl_xor_sync(0xffffffffu, ssum, o);
    float mu = ssum * (1.f / 64.f);
    float d0 = e0 - mu, d1 = e1 - mu;
    float vs = d0 * d0 + d1 * d1;
#pragma unroll
    for (int o = 16; o; o >>= 1) vs += __shfl_xor_sync(0xffffffffu, vs, o);
    float rstd = rsqrtf(vs * (1.f / 64.f) + 1e-5f);
    float n0 = d0 * rstd * scale[lane] + bias[lane];
    float n1 = d1 * rstd * scale[lane + 32] + bias[lane + 32];
    int s = row & (SEQ - 1);
    float invf = powf(10000.f, -(float)lane * (1.f / 32.f));
    float ang = (float)s * invf;
    float sn, c;
    sincosf(ang, &sn, &c);
    size_t oidx = (size_t)row * DIM + h * HD;
    qf[oidx + lane]      = __float2half_rn((n0 * c - n1 * sn) * 0.125f);
    qf[oidx + lane + 32] = __float2half_rn((n0 * sn + n1 * c) * 0.125f);
}

// ---------------- k LayerNorm -> fp16; v -> fp16 ------------------------------
__global__ __launch_bounds__(256) void ln_k_v_split_kernel(
    const float* __restrict__ kv, const float* __restrict__ scale, const float* __restrict__ bias,
    __half* __restrict__ kf, __half* __restrict__ vf)
{
    int gw = blockIdx.x * 8 + (threadIdx.x >> 5);
    int lane = threadIdx.x & 31;
    int row = gw >> 4;
    int h = gw & 15;
    const float* p = kv + (size_t)row * (2 * DIM) + h * HD;
    float e0 = p[lane], e1 = p[lane + 32];
    float ssum = e0 + e1;
#pragma unroll
    for (int o = 16; o; o >>= 1) ssum += __shfl_xor_sync(0xffffffffu, ssum, o);
    float mu = ssum * (1.f / 64.f);
    float d0 = e0 - mu, d1 = e1 - mu;
    float vs = d0 * d0 + d1 * d1;
#pragma unroll
    for (int o = 16; o; o >>= 1) vs += __shfl_xor_sync(0xffffffffu, vs, o);
    float rstd = rsqrtf(vs * (1.f / 64.f) + 1e-5f);
    size_t oidx = (size_t)row * DIM + h * HD;
    kf[oidx + lane]      = __float2half_rn(d0 * rstd * scale[lane] + bias[lane]);
    kf[oidx + lane + 32] = __float2half_rn(d1 * rstd * scale[lane + 32] + bias[lane + 32]);
    const float* pv = p + DIM;
    vf[oidx + lane]      = __float2half_rn(pv[lane]);
    vf[oidx + lane + 32] = __float2half_rn(pv[lane + 32]);
}

// ---------------- flash attention: fp16 QK + fp16 PV, P in registers ---------
// CTA 256 thr / 8 warps, BQ=128 (16 rows/warp), key tiles BK=64.
// smem: K/V double-buffered, rows 144 B. P never staged (register repack).
#define KROW 144
#define KTILE (64*KROW)            // 9216 B
#define OFF_K 0                    // [2][KTILE]
#define OFF_V (2*KTILE)
#define ATTN_SMEM (4*KTILE)        // 36864 B

__global__ __launch_bounds__(256, 2) void attn_tc_kernel(
    const __half* __restrict__ qf,
    const __half* __restrict__ kf, const __half* __restrict__ vf,
    __nv_bfloat16* __restrict__ oh, __nv_bfloat16* __restrict__ ol)
{
    extern __shared__ char dynsm[];
    char* sm = dynsm;
    const int tid = threadIdx.x;
    const int warp = tid >> 5, lane = tid & 31;
    const int g = lane >> 2, t = lane & 3;
    const int mat = lane >> 3, r = lane & 7;
    const int h = blockIdx.y, b = blockIdx.z;
    const int rowbase = b * SEQ + blockIdx.x * 128;
    const int ctxbase = b * SEQ;

#define KV_LOAD(buf, tile)                                                                     \
    do {                                                                                       \
        _Pragma("unroll")                                                                      \
        for (int u = 0; u < 2; u++) {                                                          \
            int i = tid + u * 256;                                                             \
            int key = i >> 3, c = i & 7;                                                       \
            size_t src = ((size_t)(ctxbase + (tile) * 64 + key) << 10) + h * HD + c * 8;       \
            unsigned dst = (unsigned)__cvta_generic_to_shared(sm + (buf) * KTILE + key * KROW + c * 16); \
            asm volatile("cp.async.cg.shared.global [%0], [%1], 16;" :: "r"(dst + OFF_K), "l"(kf + src)); \
            asm volatile("cp.async.cg.shared.global [%0], [%1], 16;" :: "r"(dst + OFF_V), "l"(vf + src)); \
        }                                                                                      \
        asm volatile("cp.async.commit_group;");                                                \
    } while (0)

    KV_LOAD(0, 0);

    // ---- Q fragments (fp16) via direct LDG, warp-private rows ----
    unsigned qa[4][4];
    {
        const __half* qp = qf + (size_t)(rowbase + warp * 16 + g) * DIM + h * HD;
#pragma unroll
        for (int kc = 0; kc < 4; kc++) {
            int d0 = kc * 16 + 2 * t;
            qa[kc][0] = *(const unsigned*)(qp + d0);
            qa[kc][1] = *(const unsigned*)(qp + (size_t)8 * DIM + d0);
            qa[kc][2] = *(const unsigned*)(qp + d0 + 8);
            qa[kc][3] = *(const unsigned*)(qp + (size_t)8 * DIM + d0 + 8);
        }
    }

    float o[8][4] = {};
    float m0 = -1e30f, m1 = -1e30f, l0 = 0.f, l1 = 0.f;

    const unsigned smbase = (unsigned)__cvta_generic_to_shared(sm);
    const unsigned kpre = (mat >> 1) * 8 * KROW + r * KROW + (mat & 1) * 16;  // K: key block + d half
    const unsigned vpre = (mat & 1) * 8 * KROW + r * KROW + (mat >> 1) * 16;  // V: key half + d block

    const int NT = SEQ / 64;
    for (int kt = 0; kt < NT; kt++) {
        __syncthreads();
        if (kt + 1 < NT) {
            KV_LOAD((kt + 1) & 1, kt + 1);
            asm volatile("cp.async.wait_group 1;");
        } else {
            asm volatile("cp.async.wait_group 0;");
        }
        __syncthreads();

        const unsigned buf = (kt & 1) * KTILE;

        // ---- S = Q @ K^T (fp16 single) ----
        float s[8][4] = {};
#pragma unroll
        for (int kc = 0; kc < 4; kc++) {
#pragma unroll
            for (int ntp = 0; ntp < 4; ntp++) {
                unsigned aK = smbase + OFF_K + buf + ntp * (16 * KROW) + kc * 32 + kpre;
                unsigned k0, k1, k2, k3;
                ldsm_x4(k0, k1, k2, k3, aK);
                unsigned b0[2] = {k0, k1}, b1[2] = {k2, k3};
                mma_fp16(s[2 * ntp],     qa[kc], b0);
                mma_fp16(s[2 * ntp + 1], qa[kc], b1);
            }
        }

        // ---- online softmax (rows g, g+8; warp-local over 4 tig lanes) ----
        float mx0 = s[0][0], mx1 = s[0][2];
#pragma unroll
        for (int nt = 0; nt < 8; nt++) {
            mx0 = fmaxf(mx0, fmaxf(s[nt][0], s[nt][1]));
            mx1 = fmaxf(mx1, fmaxf(s[nt][2], s[nt][3]));
        }
        mx0 = fmaxf(mx0, __shfl_xor_sync(0xffffffffu, mx0, 1));
        mx0 = fmaxf(mx0, __shfl_xor_sync(0xffffffffu, mx0, 2));
        mx1 = fmaxf(mx1, __shfl_xor_sync(0xffffffffu, mx1, 1));
        mx1 = fmaxf(mx1, __shfl_xor_sync(0xffffffffu, mx1, 2));
        float mn0 = fmaxf(m0, mx0), mn1 = fmaxf(m1, mx1);
        float a0 = __expf(m0 - mn0), a1 = __expf(m1 - mn1);
        float sum0 = 0.f, sum1 = 0.f;
#pragma unroll
        for (int nt = 0; nt < 8; nt++) {
            s[nt][0] = __expf(s[nt][0] - mn0); s[nt][1] = __expf(s[nt][1] - mn0);
            s[nt][2] = __expf(s[nt][2] - mn1); s[nt][3] = __expf(s[nt][3] - mn1);
            sum0 += s[nt][0] + s[nt][1];
            sum1 += s[nt][2] + s[nt][3];
        }
        sum0 += __shfl_xor_sync(0xffffffffu, sum0, 1);
        sum0 += __shfl_xor_sync(0xffffffffu, sum0, 2);
        sum1 += __shfl_xor_sync(0xffffffffu, sum1, 1);
        sum1 += __shfl_xor_sync(0xffffffffu, sum1, 2);
        l0 = l0 * a0 + sum0; l1 = l1 * a1 + sum1;
        m0 = mn0; m1 = mn1;
#pragma unroll
        for (int nt = 0; nt < 8; nt++) {
            o[nt][0] *= a0; o[nt][1] *= a0;
            o[nt][2] *= a1; o[nt][3] *= a1;
        }

        // ---- P: register repack (S accumulator layout == PV A-operand layout) ----
        unsigned pa[4][4];
#pragma unroll
        for (int kc = 0; kc < 4; kc++) {
            pa[kc][0] = pack_f16(s[2 * kc][0],     s[2 * kc][1]);
            pa[kc][1] = pack_f16(s[2 * kc][2],     s[2 * kc][3]);
            pa[kc][2] = pack_f16(s[2 * kc + 1][0], s[2 * kc + 1][1]);
            pa[kc][3] = pack_f16(s[2 * kc + 1][2], s[2 * kc + 1][3]);
        }

        // ---- O += P @ V (fp16) ----
#pragma unroll
        for (int kc = 0; kc < 4; kc++) {
#pragma unroll
            for (int ntp = 0; ntp < 4; ntp++) {
                unsigned aV = smbase + OFF_V + buf + kc * (16 * KROW) + ntp * 32 + vpre;
                unsigned v0, v1, v2, v3;
                ldsm_x4_t(v0, v1, v2, v3, aV);
                unsigned b0[2] = {v0, v1}, b1[2] = {v2, v3};
                mma_fp16(o[2 * ntp],     pa[kc], b0);
                mma_fp16(o[2 * ntp + 1], pa[kc], b1);
            }
        }
    }

    // ---- normalize + write as bf16 hi/lo (feeds out-proj GEMM) ----
    float i0 = 1.f / l0, i1 = 1.f / l1;
    int r0 = rowbase + warp * 16 + g;
#pragma unroll
    for (int nt = 0; nt < 8; nt++) {
        int col = h * HD + nt * 8 + 2 * t;
        size_t idx0 = (size_t)r0 * DIM + col;
        size_t idx1 = (size_t)(r0 + 8) * DIM + col;
        float x = o[nt][0] * i0, y = o[nt][1] * i0;
        float xh = __bfloat162float(__float2bfloat16_rn(x));
        float yh = __bfloat162float(__float2bfloat16_rn(y));
        *(unsigned*)(oh + idx0) = pack_bf16(xh, yh);
        *(unsigned*)(ol + idx0) = pack_bf16(x - xh, y - yh);
        x = o[nt][2] * i1; y = o[nt][3] * i1;
        xh = __bfloat162float(__float2bfloat16_rn(x));
        yh = __bfloat162float(__float2bfloat16_rn(y));
        *(unsigned*)(oh + idx1) = pack_bf16(xh, yh);
        *(unsigned*)(ol + idx1) = pack_bf16(x - xh, y - yh);
    }
}

// ---------------- launch ------------------------------------------------------
extern "C" void kernel_launch(void* const* d_in, const int* in_sizes, int n_in,
                              void* d_out, int out_size)
{
    const float* x        = (const float*)d_in[0];
    const float* context  = (const float*)d_in[1];
    const float* q_w      = (const float*)d_in[2];
    const float* kv_w     = (const float*)d_in[3];
    const float* qn_scale = (const float*)d_in[4];
    const float* qn_bias  = (const float*)d_in[5];
    const float* kn_scale = (const float*)d_in[6];
    const float* kn_bias  = (const float*)d_in[7];
    const float* proj_w   = (const float*)d_in[8];
    const float* proj_b   = (const float*)d_in[9];
    float* out = (float*)d_out;

    float *pq, *pkv;
    __half *pqf, *pkf, *pvf;
    __nv_bfloat16 *pah, *pal;
    __nv_bfloat16 *pxh, *pxl, *pch, *pcl, *pqwh, *pqwl, *pkvwh, *pkvwl, *ppwh, *ppwl;
    cudaGetSymbolAddress((void**)&pq,  g_q);
    cudaGetSymbolAddress((void**)&pkv, g_kv);
    cudaGetSymbolAddress((void**)&pqf, g_qf);
    cudaGetSymbolAddress((void**)&pkf, g_kf);
    cudaGetSymbolAddress((void**)&pvf, g_vf);
    cudaGetSymbolAddress((void**)&pah, g_ah);
    cudaGetSymbolAddress((void**)&pal, g_al);
    cudaGetSymbolAddress((void**)&pxh, g_xh);
    cudaGetSymbolAddress((void**)&pxl, g_xl);
    cudaGetSymbolAddress((void**)&pch, g_ch);
    cudaGetSymbolAddress((void**)&pcl, g_cl);
    cudaGetSymbolAddress((void**)&pqwh, g_qwh);
    cudaGetSymbolAddress((void**)&pqwl, g_qwl);
    cudaGetSymbolAddress((void**)&pkvwh, g_kvwh);
    cudaGetSymbolAddress((void**)&pkvwl, g_kvwl);
    cudaGetSymbolAddress((void**)&ppwh, g_pwh);
    cudaGetSymbolAddress((void**)&ppwl, g_pwl);

    cudaFuncSetAttribute(bf16_gemm_kernel, cudaFuncAttributeMaxDynamicSharedMemorySize, (int)GEMM_SMEM);
    cudaFuncSetAttribute(attn_tc_kernel, cudaFuncAttributeMaxDynamicSharedMemorySize, (int)ATTN_SMEM);

    // 0. split inputs/weights to bf16 hi/lo
    split_bf16_kernel<<<MROWS * DIM / 1024, 256>>>(x, pxh, pxl);
    split_bf16_kernel<<<MROWS * DIM / 1024, 256>>>(context, pch, pcl);
    split_bf16_kernel<<<DIM * DIM / 1024, 256>>>(q_w, pqwh, pqwl);
    split_bf16_kernel<<<DIM * 2 * DIM / 1024, 256>>>(kv_w, pkvwh, pkvwl);
    split_bf16_kernel<<<DIM * DIM / 1024, 256>>>(proj_w, ppwh, ppwl);

    // 1. q = x @ q_w
    bf16_gemm_kernel<<<dim3(DIM / 128, MROWS / 128), 256, GEMM_SMEM>>>(
        pxh, pxl, pqwh, pqwl, nullptr, pq, MROWS, DIM, DIM);
    // 2. kv = context @ kv_w
    bf16_gemm_kernel<<<dim3(2 * DIM / 128, MROWS / 128), 256, GEMM_SMEM>>>(
        pch, pcl, pkvwh, pkvwl, nullptr, pkv, MROWS, 2 * DIM, DIM);
    // 3. per-head LN (+RoPE+scale) -> fp16 q; k LN -> fp16; v -> fp16
    ln_rope_q_kernel<<<MROWS * NH / 8, 256>>>(pq, qn_scale, qn_bias, pqf);
    ln_k_v_split_kernel<<<MROWS * NH / 8, 256>>>(pkv, kn_scale, kn_bias, pkf, pvf);
    // 4. attention (fp16 QK + fp16 PV, P in registers)
    attn_tc_kernel<<<dim3(SEQ / 128, NH, BATCH), 256, ATTN_SMEM>>>(pqf, pkf, pvf, pah, pal);
    // 5. out = att @ proj_w + proj_b
    bf16_gemm_kernel<<<dim3(DIM / 128, MROWS / 128), 256, GEMM_SMEM>>>(
        pah, pal, ppwh, ppwl, proj_b, out, MROWS, DIM, DIM);
}

// round 16
// speedup vs baseline: 3.8966x; 1.0568x over previous
#include <cuda_runtime.h>
#include <cuda_bf16.h>
#include <cuda_fp16.h>
#include <math.h>

#define DIM 1024
#define NH 16
#define HD 64
#define BATCH 4
#define SEQ 2048
#define MROWS (BATCH*SEQ)   // 8192

// ---------------- scratch (static device memory; no allocations) -------------
__device__ float g_q  [(size_t)MROWS * DIM];            // q proj fp32 (pre-LN)
__device__ float g_kv [(size_t)MROWS * 2 * DIM];        // raw kv projection fp32
__device__ __half g_qf [(size_t)MROWS * DIM];           // q fp16 (LN+RoPE+scale)
__device__ __half g_kf [(size_t)MROWS * DIM];           // k fp16 (LN)
__device__ __half g_vf [(size_t)MROWS * DIM];           // v fp16
__device__ __half g_af [(size_t)MROWS * DIM];           // attention out fp16
__device__ __half g_xf [(size_t)MROWS * DIM];           // x fp16
__device__ __half g_cf [(size_t)MROWS * DIM];           // context fp16
__device__ __half g_qwf[(size_t)DIM * DIM];             // weights fp16
__device__ __half g_kvwf[(size_t)DIM * 2 * DIM];
__device__ __half g_pwf[(size_t)DIM * DIM];

// ---------------- helpers -----------------------------------------------------
__device__ __forceinline__ void mma_fp16(float c[4], const unsigned a[4], const unsigned b[2]) {
    asm volatile(
        "mma.sync.aligned.m16n8k16.row.col.f32.f16.f16.f32 "
        "{%0,%1,%2,%3}, {%4,%5,%6,%7}, {%8,%9}, {%0,%1,%2,%3};\n"
        : "+f"(c[0]), "+f"(c[1]), "+f"(c[2]), "+f"(c[3])
        : "r"(a[0]), "r"(a[1]), "r"(a[2]), "r"(a[3]), "r"(b[0]), "r"(b[1]));
}
__device__ __forceinline__ unsigned pack_f16(float x, float y) {
    __half2 v = __floats2half2_rn(x, y);
    return *(unsigned*)&v;
}
__device__ __forceinline__ void ldsm_x4(unsigned& r0, unsigned& r1, unsigned& r2, unsigned& r3, unsigned addr) {
    asm volatile("ldmatrix.sync.aligned.m8n8.x4.shared.b16 {%0,%1,%2,%3}, [%4];"
                 : "=r"(r0), "=r"(r1), "=r"(r2), "=r"(r3) : "r"(addr));
}
__device__ __forceinline__ void ldsm_x4_t(unsigned& r0, unsigned& r1, unsigned& r2, unsigned& r3, unsigned addr) {
    asm volatile("ldmatrix.sync.aligned.m8n8.x4.trans.shared.b16 {%0,%1,%2,%3}, [%4];"
                 : "=r"(r0), "=r"(r1), "=r"(r2), "=r"(r3) : "r"(addr));
}

// ---------------- elementwise fp32 -> fp16 convert ----------------------------
__global__ __launch_bounds__(256) void cvt_f16_kernel(
    const float* __restrict__ in, __half* __restrict__ out)
{
    size_t i = ((size_t)blockIdx.x * 256 + threadIdx.x) * 8;
    float4 a = *(const float4*)(in + i);
    float4 b = *(const float4*)(in + i + 4);
    uint4 o;
    o.x = pack_f16(a.x, a.y); o.y = pack_f16(a.z, a.w);
    o.z = pack_f16(b.x, b.y); o.w = pack_f16(b.z, b.w);
    *(uint4*)(out + i) = o;
}

// =======================  fp16 ldmatrix GEMM, 4-stage pipeline  ==============
// C[M,N](fp32) = A[M,K] @ B[K,N] (+bias), fp16 operands, fp32 accumulate.
// CTA 128x128, BK=32, 256 thr / 8 warps (2x4 of 64x32).
#define G_AROW 80
#define G_BROW 272
#define G_OFF_B 10240
#define G_STG 18944
#define GEMM_SMEM (4*G_STG)   // 75776 B

__global__ __launch_bounds__(256) void fp16_gemm_kernel(
    const __half* __restrict__ A, const __half* __restrict__ B,
    const float* __restrict__ bias, float* __restrict__ C,
    int M, int N, int K)
{
    extern __shared__ char dynsm[];
    char* sm = dynsm;
    const int tid = threadIdx.x;
    const int warp = tid >> 5, lane = tid & 31;
    const int group = lane >> 2, tig = lane & 3;
    const int mat = lane >> 3, r = lane & 7;
    const int wm = (warp & 1) * 64;
    const int wn = (warp >> 1) * 32;
    const int m0 = blockIdx.y * 128, n0 = blockIdx.x * 128;

    float acc[4][4][4] = {};

#define FGEMM_ISSUE(s, k0)                                                                    \
    do {                                                                                      \
        _Pragma("unroll")                                                                     \
        for (int u = 0; u < 2; u++) {                                                         \
            int j = tid + u * 256;                                                            \
            int row = j >> 2, c = j & 3;                                                      \
            size_t src = (size_t)(m0 + row) * K + (k0) + c * 8;                               \
            unsigned d = (unsigned)__cvta_generic_to_shared(sm + (s) * G_STG + row * G_AROW + c * 16); \
            asm volatile("cp.async.cg.shared.global [%0], [%1], 16;" :: "r"(d), "l"(A + src)); \
        }                                                                                     \
        _Pragma("unroll")                                                                     \
        for (int u = 0; u < 2; u++) {                                                         \
            int j = tid + u * 256;                                                            \
            int kr = j >> 4, c = j & 15;                                                      \
            size_t src = (size_t)((k0) + kr) * N + n0 + c * 8;                                \
            unsigned d = (unsigned)__cvta_generic_to_shared(sm + (s) * G_STG + G_OFF_B + kr * G_BROW + c * 16); \
            asm volatile("cp.async.cg.shared.global [%0], [%1], 16;" :: "r"(d), "l"(B + src)); \
        }                                                                                     \
        asm volatile("cp.async.commit_group;");                                               \
    } while (0)

    const unsigned smbase = (unsigned)__cvta_generic_to_shared(sm);
    const unsigned a_pre = ((mat & 1) * 8 + r) * G_AROW + (mat >> 1) * 16;
    const unsigned b_pre = ((mat & 1) * 8 + r) * G_BROW + (mat >> 1) * 16;

    const int NT = K / 32;
    FGEMM_ISSUE(0, 0);
    FGEMM_ISSUE(1, 32);
    FGEMM_ISSUE(2, 64);
    for (int kt = 0; kt < NT; kt++) {
        if (kt + 3 < NT) {
            FGEMM_ISSUE((kt + 3) & 3, (kt + 3) * 32);
            asm volatile("cp.async.wait_group 3;");
        } else if (kt + 3 == NT) {
            asm volatile("cp.async.wait_group 2;");
        } else if (kt + 2 == NT) {
            asm volatile("cp.async.wait_group 1;");
        } else {
            asm volatile("cp.async.wait_group 0;");
        }
        __syncthreads();

        const unsigned base = smbase + (kt & 3) * G_STG;
#pragma unroll
        for (int kk = 0; kk < 2; kk++) {
            unsigned af[4][4];
#pragma unroll
            for (int mi = 0; mi < 4; mi++) {
                unsigned aa = base + (wm + mi * 16) * G_AROW + kk * 32 + a_pre;
                ldsm_x4(af[mi][0], af[mi][1], af[mi][2], af[mi][3], aa);
            }
            unsigned bf[4][2];
#pragma unroll
            for (int j = 0; j < 2; j++) {
                unsigned bb = base + G_OFF_B + kk * 16 * G_BROW + (wn + j * 16) * 2 + b_pre;
                unsigned t0, t1, t2, t3;
                ldsm_x4_t(t0, t1, t2, t3, bb);
                bf[2 * j][0] = t0; bf[2 * j][1] = t1; bf[2 * j + 1][0] = t2; bf[2 * j + 1][1] = t3;
            }
#pragma unroll
            for (int mi = 0; mi < 4; mi++)
#pragma unroll
                for (int ni = 0; ni < 4; ni++)
                    mma_fp16(acc[mi][ni], af[mi], bf[ni]);
        }
        __syncthreads();
    }

#pragma unroll
    for (int mi = 0; mi < 4; mi++) {
#pragma unroll
        for (int ni = 0; ni < 4; ni++) {
            int col = n0 + wn + ni * 8 + tig * 2;
            float bx = 0.f, by = 0.f;
            if (bias) { bx = bias[col]; by = bias[col + 1]; }
            int r0 = m0 + wm + mi * 16 + group;
            float2 v0; v0.x = acc[mi][ni][0] + bx; v0.y = acc[mi][ni][1] + by;
            *(float2*)(C + (size_t)r0 * N + col) = v0;
            float2 v1; v1.x = acc[mi][ni][2] + bx; v1.y = acc[mi][ni][3] + by;
            *(float2*)(C + (size_t)(r0 + 8) * N + col) = v1;
        }
    }
}

// ---------------- per-head LayerNorm (+RoPE + 1/8 scale) -> fp16 q -----------
__global__ __launch_bounds__(256) void ln_rope_q_kernel(
    const float* __restrict__ q, const float* __restrict__ scale, const float* __restrict__ bias,
    __half* __restrict__ qf)
{
    int gw = blockIdx.x * 8 + (threadIdx.x >> 5);
    int lane = threadIdx.x & 31;
    int row = gw >> 4;
    int h = gw & 15;
    const float* p = q + (size_t)row * DIM + h * HD;
    float e0 = p[lane], e1 = p[lane + 32];
    float ssum = e0 + e1;
#pragma unroll
    for (int o = 16; o; o >>= 1) ssum += __shfl_xor_sync(0xffffffffu, ssum, o);
    float mu = ssum * (1.f / 64.f);
    float d0 = e0 - mu, d1 = e1 - mu;
    float vs = d0 * d0 + d1 * d1;
#pragma unroll
    for (int o = 16; o; o >>= 1) vs += __shfl_xor_sync(0xffffffffu, vs, o);
    float rstd = rsqrtf(vs * (1.f / 64.f) + 1e-5f);
    float n0 = d0 * rstd * scale[lane] + bias[lane];
    float n1 = d1 * rstd * scale[lane + 32] + bias[lane + 32];
    int s = row & (SEQ - 1);
    float invf = powf(10000.f, -(float)lane * (1.f / 32.f));
    float ang = (float)s * invf;
    float sn, c;
    sincosf(ang, &sn, &c);
    size_t oidx = (size_t)row * DIM + h * HD;
    qf[oidx + lane]      = __float2half_rn((n0 * c - n1 * sn) * 0.125f);
    qf[oidx + lane + 32] = __float2half_rn((n0 * sn + n1 * c) * 0.125f);
}

// ---------------- k LayerNorm -> fp16; v -> fp16 ------------------------------
__global__ __launch_bounds__(256) void ln_k_v_split_kernel(
    const float* __restrict__ kv, const float* __restrict__ scale, const float* __restrict__ bias,
    __half* __restrict__ kf, __half* __restrict__ vf)
{
    int gw = blockIdx.x * 8 + (threadIdx.x >> 5);
    int lane = threadIdx.x & 31;
    int row = gw >> 4;
    int h = gw & 15;
    const float* p = kv + (size_t)row * (2 * DIM) + h * HD;
    float e0 = p[lane], e1 = p[lane + 32];
    float ssum = e0 + e1;
#pragma unroll
    for (int o = 16; o; o >>= 1) ssum += __shfl_xor_sync(0xffffffffu, ssum, o);
    float mu = ssum * (1.f / 64.f);
    float d0 = e0 - mu, d1 = e1 - mu;
    float vs = d0 * d0 + d1 * d1;
#pragma unroll
    for (int o = 16; o; o >>= 1) vs += __shfl_xor_sync(0xffffffffu, vs, o);
    float rstd = rsqrtf(vs * (1.f / 64.f) + 1e-5f);
    size_t oidx = (size_t)row * DIM + h * HD;
    kf[oidx + lane]      = __float2half_rn(d0 * rstd * scale[lane] + bias[lane]);
    kf[oidx + lane + 32] = __float2half_rn(d1 * rstd * scale[lane + 32] + bias[lane + 32]);
    const float* pv = p + DIM;
    vf[oidx + lane]      = __float2half_rn(pv[lane]);
    vf[oidx + lane + 32] = __float2half_rn(pv[lane + 32]);
}

// ---------------- flash attention: fp16 QK + fp16 PV, P in registers ---------
#define KROW 144
#define KTILE (64*KROW)            // 9216 B
#define OFF_K 0                    // [2][KTILE]
#define OFF_V (2*KTILE)
#define ATTN_SMEM (4*KTILE)        // 36864 B

__global__ __launch_bounds__(256, 2) void attn_tc_kernel(
    const __half* __restrict__ qf,
    const __half* __restrict__ kf, const __half* __restrict__ vf,
    __half* __restrict__ of)
{
    extern __shared__ char dynsm[];
    char* sm = dynsm;
    const int tid = threadIdx.x;
    const int warp = tid >> 5, lane = tid & 31;
    const int g = lane >> 2, t = lane & 3;
    const int mat = lane >> 3, r = lane & 7;
    const int h = blockIdx.y, b = blockIdx.z;
    const int rowbase = b * SEQ + blockIdx.x * 128;
    const int ctxbase = b * SEQ;

#define KV_LOAD(buf, tile)                                                                     \
    do {                                                                                       \
        _Pragma("unroll")                                                                      \
        for (int i2 = 0; i2 < 2; i2++) {                                                       \
            int i = tid + i2 * 256;                                                            \
            int key = i >> 3, c = i & 7;                                                       \
            size_t src = ((size_t)(ctxbase + (tile) * 64 + key) << 10) + h * HD + c * 8;       \
            unsigned dst = (unsigned)__cvta_generic_to_shared(sm + (buf) * KTILE + key * KROW + c * 16); \
            asm volatile("cp.async.cg.shared.global [%0], [%1], 16;" :: "r"(dst + OFF_K), "l"(kf + src)); \
            asm volatile("cp.async.cg.shared.global [%0], [%1], 16;" :: "r"(dst + OFF_V), "l"(vf + src)); \
        }                                                                                      \
        asm volatile("cp.async.commit_group;");                                                \
    } while (0)

    KV_LOAD(0, 0);

    // ---- Q fragments (fp16) via direct LDG, warp-private rows ----
    unsigned qa[4][4];
    {
        const __half* qp = qf + (size_t)(rowbase + warp * 16 + g) * DIM + h * HD;
#pragma unroll
        for (int kc = 0; kc < 4; kc++) {
            int d0 = kc * 16 + 2 * t;
            qa[kc][0] = *(const unsigned*)(qp + d0);
            qa[kc][1] = *(const unsigned*)(qp + (size_t)8 * DIM + d0);
            qa[kc][2] = *(const unsigned*)(qp + d0 + 8);
            qa[kc][3] = *(const unsigned*)(qp + (size_t)8 * DIM + d0 + 8);
        }
    }

    float o[8][4] = {};
    float m0 = -1e30f, m1 = -1e30f, l0 = 0.f, l1 = 0.f;

    const unsigned smbase = (unsigned)__cvta_generic_to_shared(sm);
    const unsigned kpre = (mat >> 1) * 8 * KROW + r * KROW + (mat & 1) * 16;
    const unsigned vpre = (mat & 1) * 8 * KROW + r * KROW + (mat >> 1) * 16;

    const int NT = SEQ / 64;
    for (int kt = 0; kt < NT; kt++) {
        __syncthreads();
        if (kt + 1 < NT) {
            KV_LOAD((kt + 1) & 1, kt + 1);
            asm volatile("cp.async.wait_group 1;");
        } else {
            asm volatile("cp.async.wait_group 0;");
        }
        __syncthreads();

        const unsigned buf = (kt & 1) * KTILE;

        // ---- S = Q @ K^T ----
        float s[8][4] = {};
#pragma unroll
        for (int kc = 0; kc < 4; kc++) {
#pragma unroll
            for (int ntp = 0; ntp < 4; ntp++) {
                unsigned aK = smbase + OFF_K + buf + ntp * (16 * KROW) + kc * 32 + kpre;
                unsigned k0, k1, k2, k3;
                ldsm_x4(k0, k1, k2, k3, aK);
                unsigned b0[2] = {k0, k1}, b1[2] = {k2, k3};
                mma_fp16(s[2 * ntp],     qa[kc], b0);
                mma_fp16(s[2 * ntp + 1], qa[kc], b1);
            }
        }

        // ---- online softmax ----
        float mx0 = s[0][0], mx1 = s[0][2];
#pragma unroll
        for (int nt = 0; nt < 8; nt++) {
            mx0 = fmaxf(mx0, fmaxf(s[nt][0], s[nt][1]));
            mx1 = fmaxf(mx1, fmaxf(s[nt][2], s[nt][3]));
        }
        mx0 = fmaxf(mx0, __shfl_xor_sync(0xffffffffu, mx0, 1));
        mx0 = fmaxf(mx0, __shfl_xor_sync(0xffffffffu, mx0, 2));
        mx1 = fmaxf(mx1, __shfl_xor_sync(0xffffffffu, mx1, 1));
        mx1 = fmaxf(mx1, __shfl_xor_sync(0xffffffffu, mx1, 2));
        float mn0 = fmaxf(m0, mx0), mn1 = fmaxf(m1, mx1);
        float a0 = __expf(m0 - mn0), a1 = __expf(m1 - mn1);
        float sum0 = 0.f, sum1 = 0.f;
#pragma unroll
        for (int nt = 0; nt < 8; nt++) {
            s[nt][0] = __expf(s[nt][0] - mn0); s[nt][1] = __expf(s[nt][1] - mn0);
            s[nt][2] = __expf(s[nt][2] - mn1); s[nt][3] = __expf(s[nt][3] - mn1);
            sum0 += s[nt][0] + s[nt][1];
            sum1 += s[nt][2] + s[nt][3];
        }
        sum0 += __shfl_xor_sync(0xffffffffu, sum0, 1);
        sum0 += __shfl_xor_sync(0xffffffffu, sum0, 2);
        sum1 += __shfl_xor_sync(0xffffffffu, sum1, 1);
        sum1 += __shfl_xor_sync(0xffffffffu, sum1, 2);
        l0 = l0 * a0 + sum0; l1 = l1 * a1 + sum1;
        m0 = mn0; m1 = mn1;
#pragma unroll
        for (int nt = 0; nt < 8; nt++) {
            o[nt][0] *= a0; o[nt][1] *= a0;
            o[nt][2] *= a1; o[nt][3] *= a1;
        }

        // ---- P: register repack ----
        unsigned pa[4][4];
#pragma unroll
        for (int kc = 0; kc < 4; kc++) {
            pa[kc][0] = pack_f16(s[2 * kc][0],     s[2 * kc][1]);
            pa[kc][1] = pack_f16(s[2 * kc][2],     s[2 * kc][3]);
            pa[kc][2] = pack_f16(s[2 * kc + 1][0], s[2 * kc + 1][1]);
            pa[kc][3] = pack_f16(s[2 * kc + 1][2], s[2 * kc + 1][3]);
        }

        // ---- O += P @ V ----
#pragma unroll
        for (int kc = 0; kc < 4; kc++) {
#pragma unroll
            for (int ntp = 0; ntp < 4; ntp++) {
                unsigned aV = smbase + OFF_V + buf + kc * (16 * KROW) + ntp * 32 + vpre;
                unsigned v0, v1, v2, v3;
                ldsm_x4_t(v0, v1, v2, v3, aV);
                unsigned b0[2] = {v0, v1}, b1[2] = {v2, v3};
                mma_fp16(o[2 * ntp],     pa[kc], b0);
                mma_fp16(o[2 * ntp + 1], pa[kc], b1);
            }
        }
    }

    // ---- normalize + write fp16 (feeds out-proj GEMM) ----
    float i0 = 1.f / l0, i1 = 1.f / l1;
    int r0 = rowbase + warp * 16 + g;
#pragma unroll
    for (int nt = 0; nt < 8; nt++) {
        int col = h * HD + nt * 8 + 2 * t;
        *(unsigned*)(of + (size_t)r0 * DIM + col)       = pack_f16(o[nt][0] * i0, o[nt][1] * i0);
        *(unsigned*)(of + (size_t)(r0 + 8) * DIM + col) = pack_f16(o[nt][2] * i1, o[nt][3] * i1);
    }
}

// ---------------- launch ------------------------------------------------------
extern "C" void kernel_launch(void* const* d_in, const int* in_sizes, int n_in,
                              void* d_out, int out_size)
{
    const float* x        = (const float*)d_in[0];
    const float* context  = (const float*)d_in[1];
    const float* q_w      = (const float*)d_in[2];
    const float* kv_w     = (const float*)d_in[3];
    const float* qn_scale = (const float*)d_in[4];
    const float* qn_bias  = (const float*)d_in[5];
    const float* kn_scale = (const float*)d_in[6];
    const float* kn_bias  = (const float*)d_in[7];
    const float* proj_w   = (const float*)d_in[8];
    const float* proj_b   = (const float*)d_in[9];
    float* out = (float*)d_out;

    float *pq, *pkv;
    __half *pqf, *pkf, *pvf, *paf, *pxf, *pcf, *pqwf, *pkvwf, *ppwf;
    cudaGetSymbolAddress((void**)&pq,  g_q);
    cudaGetSymbolAddress((void**)&pkv, g_kv);
    cudaGetSymbolAddress((void**)&pqf, g_qf);
    cudaGetSymbolAddress((void**)&pkf, g_kf);
    cudaGetSymbolAddress((void**)&pvf, g_vf);
    cudaGetSymbolAddress((void**)&paf, g_af);
    cudaGetSymbolAddress((void**)&pxf, g_xf);
    cudaGetSymbolAddress((void**)&pcf, g_cf);
    cudaGetSymbolAddress((void**)&pqwf, g_qwf);
    cudaGetSymbolAddress((void**)&pkvwf, g_kvwf);
    cudaGetSymbolAddress((void**)&ppwf, g_pwf);

    cudaFuncSetAttribute(fp16_gemm_kernel, cudaFuncAttributeMaxDynamicSharedMemorySize, (int)GEMM_SMEM);
    cudaFuncSetAttribute(attn_tc_kernel, cudaFuncAttributeMaxDynamicSharedMemorySize, (int)ATTN_SMEM);

    // 0. convert inputs/weights to fp16
    cvt_f16_kernel<<<MROWS * DIM / 2048, 256>>>(x, pxf);
    cvt_f16_kernel<<<MROWS * DIM / 2048, 256>>>(context, pcf);
    cvt_f16_kernel<<<DIM * DIM / 2048, 256>>>(q_w, pqwf);
    cvt_f16_kernel<<<DIM * 2 * DIM / 2048, 256>>>(kv_w, pkvwf);
    cvt_f16_kernel<<<DIM * DIM / 2048, 256>>>(proj_w, ppwf);

    // 1. q = x @ q_w
    fp16_gemm_kernel<<<dim3(DIM / 128, MROWS / 128), 256, GEMM_SMEM>>>(
        pxf, pqwf, nullptr, pq, MROWS, DIM, DIM);
    // 2. kv = context @ kv_w
    fp16_gemm_kernel<<<dim3(2 * DIM / 128, MROWS / 128), 256, GEMM_SMEM>>>(
        pcf, pkvwf, nullptr, pkv, MROWS, 2 * DIM, DIM);
    // 3. per-head LN (+RoPE+scale) -> fp16 q; k LN -> fp16; v -> fp16
    ln_rope_q_kernel<<<MROWS * NH / 8, 256>>>(pq, qn_scale, qn_bias, pqf);
    ln_k_v_split_kernel<<<MROWS * NH / 8, 256>>>(pkv, kn_scale, kn_bias, pkf, pvf);
    // 4. attention (fp16 QK + fp16 PV, P in registers) -> fp16
    attn_tc_kernel<<<dim3(SEQ / 128, NH, BATCH), 256, ATTN_SMEM>>>(pqf, pkf, pvf, paf);
    // 5. out = att @ proj_w + proj_b
    fp16_gemm_kernel<<<dim3(DIM / 128, MROWS / 128), 256, GEMM_SMEM>>>(
        paf, ppwf, proj_b, out, MROWS, DIM, DIM);
}